// round 7
// baseline (speedup 1.0000x reference)
#include <cuda_runtime.h>
#include <cuda_bf16.h>
#include <math.h>
#include <cstdint>

#define BATCH   32
#define HEADS   8
#define SEQ     512
#define DMODEL  1024
#define DHEAD   128
#define DCOL    18
#define BHS     (BATCH*HEADS)   // 256
#define BSD     ((size_t)BATCH*SEQ*DMODEL)   // 16777216

// ---------------- scratch (static device globals; no allocation) ----------------
__device__ __align__(256) __nv_bfloat16 g_xqh[BSD], g_xql[BSD];
__device__ __align__(256) __nv_bfloat16 g_xkh[BSD], g_xkl[BSD];
__device__ __align__(256) __nv_bfloat16 g_Whh[DMODEL*DMODEL], g_Whl[DMODEL*DMODEL];
__device__ __align__(256) __nv_bfloat16 g_Wvh[DMODEL*DMODEL], g_Wvl[DMODEL*DMODEL];
__device__ __align__(256) __nv_bfloat16 g_Woh[DMODEL*DMODEL], g_Wol[DMODEL*DMODEL];
__device__ __align__(256) __nv_bfloat16 g_fhh[BSD], g_fhl[BSD];   // f_head hi/lo [b,h,q,dh]
__device__ __align__(256) __nv_bfloat16 g_fth[BSD], g_ftl[BSD];   // f_tail hi/lo [b,h,k,dh]
__device__ __align__(256) float        g_fv [BSD];                 // f_v fp32 [b,h,k,dh]
__device__ __align__(256) __nv_bfloat16 g_ath[BSD], g_atl[BSD];    // attn hi/lo [b,q,h*dh]
__device__ __align__(256) float        g_adjm[(size_t)HEADS*SEQ*SEQ];

// ---------------- small helpers ----------------
__device__ __forceinline__ unsigned packbf(float f0, float f1) {   // f0 -> low half
    unsigned d;
    asm("cvt.rn.bf16x2.f32 %0, %1, %2;" : "=r"(d) : "f"(f1), "f"(f0));
    return d;
}
__device__ __forceinline__ float bf_lo(unsigned p) { return __uint_as_float(p << 16); }
__device__ __forceinline__ float bf_up(unsigned p) { return __uint_as_float(p & 0xFFFF0000u); }

__device__ __forceinline__ unsigned smem_u32(const void* p) {
    unsigned a;
    asm("{ .reg .u64 t; cvta.to.shared.u64 t, %1; cvt.u32.u64 %0, t; }" : "=r"(a) : "l"(p));
    return a;
}
__device__ __forceinline__ void cpa16s(unsigned dst, const void* src) {
    asm volatile("cp.async.ca.shared.global [%0], [%1], 16;" :: "r"(dst), "l"(src));
}
__device__ __forceinline__ void cpa_commit() { asm volatile("cp.async.commit_group;"); }
template<int N>
__device__ __forceinline__ void cpa_wait() { asm volatile("cp.async.wait_group %0;" :: "n"(N)); }

__device__ __forceinline__ void ldm4(unsigned& r0, unsigned& r1, unsigned& r2, unsigned& r3,
                                     unsigned addr) {
    asm volatile("ldmatrix.sync.aligned.m8n8.x4.shared.b16 {%0,%1,%2,%3}, [%4];"
                 : "=r"(r0), "=r"(r1), "=r"(r2), "=r"(r3) : "r"(addr));
}

__device__ __forceinline__ void mmabf(float* c, unsigned a0, unsigned a1, unsigned a2,
                                      unsigned a3, unsigned b0, unsigned b1) {
    asm volatile(
        "mma.sync.aligned.m16n8k16.row.col.f32.bf16.bf16.f32 "
        "{%0,%1,%2,%3}, {%4,%5,%6,%7}, {%8,%9}, {%0,%1,%2,%3};\n"
        : "+f"(c[0]), "+f"(c[1]), "+f"(c[2]), "+f"(c[3])
        : "r"(a0), "r"(a1), "r"(a2), "r"(a3), "r"(b0), "r"(b1));
}

__device__ __forceinline__ void cvt8(const float* f, unsigned* ph, unsigned* pl) {
#pragma unroll
    for (int j = 0; j < 4; j++) {
        unsigned h = packbf(f[2*j], f[2*j+1]);
        ph[j] = h;
        pl[j] = packbf(f[2*j] - bf_lo(h), f[2*j+1] - bf_up(h));
    }
}

// ---------------- fp32 -> bf16 hi/lo conversion (W selects destination) ----------------
template<int W>
__global__ void cvt_hilo(const float* __restrict__ src, int n4)
{
    __nv_bfloat16 *hi, *lo;
    if constexpr (W == 0) { hi = g_xqh; lo = g_xql; }
    else if constexpr (W == 1) { hi = g_xkh; lo = g_xkl; }
    else if constexpr (W == 2) { hi = g_Whh; lo = g_Whl; }
    else if constexpr (W == 3) { hi = g_Wvh; lo = g_Wvl; }
    else                       { hi = g_Woh; lo = g_Wol; }
    uint2* hu = reinterpret_cast<uint2*>(hi);
    uint2* lu = reinterpret_cast<uint2*>(lo);
    const float4* s4 = reinterpret_cast<const float4*>(src);
    for (int i = blockIdx.x * blockDim.x + threadIdx.x; i < n4; i += gridDim.x * blockDim.x) {
        float4 v = s4[i];
        unsigned h0 = packbf(v.x, v.y), h1 = packbf(v.z, v.w);
        unsigned l0 = packbf(v.x - bf_lo(h0), v.y - bf_up(h0));
        unsigned l1 = packbf(v.z - bf_lo(h1), v.w - bf_up(h1));
        hu[i] = make_uint2(h0, h1);
        lu[i] = make_uint2(l0, l1);
    }
}

// ---------------- adjacency: softmax(col_head @ col_tail^T, diag=0) ----------------
__global__ void adj_kernel(const float* __restrict__ col_head,
                           const float* __restrict__ col_tail)
{
    const int q = blockIdx.x;
    const int h = blockIdx.y;
    const int t = threadIdx.x;                 // 128 threads
    __shared__ float ch[DCOL];
    __shared__ float sred[4];

    if (t < DCOL) ch[t] = col_head[((size_t)h*SEQ + q)*DCOL + t];
    __syncthreads();

    float l[4];
#pragma unroll
    for (int i = 0; i < 4; i++) {
        const int k = t + i*128;
        const float* ct = col_tail + ((size_t)h*SEQ + k)*DCOL;
        float s = 0.f;
#pragma unroll
        for (int c = 0; c < DCOL; c++) s += ch[c]*ct[c];
        l[i] = (k == q) ? 0.f : s;
    }

    float mx = fmaxf(fmaxf(l[0],l[1]), fmaxf(l[2],l[3]));
#pragma unroll
    for (int o = 16; o; o >>= 1) mx = fmaxf(mx, __shfl_xor_sync(0xffffffffu, mx, o));
    if ((t & 31) == 0) sred[t >> 5] = mx;
    __syncthreads();
    mx = fmaxf(fmaxf(sred[0],sred[1]), fmaxf(sred[2],sred[3]));
    __syncthreads();

    float e[4]; float sum = 0.f;
#pragma unroll
    for (int i = 0; i < 4; i++) { e[i] = expf(l[i]-mx); sum += e[i]; }
#pragma unroll
    for (int o = 16; o; o >>= 1) sum += __shfl_xor_sync(0xffffffffu, sum, o);
    if ((t & 31) == 0) sred[t >> 5] = sum;
    __syncthreads();
    sum = sred[0]+sred[1]+sred[2]+sred[3];
    const float inv = 1.f/sum;

    float* dst = g_adjm + ((size_t)h*SEQ + q)*SEQ;
#pragma unroll
    for (int i = 0; i < 4; i++) {
        const int k = t + i*128;
        dst[k] = (1.f - e[i]*inv) * (-10000.f);
    }
}

// ---------------- mode epilogue: contiguous (n, n+1) pair ----------------
template<int MODE>
__device__ __forceinline__ void store_pair(float v0, float v1, int m, int n, int z,
    const float* __restrict__ bias, const float* __restrict__ aux,
    float* __restrict__ Cext)
{
    if constexpr (MODE == 0 || MODE == 1) {
        v0 = (v0 + bias[n]) * aux[n];
        v1 = (v1 + bias[n+1]) * aux[n+1];
        const int b = m >> 9, q = m & 511, h = n >> 7, dh = n & 127;
        const size_t idx = (((size_t)((b<<3)|h))*SEQ + q)*DHEAD + dh;  // even
        const unsigned ph = packbf(v0, v1);
        const unsigned pl = packbf(v0 - bf_lo(ph), v1 - bf_up(ph));
        __nv_bfloat16* dh_a = (MODE == 0) ? g_fhh : g_fth;
        __nv_bfloat16* dl_a = (MODE == 0) ? g_fhl : g_ftl;
        *reinterpret_cast<unsigned*>(&dh_a[idx]) = ph;
        *reinterpret_cast<unsigned*>(&dl_a[idx]) = pl;
    } else if constexpr (MODE == 2) {
        const int b = m >> 9, q = m & 511, h = n >> 7, dh = n & 127;
        float2 o; o.x = v0 + bias[n]; o.y = v1 + bias[n+1];
        *reinterpret_cast<float2*>(&g_fv[(((size_t)((b<<3)|h))*SEQ + q)*DHEAD + dh]) = o;
    } else if constexpr (MODE == 3) {
        const int h = z & 7;
        const size_t off = (size_t)m*SEQ + n;
        float2 am = *reinterpret_cast<const float2*>(&g_adjm[(size_t)h*SEQ*SEQ + off]);
        float2 o;
        o.x = v0 * 0.08838834764831845f + am.x;
        o.y = v1 * 0.08838834764831845f + am.y;
        *reinterpret_cast<float2*>(&Cext[(size_t)z*SEQ*SEQ + off]) = o;
    } else {
        float2 o; o.x = v0 + bias[n]; o.y = v1 + bias[n+1];
        *reinterpret_cast<float2*>(&Cext[(size_t)m*DMODEL + n]) = o;
    }
}

// ---------------- bf16 3-term ldmatrix GEMM: C = A[M,K] @ B[N,K]^T ----------------
// 128 threads, 4 warps (2m x 2n), warptile 64x64, 2-stage cp.async pipeline.
#define LDK    40                 // padded smem row (bf16 elems), 80 bytes
#define TILEB  (128*LDK*2)        // 10240 B per tile
#define STAGEB (4*TILEB)          // Ah, Al, Bh, Bl
#define BFG_DSM (2*STAGEB)        // 81920 B

template<int MODE>
__global__ void __launch_bounds__(128, 2)
bf_gemm(const float* __restrict__ bias, const float* __restrict__ aux,
        float* __restrict__ Cext, int K)
{
    extern __shared__ char sm[];
    const unsigned sbase = smem_u32(sm);

    const int tid  = threadIdx.x;
    const int lane = tid & 31;
    const int warp = tid >> 5;
    const int wm   = warp >> 1;   // 0..1, 64 rows each
    const int wn   = warp & 1;    // 0..1, 64 cols each
    const int z    = blockIdx.z;
    const int m0   = blockIdx.y * 128;
    const int n0   = blockIdx.x * 128;

    const __nv_bfloat16 *Ah, *Al, *Bh, *Bl;
    if constexpr (MODE == 0)      { Ah=g_xqh; Al=g_xql; Bh=g_Whh; Bl=g_Whl; }
    else if constexpr (MODE == 1) { Ah=g_xkh; Al=g_xkl; Bh=g_Whh; Bl=g_Whl; }
    else if constexpr (MODE == 2) { Ah=g_xkh; Al=g_xkl; Bh=g_Wvh; Bl=g_Wvl; }
    else if constexpr (MODE == 3) {
        Ah = g_fhh + (size_t)z*SEQ*DHEAD;  Al = g_fhl + (size_t)z*SEQ*DHEAD;
        Bh = g_fth + (size_t)z*SEQ*DHEAD;  Bl = g_ftl + (size_t)z*SEQ*DHEAD;
    } else {
        Ah = g_ath; Al = g_atl; Bh = g_Woh; Bl = g_Wol;
    }

    auto load_stage = [&](int st, int kt) {
        const unsigned sb = sbase + st*STAGEB;
#pragma unroll
        for (int i = 0; i < 16; i++) {
            const int idx  = tid + i*128;          // 0..2047 chunks
            const int tile = idx >> 9;             // 0:Ah 1:Al 2:Bh 3:Bl
            const int r    = (idx >> 2) & 127;
            const int c    = idx & 3;              // 16B chunk within 64B row
            const __nv_bfloat16* s = (tile == 0) ? Ah : (tile == 1) ? Al :
                                     (tile == 2) ? Bh : Bl;
            const int rg = ((tile < 2) ? m0 : n0) + r;
            cpa16s(sb + tile*TILEB + r*(LDK*2) + c*16,
                   s + (size_t)rg*K + kt + c*8);
        }
    };

    float acc[4][8][4];
#pragma unroll
    for (int i = 0; i < 4; i++)
#pragma unroll
        for (int j = 0; j < 8; j++)
#pragma unroll
            for (int f = 0; f < 4; f++) acc[i][j][f] = 0.f;

    // ldmatrix lane geometry
    const int rowA = (lane & 7) + ((lane >> 3) & 1) * 8;
    const int colA = ((lane >> 4) & 1) * 8;
    const int rowB = (lane & 7) + ((lane >> 4) & 1) * 8;
    const int colB = ((lane >> 3) & 1) * 8;

    const int iters = K >> 5;
    load_stage(0, 0);
    cpa_commit();

    for (int it = 0; it < iters; ++it) {
        const int cur = it & 1;
        cpa_wait<0>();
        __syncthreads();
        if (it + 1 < iters) { load_stage(cur ^ 1, (it + 1) << 5); cpa_commit(); }

        const unsigned sb  = sbase + cur*STAGEB;
        const unsigned aAh = sb + (wm*64 + rowA)*(LDK*2) + colA*2;
        const unsigned aAl = aAh + TILEB;
        const unsigned aBh = sb + 2*TILEB + (wn*64 + rowB)*(LDK*2) + colB*2;
        const unsigned aBl = aBh + TILEB;

#pragma unroll
        for (int ks = 0; ks < 2; ks++) {
            const unsigned ko = ks*32;   // 16 bf16 = 32 bytes
            unsigned ah[4][4], al_[4][4], bh[8][2], bl[8][2];
#pragma unroll
            for (int mt = 0; mt < 4; mt++) {
                ldm4(ah[mt][0], ah[mt][1], ah[mt][2], ah[mt][3],
                     aAh + mt*16*(LDK*2) + ko);
                ldm4(al_[mt][0], al_[mt][1], al_[mt][2], al_[mt][3],
                     aAl + mt*16*(LDK*2) + ko);
            }
#pragma unroll
            for (int g = 0; g < 4; g++) {
                unsigned r0, r1, r2, r3;
                ldm4(r0, r1, r2, r3, aBh + g*16*(LDK*2) + ko);
                bh[2*g][0]=r0; bh[2*g][1]=r1; bh[2*g+1][0]=r2; bh[2*g+1][1]=r3;
                ldm4(r0, r1, r2, r3, aBl + g*16*(LDK*2) + ko);
                bl[2*g][0]=r0; bl[2*g][1]=r1; bl[2*g+1][0]=r2; bl[2*g+1][1]=r3;
            }
#pragma unroll
            for (int mt = 0; mt < 4; mt++)
#pragma unroll
                for (int nt = 0; nt < 8; nt++) {
                    mmabf(acc[mt][nt], ah[mt][0],ah[mt][1],ah[mt][2],ah[mt][3],
                          bh[nt][0], bh[nt][1]);
                    mmabf(acc[mt][nt], ah[mt][0],ah[mt][1],ah[mt][2],ah[mt][3],
                          bl[nt][0], bl[nt][1]);
                    mmabf(acc[mt][nt], al_[mt][0],al_[mt][1],al_[mt][2],al_[mt][3],
                          bh[nt][0], bh[nt][1]);
                }
        }
        __syncthreads();
    }

    const int lr2 = lane >> 2;
    const int lc2 = (lane & 3) << 1;
#pragma unroll
    for (int mt = 0; mt < 4; mt++)
#pragma unroll
        for (int nt = 0; nt < 8; nt++) {
            const int mb = m0 + wm*64 + mt*16 + lr2;
            const int nb = n0 + wn*64 + nt*8 + lc2;
            store_pair<MODE>(acc[mt][nt][0], acc[mt][nt][1], mb,   nb, z, bias, aux, Cext);
            store_pair<MODE>(acc[mt][nt][2], acc[mt][nt][3], mb+8, nb, z, bias, aux, Cext);
        }
}

// ---------------- fused softmax + P @ V (unchanged from R6) ----------------
__global__ void __launch_bounds__(256, 2)
gemm_sm_pv(float* __restrict__ fr, int K)
{
    constexpr int BM = 128, PPAD = 12;
    __shared__ __align__(16) unsigned pAh[BM][PPAD];
    __shared__ __align__(16) unsigned pAl[BM][PPAD];
    __shared__ __align__(16) unsigned pBh[128][PPAD];
    __shared__ __align__(16) unsigned pBl[128][PPAD];
    __shared__ float sm_m[BM];
    __shared__ float sm_inv[BM];

    const int tid  = threadIdx.x;
    const int lane = tid & 31;
    const int warp = tid >> 5;
    const int wm   = warp >> 2, wn = warp & 3;
    const int lr   = lane >> 2, lc = lane & 3;
    const int z    = blockIdx.z;

    float* A        = fr + (size_t)z*SEQ*SEQ;
    const float* Bp = g_fv + (size_t)z*SEQ*DHEAD;

    const int m0 = blockIdx.y * BM;

    const int arow  = tid >> 1;
    const int akoff = (tid & 1) << 3;
    const int bn    = tid & 127;
    const int bhalf = tid >> 7;

    float fa[8], fb[8];

    auto ldg_stage = [&](int kt) {
        const float* ap = A + (size_t)(m0 + arow)*K + kt + akoff;
        float4 v0 = *reinterpret_cast<const float4*>(ap);
        float4 v1 = *reinterpret_cast<const float4*>(ap + 4);
        fa[0]=v0.x; fa[1]=v0.y; fa[2]=v0.z; fa[3]=v0.w;
        fa[4]=v1.x; fa[5]=v1.y; fa[6]=v1.z; fa[7]=v1.w;
#pragma unroll
        for (int j = 0; j < 8; j++)
            fb[j] = Bp[(size_t)(kt + 8*bhalf + j)*DHEAD + bn];
    };

    ldg_stage(0);

    // ---- pass 1: per-row max and sum of exp (warp handles 16 rows) ----
    {
        const int r0 = warp * 16;
        for (int rr = 0; rr < 16; rr++) {
            const int r = r0 + rr;
            const float4* rp = reinterpret_cast<const float4*>(A + (size_t)(m0 + r)*SEQ);
            float4 v0 = rp[lane], v1 = rp[lane+32], v2 = rp[lane+64], v3 = rp[lane+96];
            float mx = fmaxf(fmaxf(fmaxf(v0.x,v0.y), fmaxf(v0.z,v0.w)),
                      fmaxf(fmaxf(fmaxf(v1.x,v1.y), fmaxf(v1.z,v1.w)),
                      fmaxf(fmaxf(fmaxf(v2.x,v2.y), fmaxf(v2.z,v2.w)),
                            fmaxf(fmaxf(v3.x,v3.y), fmaxf(v3.z,v3.w)))));
#pragma unroll
            for (int o = 16; o; o >>= 1) mx = fmaxf(mx, __shfl_xor_sync(0xffffffffu, mx, o));
            float s = __expf(v0.x-mx)+__expf(v0.y-mx)+__expf(v0.z-mx)+__expf(v0.w-mx)
                    + __expf(v1.x-mx)+__expf(v1.y-mx)+__expf(v1.z-mx)+__expf(v1.w-mx)
                    + __expf(v2.x-mx)+__expf(v2.y-mx)+__expf(v2.z-mx)+__expf(v2.w-mx)
                    + __expf(v3.x-mx)+__expf(v3.y-mx)+__expf(v3.z-mx)+__expf(v3.w-mx);
#pragma unroll
            for (int o = 16; o; o >>= 1) s += __shfl_xor_sync(0xffffffffu, s, o);
            if (lane == 0) { sm_m[r] = mx; sm_inv[r] = 1.f/s; }
        }
    }
    __syncthreads();

    float acc[4][4][4];
#pragma unroll
    for (int i = 0; i < 4; i++)
#pragma unroll
        for (int j = 0; j < 4; j++)
#pragma unroll
            for (int f = 0; f < 4; f++) acc[i][j][f] = 0.f;

    const int iters = K / 16;

    for (int it = 0; it < iters; ++it) {
        __syncthreads();
        {
            const float mr = sm_m[arow];
            const float ir = sm_inv[arow];
#pragma unroll
            for (int j = 0; j < 8; j++) fa[j] = __expf(fa[j] - mr) * ir;

            float* ap = A + (size_t)(m0 + arow)*K + it*16 + akoff;
            *reinterpret_cast<float4*>(ap)     = make_float4(fa[0], fa[1], fa[2], fa[3]);
            *reinterpret_cast<float4*>(ap + 4) = make_float4(fa[4], fa[5], fa[6], fa[7]);

            unsigned ph[4], pl[4];
            cvt8(fa, ph, pl);
            *reinterpret_cast<uint4*>(&pAh[arow][akoff >> 1]) = make_uint4(ph[0],ph[1],ph[2],ph[3]);
            *reinterpret_cast<uint4*>(&pAl[arow][akoff >> 1]) = make_uint4(pl[0],pl[1],pl[2],pl[3]);
            cvt8(fb, ph, pl);
            *reinterpret_cast<uint4*>(&pBh[bn][4*bhalf]) = make_uint4(ph[0],ph[1],ph[2],ph[3]);
            *reinterpret_cast<uint4*>(&pBl[bn][4*bhalf]) = make_uint4(pl[0],pl[1],pl[2],pl[3]);
        }
        __syncthreads();

        if (it + 1 < iters) ldg_stage((it + 1) * 16);

        uint2 a0[4], a1[4], b_h[4], b_l[4];
#pragma unroll
        for (int mt = 0; mt < 4; mt++) {
            const int r = wm*64 + mt*16 + lr;
            a0[mt] = *reinterpret_cast<const uint2*>(&pAh[r  ][2*lc]);
            a1[mt] = *reinterpret_cast<const uint2*>(&pAh[r+8][2*lc]);
        }
#pragma unroll
        for (int nt = 0; nt < 4; nt++) {
            const int c = wn*32 + nt*8 + lr;
            b_h[nt] = *reinterpret_cast<const uint2*>(&pBh[c][2*lc]);
            b_l[nt] = *reinterpret_cast<const uint2*>(&pBl[c][2*lc]);
        }
#pragma unroll
        for (int mt = 0; mt < 4; mt++)
#pragma unroll
            for (int nt = 0; nt < 4; nt++) {
                mmabf(acc[mt][nt], a0[mt].x, a1[mt].x, a0[mt].y, a1[mt].y, b_h[nt].x, b_h[nt].y);
                mmabf(acc[mt][nt], a0[mt].x, a1[mt].x, a0[mt].y, a1[mt].y, b_l[nt].x, b_l[nt].y);
            }
#pragma unroll
        for (int mt = 0; mt < 4; mt++) {
            const int r = wm*64 + mt*16 + lr;
            a0[mt] = *reinterpret_cast<const uint2*>(&pAl[r  ][2*lc]);
            a1[mt] = *reinterpret_cast<const uint2*>(&pAl[r+8][2*lc]);
        }
#pragma unroll
        for (int mt = 0; mt < 4; mt++)
#pragma unroll
            for (int nt = 0; nt < 4; nt++)
                mmabf(acc[mt][nt], a0[mt].x, a1[mt].x, a0[mt].y, a1[mt].y, b_h[nt].x, b_h[nt].y);
    }

    const int b = z >> 3, h = z & 7;
    const int lc2 = (lane & 3) << 1;
#pragma unroll
    for (int mt = 0; mt < 4; mt++)
#pragma unroll
        for (int nt = 0; nt < 4; nt++) {
            const int mb = m0 + wm*64 + mt*16 + lr;
            const int nb = wn*32 + nt*8 + lc2;
#pragma unroll
            for (int hh = 0; hh < 2; hh++) {
                const float v0 = acc[mt][nt][hh*2+0];
                const float v1 = acc[mt][nt][hh*2+1];
                const size_t idx = ((size_t)(b*SEQ + mb + hh*8))*DMODEL + h*DHEAD + nb;
                const unsigned ph = packbf(v0, v1);
                const unsigned pl = packbf(v0 - bf_lo(ph), v1 - bf_up(ph));
                *reinterpret_cast<unsigned*>(&g_ath[idx]) = ph;
                *reinterpret_cast<unsigned*>(&g_atl[idx]) = pl;
            }
        }
}

// ---------------- launch ----------------
extern "C" void kernel_launch(void* const* d_in, const int* in_sizes, int n_in,
                              void* d_out, int out_size)
{
    const float* x_q      = (const float*)d_in[0];
    const float* x_kv     = (const float*)d_in[1];
    const float* W_head_w = (const float*)d_in[2];
    const float* W_head_b = (const float*)d_in[3];
    const float* W_v_w    = (const float*)d_in[4];
    const float* W_v_b    = (const float*)d_in[5];
    const float* W_out_w  = (const float*)d_in[6];
    const float* W_out_b  = (const float*)d_in[7];
    const float* rel_emb  = (const float*)d_in[8];
    const float* col_head = (const float*)d_in[9];
    const float* col_tail = (const float*)d_in[10];

    float* out_x  = (float*)d_out;                          // [32,512,1024]
    float* out_fr = out_x + (size_t)BATCH*SEQ*DMODEL;       // [256,512,512]

    static bool attr_done = false;
    if (!attr_done) {
        cudaFuncSetAttribute(bf_gemm<0>, cudaFuncAttributeMaxDynamicSharedMemorySize, BFG_DSM);
        cudaFuncSetAttribute(bf_gemm<1>, cudaFuncAttributeMaxDynamicSharedMemorySize, BFG_DSM);
        cudaFuncSetAttribute(bf_gemm<2>, cudaFuncAttributeMaxDynamicSharedMemorySize, BFG_DSM);
        cudaFuncSetAttribute(bf_gemm<3>, cudaFuncAttributeMaxDynamicSharedMemorySize, BFG_DSM);
        cudaFuncSetAttribute(bf_gemm<5>, cudaFuncAttributeMaxDynamicSharedMemorySize, BFG_DSM);
        attr_done = true;
    }

    // 0) pre-convert inputs to bf16 hi/lo
    cvt_hilo<0><<<2048, 256>>>(x_q,      (int)(BSD/4));
    cvt_hilo<1><<<2048, 256>>>(x_kv,     (int)(BSD/4));
    cvt_hilo<2><<<1024, 256>>>(W_head_w, DMODEL*DMODEL/4);
    cvt_hilo<3><<<1024, 256>>>(W_v_w,    DMODEL*DMODEL/4);
    cvt_hilo<4><<<1024, 256>>>(W_out_w,  DMODEL*DMODEL/4);

    // 1) learned column topology mask
    adj_kernel<<<dim3(SEQ, HEADS), 128>>>(col_head, col_tail);

    // 2) projections (128-thread, 64x64-warptile GEMM)
    bf_gemm<0><<<dim3(8, 128), 128, BFG_DSM>>>(W_head_b, rel_emb, nullptr, DMODEL);
    bf_gemm<1><<<dim3(8, 128), 128, BFG_DSM>>>(W_head_b, rel_emb, nullptr, DMODEL);
    bf_gemm<2><<<dim3(8, 128), 128, BFG_DSM>>>(W_v_b,    nullptr, nullptr, DMODEL);

    // 3) scores + mask -> fr region of d_out (raw logits)
    bf_gemm<3><<<dim3(4, 4, BHS), 128, BFG_DSM>>>(nullptr, nullptr, out_fr, DHEAD);

    // 4+5) fused softmax + P @ V -> fr gets final probabilities, attn hi/lo produced
    gemm_sm_pv<<<dim3(1, 4, BHS), 256>>>(out_fr, SEQ);

    // 6) output projection
    bf_gemm<5><<<dim3(8, 128), 128, BFG_DSM>>>(W_out_b, nullptr, out_x, DMODEL);
}

// round 8
// speedup vs baseline: 1.0649x; 1.0649x over previous
#include <cuda_runtime.h>
#include <cuda_bf16.h>
#include <math.h>
#include <cstdint>

#define BATCH   32
#define HEADS   8
#define SEQ     512
#define DMODEL  1024
#define DHEAD   128
#define DCOL    18
#define BHS     (BATCH*HEADS)   // 256
#define BSD     ((size_t)BATCH*SEQ*DMODEL)   // 16777216

// ---------------- scratch (static device globals; no allocation) ----------------
__device__ __align__(256) __nv_bfloat16 g_xqh[BSD], g_xql[BSD];
__device__ __align__(256) __nv_bfloat16 g_xkh[BSD], g_xkl[BSD];
__device__ __align__(256) __nv_bfloat16 g_Whh[DMODEL*DMODEL], g_Whl[DMODEL*DMODEL];
__device__ __align__(256) __nv_bfloat16 g_Wvh[DMODEL*DMODEL], g_Wvl[DMODEL*DMODEL];
__device__ __align__(256) __nv_bfloat16 g_Woh[DMODEL*DMODEL], g_Wol[DMODEL*DMODEL];
__device__ __align__(256) __nv_bfloat16 g_fhh[BSD], g_fhl[BSD];   // f_head hi/lo [b,h,q,dh]
__device__ __align__(256) __nv_bfloat16 g_fth[BSD], g_ftl[BSD];   // f_tail hi/lo [b,h,k,dh]
__device__ __align__(256) float        g_fv [BSD];                 // f_v fp32 [b,h,k,dh]
__device__ __align__(256) __nv_bfloat16 g_ath[BSD], g_atl[BSD];    // attn hi/lo [b,q,h*dh]
__device__ __align__(256) float        g_adjm[(size_t)HEADS*SEQ*SEQ];

// ---------------- small helpers ----------------
__device__ __forceinline__ unsigned packbf(float f0, float f1) {   // f0 -> low half
    unsigned d;
    asm("cvt.rn.bf16x2.f32 %0, %1, %2;" : "=r"(d) : "f"(f1), "f"(f0));
    return d;
}
__device__ __forceinline__ float bf_lo(unsigned p) { return __uint_as_float(p << 16); }
__device__ __forceinline__ float bf_up(unsigned p) { return __uint_as_float(p & 0xFFFF0000u); }

__device__ __forceinline__ unsigned smem_u32(const void* p) {
    unsigned a;
    asm("{ .reg .u64 t; cvta.to.shared.u64 t, %1; cvt.u32.u64 %0, t; }" : "=r"(a) : "l"(p));
    return a;
}
__device__ __forceinline__ void cpa16s(unsigned dst, const void* src) {
    asm volatile("cp.async.ca.shared.global [%0], [%1], 16;" :: "r"(dst), "l"(src));
}
__device__ __forceinline__ void cpa_commit() { asm volatile("cp.async.commit_group;"); }
template<int N>
__device__ __forceinline__ void cpa_wait() { asm volatile("cp.async.wait_group %0;" :: "n"(N)); }

__device__ __forceinline__ void ldm4(unsigned& r0, unsigned& r1, unsigned& r2, unsigned& r3,
                                     unsigned addr) {
    asm volatile("ldmatrix.sync.aligned.m8n8.x4.shared.b16 {%0,%1,%2,%3}, [%4];"
                 : "=r"(r0), "=r"(r1), "=r"(r2), "=r"(r3) : "r"(addr));
}

__device__ __forceinline__ void mmabf(float* c, unsigned a0, unsigned a1, unsigned a2,
                                      unsigned a3, unsigned b0, unsigned b1) {
    asm volatile(
        "mma.sync.aligned.m16n8k16.row.col.f32.bf16.bf16.f32 "
        "{%0,%1,%2,%3}, {%4,%5,%6,%7}, {%8,%9}, {%0,%1,%2,%3};\n"
        : "+f"(c[0]), "+f"(c[1]), "+f"(c[2]), "+f"(c[3])
        : "r"(a0), "r"(a1), "r"(a2), "r"(a3), "r"(b0), "r"(b1));
}

__device__ __forceinline__ void cvt8(const float* f, unsigned* ph, unsigned* pl) {
#pragma unroll
    for (int j = 0; j < 4; j++) {
        unsigned h = packbf(f[2*j], f[2*j+1]);
        ph[j] = h;
        pl[j] = packbf(f[2*j] - bf_lo(h), f[2*j+1] - bf_up(h));
    }
}

// ---------------- fp32 -> bf16 hi/lo conversion (W selects destination) ----------------
template<int W>
__global__ void cvt_hilo(const float* __restrict__ src, int n4)
{
    __nv_bfloat16 *hi, *lo;
    if constexpr (W == 0) { hi = g_xqh; lo = g_xql; }
    else if constexpr (W == 1) { hi = g_xkh; lo = g_xkl; }
    else if constexpr (W == 2) { hi = g_Whh; lo = g_Whl; }
    else if constexpr (W == 3) { hi = g_Wvh; lo = g_Wvl; }
    else                       { hi = g_Woh; lo = g_Wol; }
    uint2* hu = reinterpret_cast<uint2*>(hi);
    uint2* lu = reinterpret_cast<uint2*>(lo);
    const float4* s4 = reinterpret_cast<const float4*>(src);
    for (int i = blockIdx.x * blockDim.x + threadIdx.x; i < n4; i += gridDim.x * blockDim.x) {
        float4 v = s4[i];
        unsigned h0 = packbf(v.x, v.y), h1 = packbf(v.z, v.w);
        unsigned l0 = packbf(v.x - bf_lo(h0), v.y - bf_up(h0));
        unsigned l1 = packbf(v.z - bf_lo(h1), v.w - bf_up(h1));
        hu[i] = make_uint2(h0, h1);
        lu[i] = make_uint2(l0, l1);
    }
}

// ---------------- adjacency: softmax(col_head @ col_tail^T, diag=0) ----------------
__global__ void adj_kernel(const float* __restrict__ col_head,
                           const float* __restrict__ col_tail)
{
    const int q = blockIdx.x;
    const int h = blockIdx.y;
    const int t = threadIdx.x;                 // 128 threads
    __shared__ float ch[DCOL];
    __shared__ float sred[4];

    if (t < DCOL) ch[t] = col_head[((size_t)h*SEQ + q)*DCOL + t];
    __syncthreads();

    float l[4];
#pragma unroll
    for (int i = 0; i < 4; i++) {
        const int k = t + i*128;
        const float* ct = col_tail + ((size_t)h*SEQ + k)*DCOL;
        float s = 0.f;
#pragma unroll
        for (int c = 0; c < DCOL; c++) s += ch[c]*ct[c];
        l[i] = (k == q) ? 0.f : s;
    }

    float mx = fmaxf(fmaxf(l[0],l[1]), fmaxf(l[2],l[3]));
#pragma unroll
    for (int o = 16; o; o >>= 1) mx = fmaxf(mx, __shfl_xor_sync(0xffffffffu, mx, o));
    if ((t & 31) == 0) sred[t >> 5] = mx;
    __syncthreads();
    mx = fmaxf(fmaxf(sred[0],sred[1]), fmaxf(sred[2],sred[3]));
    __syncthreads();

    float e[4]; float sum = 0.f;
#pragma unroll
    for (int i = 0; i < 4; i++) { e[i] = expf(l[i]-mx); sum += e[i]; }
#pragma unroll
    for (int o = 16; o; o >>= 1) sum += __shfl_xor_sync(0xffffffffu, sum, o);
    if ((t & 31) == 0) sred[t >> 5] = sum;
    __syncthreads();
    sum = sred[0]+sred[1]+sred[2]+sred[3];
    const float inv = 1.f/sum;

    float* dst = g_adjm + ((size_t)h*SEQ + q)*SEQ;
#pragma unroll
    for (int i = 0; i < 4; i++) {
        const int k = t + i*128;
        dst[k] = (1.f - e[i]*inv) * (-10000.f);
    }
}

// ---------------- mode epilogue: contiguous (n, n+1) pair ----------------
template<int MODE>
__device__ __forceinline__ void store_pair(float v0, float v1, int m, int n, int z,
    const float* __restrict__ bias, const float* __restrict__ aux,
    float* __restrict__ Cext)
{
    if constexpr (MODE == 0 || MODE == 1) {
        v0 = (v0 + bias[n]) * aux[n];
        v1 = (v1 + bias[n+1]) * aux[n+1];
        const int b = m >> 9, q = m & 511, h = n >> 7, dh = n & 127;
        const size_t idx = (((size_t)((b<<3)|h))*SEQ + q)*DHEAD + dh;  // even
        const unsigned ph = packbf(v0, v1);
        const unsigned pl = packbf(v0 - bf_lo(ph), v1 - bf_up(ph));
        __nv_bfloat16* dh_a = (MODE == 0) ? g_fhh : g_fth;
        __nv_bfloat16* dl_a = (MODE == 0) ? g_fhl : g_ftl;
        *reinterpret_cast<unsigned*>(&dh_a[idx]) = ph;
        *reinterpret_cast<unsigned*>(&dl_a[idx]) = pl;
    } else if constexpr (MODE == 2) {
        const int b = m >> 9, q = m & 511, h = n >> 7, dh = n & 127;
        float2 o; o.x = v0 + bias[n]; o.y = v1 + bias[n+1];
        *reinterpret_cast<float2*>(&g_fv[(((size_t)((b<<3)|h))*SEQ + q)*DHEAD + dh]) = o;
    } else if constexpr (MODE == 3) {
        const int h = z & 7;
        const size_t off = (size_t)m*SEQ + n;
        float2 am = *reinterpret_cast<const float2*>(&g_adjm[(size_t)h*SEQ*SEQ + off]);
        float2 o;
        o.x = v0 * 0.08838834764831845f + am.x;
        o.y = v1 * 0.08838834764831845f + am.y;
        *reinterpret_cast<float2*>(&Cext[(size_t)z*SEQ*SEQ + off]) = o;
    } else {
        float2 o; o.x = v0 + bias[n]; o.y = v1 + bias[n+1];
        *reinterpret_cast<float2*>(&Cext[(size_t)m*DMODEL + n]) = o;
    }
}

// ---------------- bf16 3-term ldmatrix GEMM (R5-proven 256-thread version) ----------------
#define LDK    40                 // padded smem row (bf16 elems), 80 bytes
#define TILEB  (128*LDK*2)        // 10240 B per tile
#define STAGEB (4*TILEB)          // Ah, Al, Bh, Bl
#define BFG_DSM (2*STAGEB)        // 81920 B

template<int MODE>
__global__ void __launch_bounds__(256, 2)
bf_gemm(const float* __restrict__ bias, const float* __restrict__ aux,
        float* __restrict__ Cext, int K)
{
    extern __shared__ char sm[];
    const unsigned sbase = smem_u32(sm);

    const int tid  = threadIdx.x;
    const int lane = tid & 31;
    const int warp = tid >> 5;
    const int wm   = warp >> 2, wn = warp & 3;
    const int z    = blockIdx.z;
    const int m0   = blockIdx.y * 128;
    const int n0   = blockIdx.x * 128;

    const __nv_bfloat16 *Ah, *Al, *Bh, *Bl;
    if constexpr (MODE == 0)      { Ah=g_xqh; Al=g_xql; Bh=g_Whh; Bl=g_Whl; }
    else if constexpr (MODE == 1) { Ah=g_xkh; Al=g_xkl; Bh=g_Whh; Bl=g_Whl; }
    else if constexpr (MODE == 2) { Ah=g_xkh; Al=g_xkl; Bh=g_Wvh; Bl=g_Wvl; }
    else if constexpr (MODE == 3) {
        Ah = g_fhh + (size_t)z*SEQ*DHEAD;  Al = g_fhl + (size_t)z*SEQ*DHEAD;
        Bh = g_fth + (size_t)z*SEQ*DHEAD;  Bl = g_ftl + (size_t)z*SEQ*DHEAD;
    } else {
        Ah = g_ath; Al = g_atl; Bh = g_Woh; Bl = g_Wol;
    }

    auto load_stage = [&](int st, int kt) {
        const unsigned sb = sbase + st*STAGEB;
#pragma unroll
        for (int i = 0; i < 8; i++) {
            const int idx  = tid + i*256;          // 0..2047 chunks
            const int tile = idx >> 9;             // 0:Ah 1:Al 2:Bh 3:Bl
            const int r    = (idx >> 2) & 127;
            const int c    = idx & 3;              // 16B chunk within 64B row
            const __nv_bfloat16* s = (tile == 0) ? Ah : (tile == 1) ? Al :
                                     (tile == 2) ? Bh : Bl;
            const int rg = ((tile < 2) ? m0 : n0) + r;
            cpa16s(sb + tile*TILEB + r*(LDK*2) + c*16,
                   s + (size_t)rg*K + kt + c*8);
        }
    };

    float acc[4][4][4];
#pragma unroll
    for (int i = 0; i < 4; i++)
#pragma unroll
        for (int j = 0; j < 4; j++)
#pragma unroll
            for (int f = 0; f < 4; f++) acc[i][j][f] = 0.f;

    // ldmatrix lane geometry
    const int rowA = (lane & 7) + ((lane >> 3) & 1) * 8;
    const int colA = ((lane >> 4) & 1) * 8;
    const int rowB = (lane & 7) + ((lane >> 4) & 1) * 8;
    const int colB = ((lane >> 3) & 1) * 8;

    const int iters = K >> 5;
    load_stage(0, 0);
    cpa_commit();

    for (int it = 0; it < iters; ++it) {
        const int cur = it & 1;
        if (it + 1 < iters) { load_stage(cur ^ 1, (it + 1) << 5); cpa_commit(); cpa_wait<1>(); }
        else                { cpa_wait<0>(); }
        __syncthreads();

        const unsigned sb  = sbase + cur*STAGEB;
        const unsigned aAh = sb + (wm*64 + rowA)*(LDK*2) + colA*2;
        const unsigned aAl = aAh + TILEB;
        const unsigned aBh = sb + 2*TILEB + (wn*32 + rowB)*(LDK*2) + colB*2;
        const unsigned aBl = aBh + TILEB;

#pragma unroll
        for (int ks = 0; ks < 2; ks++) {
            const unsigned ko = ks*32;   // 16 bf16 = 32 bytes
            unsigned bh[4][2], bl[4][2];
#pragma unroll
            for (int p = 0; p < 2; p++) {
                unsigned r0, r1, r2, r3;
                ldm4(r0, r1, r2, r3, aBh + p*16*(LDK*2) + ko);
                bh[2*p][0]=r0; bh[2*p][1]=r1; bh[2*p+1][0]=r2; bh[2*p+1][1]=r3;
                ldm4(r0, r1, r2, r3, aBl + p*16*(LDK*2) + ko);
                bl[2*p][0]=r0; bl[2*p][1]=r1; bl[2*p+1][0]=r2; bl[2*p+1][1]=r3;
            }
#pragma unroll
            for (int mt = 0; mt < 4; mt++) {
                unsigned a[4], al_[4];
                ldm4(a[0], a[1], a[2], a[3],     aAh + mt*16*(LDK*2) + ko);
                ldm4(al_[0], al_[1], al_[2], al_[3], aAl + mt*16*(LDK*2) + ko);
#pragma unroll
                for (int nt = 0; nt < 4; nt++) {
                    mmabf(acc[mt][nt], a[0],a[1],a[2],a[3],     bh[nt][0], bh[nt][1]);
                    mmabf(acc[mt][nt], a[0],a[1],a[2],a[3],     bl[nt][0], bl[nt][1]);
                    mmabf(acc[mt][nt], al_[0],al_[1],al_[2],al_[3], bh[nt][0], bh[nt][1]);
                }
            }
        }
        __syncthreads();
    }

    const int lr2 = lane >> 2;
    const int lc2 = (lane & 3) << 1;
#pragma unroll
    for (int mt = 0; mt < 4; mt++)
#pragma unroll
        for (int nt = 0; nt < 4; nt++) {
            const int mb = m0 + wm*64 + mt*16 + lr2;
            const int nb = n0 + wn*32 + nt*8 + lc2;
            store_pair<MODE>(acc[mt][nt][0], acc[mt][nt][1], mb,   nb, z, bias, aux, Cext);
            store_pair<MODE>(acc[mt][nt][2], acc[mt][nt][3], mb+8, nb, z, bias, aux, Cext);
        }
}

// ---------------- fused softmax + P @ V, double-buffered packed smem ----------------
// Dynamic smem layout (words): buffer b at b*6144:
//   pAh: +0, pAl: +1536, pBh: +3072, pBl: +4608   (each 128 rows x 12 words)
// sm_m at byte 49152 (128 floats), sm_inv after it.
#define PV_DSM (49152 + 1024)

__global__ void __launch_bounds__(256, 2)
gemm_sm_pv(float* __restrict__ fr, int K)
{
    extern __shared__ char sm[];
    unsigned* pW  = reinterpret_cast<unsigned*>(sm);
    float* sm_m   = reinterpret_cast<float*>(sm + 49152);
    float* sm_inv = sm_m + 128;

    const int tid  = threadIdx.x;
    const int lane = tid & 31;
    const int warp = tid >> 5;
    const int wm   = warp >> 2, wn = warp & 3;
    const int lr   = lane >> 2, lc = lane & 3;
    const int z    = blockIdx.z;

    float* A        = fr + (size_t)z*SEQ*SEQ;
    const float* Bp = g_fv + (size_t)z*SEQ*DHEAD;

    const int m0 = blockIdx.y * 128;

    const int arow  = tid >> 1;          // 0..127
    const int akoff = (tid & 1) << 3;    // 0 or 8
    const int bn    = tid & 127;
    const int bhalf = tid >> 7;

    float fa[8], fb[8];

    auto ldg_stage = [&](int kt) {
        const float* ap = A + (size_t)(m0 + arow)*K + kt + akoff;
        float4 v0 = *reinterpret_cast<const float4*>(ap);
        float4 v1 = *reinterpret_cast<const float4*>(ap + 4);
        fa[0]=v0.x; fa[1]=v0.y; fa[2]=v0.z; fa[3]=v0.w;
        fa[4]=v1.x; fa[5]=v1.y; fa[6]=v1.z; fa[7]=v1.w;
#pragma unroll
        for (int j = 0; j < 8; j++)
            fb[j] = Bp[(size_t)(kt + 8*bhalf + j)*DHEAD + bn];
    };

    ldg_stage(0);

    // ---- pass 1: per-row max and sum of exp (warp handles 16 rows) ----
    {
        const int r0 = warp * 16;
        for (int rr = 0; rr < 16; rr++) {
            const int r = r0 + rr;
            const float4* rp = reinterpret_cast<const float4*>(A + (size_t)(m0 + r)*SEQ);
            float4 v0 = rp[lane], v1 = rp[lane+32], v2 = rp[lane+64], v3 = rp[lane+96];
            float mx = fmaxf(fmaxf(fmaxf(v0.x,v0.y), fmaxf(v0.z,v0.w)),
                      fmaxf(fmaxf(fmaxf(v1.x,v1.y), fmaxf(v1.z,v1.w)),
                      fmaxf(fmaxf(fmaxf(v2.x,v2.y), fmaxf(v2.z,v2.w)),
                            fmaxf(fmaxf(v3.x,v3.y), fmaxf(v3.z,v3.w)))));
#pragma unroll
            for (int o = 16; o; o >>= 1) mx = fmaxf(mx, __shfl_xor_sync(0xffffffffu, mx, o));
            float s = __expf(v0.x-mx)+__expf(v0.y-mx)+__expf(v0.z-mx)+__expf(v0.w-mx)
                    + __expf(v1.x-mx)+__expf(v1.y-mx)+__expf(v1.z-mx)+__expf(v1.w-mx)
                    + __expf(v2.x-mx)+__expf(v2.y-mx)+__expf(v2.z-mx)+__expf(v2.w-mx)
                    + __expf(v3.x-mx)+__expf(v3.y-mx)+__expf(v3.z-mx)+__expf(v3.w-mx);
#pragma unroll
            for (int o = 16; o; o >>= 1) s += __shfl_xor_sync(0xffffffffu, s, o);
            if (lane == 0) { sm_m[r] = mx; sm_inv[r] = 1.f/s; }
        }
    }
    __syncthreads();   // stats ready; all pass-1 reads of A complete

    float acc[4][4][4];
#pragma unroll
    for (int i = 0; i < 4; i++)
#pragma unroll
        for (int j = 0; j < 4; j++)
#pragma unroll
            for (int f = 0; f < 4; f++) acc[i][j][f] = 0.f;

    const int iters = K / 16;   // 32

    for (int it = 0; it < iters; ++it) {
        const unsigned b0 = (unsigned)(it & 1) * 6144;

        // ---- pack(it) into buffer (it&1); data for chunk `it` is in fa/fb regs ----
        {
            const float mr = sm_m[arow];
            const float ir = sm_inv[arow];
#pragma unroll
            for (int j = 0; j < 8; j++) fa[j] = __expf(fa[j] - mr) * ir;

            // in-place P writeback (fr_graph output)
            float* ap = A + (size_t)(m0 + arow)*K + it*16 + akoff;
            *reinterpret_cast<float4*>(ap)     = make_float4(fa[0], fa[1], fa[2], fa[3]);
            *reinterpret_cast<float4*>(ap + 4) = make_float4(fa[4], fa[5], fa[6], fa[7]);

            unsigned ph[4], pl[4];
            cvt8(fa, ph, pl);
            *reinterpret_cast<uint4*>(&pW[b0 +        arow*12 + (akoff >> 1)]) =
                make_uint4(ph[0], ph[1], ph[2], ph[3]);
            *reinterpret_cast<uint4*>(&pW[b0 + 1536 + arow*12 + (akoff >> 1)]) =
                make_uint4(pl[0], pl[1], pl[2], pl[3]);
            cvt8(fb, ph, pl);
            *reinterpret_cast<uint4*>(&pW[b0 + 3072 + bn*12 + 4*bhalf]) =
                make_uint4(ph[0], ph[1], ph[2], ph[3]);
            *reinterpret_cast<uint4*>(&pW[b0 + 4608 + bn*12 + 4*bhalf]) =
                make_uint4(pl[0], pl[1], pl[2], pl[3]);
        }
        __syncthreads();   // buf(it&1) ready; compute(it-1) finished for all warps

        if (it + 1 < iters) ldg_stage((it + 1) * 16);   // LDG overlaps compute below

        // ---- compute(it) from buffer (it&1) ----
        uint2 a0[4], a1[4], b_h[4], b_l[4];
#pragma unroll
        for (int mt = 0; mt < 4; mt++) {
            const int r = wm*64 + mt*16 + lr;
            a0[mt] = *reinterpret_cast<const uint2*>(&pW[b0 + r*12 + 2*lc]);
            a1[mt] = *reinterpret_cast<const uint2*>(&pW[b0 + (r+8)*12 + 2*lc]);
        }
#pragma unroll
        for (int nt = 0; nt < 4; nt++) {
            const int c = wn*32 + nt*8 + lr;
            b_h[nt] = *reinterpret_cast<const uint2*>(&pW[b0 + 3072 + c*12 + 2*lc]);
            b_l[nt] = *reinterpret_cast<const uint2*>(&pW[b0 + 4608 + c*12 + 2*lc]);
        }
#pragma unroll
        for (int mt = 0; mt < 4; mt++)
#pragma unroll
            for (int nt = 0; nt < 4; nt++) {
                mmabf(acc[mt][nt], a0[mt].x, a1[mt].x, a0[mt].y, a1[mt].y, b_h[nt].x, b_h[nt].y);
                mmabf(acc[mt][nt], a0[mt].x, a1[mt].x, a0[mt].y, a1[mt].y, b_l[nt].x, b_l[nt].y);
            }
#pragma unroll
        for (int mt = 0; mt < 4; mt++) {
            const int r = wm*64 + mt*16 + lr;
            a0[mt] = *reinterpret_cast<const uint2*>(&pW[b0 + 1536 + r*12 + 2*lc]);
            a1[mt] = *reinterpret_cast<const uint2*>(&pW[b0 + 1536 + (r+8)*12 + 2*lc]);
        }
#pragma unroll
        for (int mt = 0; mt < 4; mt++)
#pragma unroll
            for (int nt = 0; nt < 4; nt++)
                mmabf(acc[mt][nt], a0[mt].x, a1[mt].x, a0[mt].y, a1[mt].y, b_h[nt].x, b_h[nt].y);
        // no trailing sync: next iteration packs the OTHER buffer
    }

    // epilogue: emit attn hi/lo bf16 pairs
    const int b = z >> 3, h = z & 7;
    const int lc2 = (lane & 3) << 1;
#pragma unroll
    for (int mt = 0; mt < 4; mt++)
#pragma unroll
        for (int nt = 0; nt < 4; nt++) {
            const int mb = m0 + wm*64 + mt*16 + lr;
            const int nb = wn*32 + nt*8 + lc2;
#pragma unroll
            for (int hh = 0; hh < 2; hh++) {
                const float v0 = acc[mt][nt][hh*2+0];
                const float v1 = acc[mt][nt][hh*2+1];
                const size_t idx = ((size_t)(b*SEQ + mb + hh*8))*DMODEL + h*DHEAD + nb;
                const unsigned ph = packbf(v0, v1);
                const unsigned pl = packbf(v0 - bf_lo(ph), v1 - bf_up(ph));
                *reinterpret_cast<unsigned*>(&g_ath[idx]) = ph;
                *reinterpret_cast<unsigned*>(&g_atl[idx]) = pl;
            }
        }
}

// ---------------- launch ----------------
extern "C" void kernel_launch(void* const* d_in, const int* in_sizes, int n_in,
                              void* d_out, int out_size)
{
    const float* x_q      = (const float*)d_in[0];
    const float* x_kv     = (const float*)d_in[1];
    const float* W_head_w = (const float*)d_in[2];
    const float* W_head_b = (const float*)d_in[3];
    const float* W_v_w    = (const float*)d_in[4];
    const float* W_v_b    = (const float*)d_in[5];
    const float* W_out_w  = (const float*)d_in[6];
    const float* W_out_b  = (const float*)d_in[7];
    const float* rel_emb  = (const float*)d_in[8];
    const float* col_head = (const float*)d_in[9];
    const float* col_tail = (const float*)d_in[10];

    float* out_x  = (float*)d_out;                          // [32,512,1024]
    float* out_fr = out_x + (size_t)BATCH*SEQ*DMODEL;       // [256,512,512]

    static bool attr_done = false;
    if (!attr_done) {
        cudaFuncSetAttribute(bf_gemm<0>, cudaFuncAttributeMaxDynamicSharedMemorySize, BFG_DSM);
        cudaFuncSetAttribute(bf_gemm<1>, cudaFuncAttributeMaxDynamicSharedMemorySize, BFG_DSM);
        cudaFuncSetAttribute(bf_gemm<2>, cudaFuncAttributeMaxDynamicSharedMemorySize, BFG_DSM);
        cudaFuncSetAttribute(bf_gemm<3>, cudaFuncAttributeMaxDynamicSharedMemorySize, BFG_DSM);
        cudaFuncSetAttribute(bf_gemm<5>, cudaFuncAttributeMaxDynamicSharedMemorySize, BFG_DSM);
        cudaFuncSetAttribute(gemm_sm_pv, cudaFuncAttributeMaxDynamicSharedMemorySize, PV_DSM);
        attr_done = true;
    }

    // 0) pre-convert inputs to bf16 hi/lo
    cvt_hilo<0><<<2048, 256>>>(x_q,      (int)(BSD/4));
    cvt_hilo<1><<<2048, 256>>>(x_kv,     (int)(BSD/4));
    cvt_hilo<2><<<1024, 256>>>(W_head_w, DMODEL*DMODEL/4);
    cvt_hilo<3><<<1024, 256>>>(W_v_w,    DMODEL*DMODEL/4);
    cvt_hilo<4><<<1024, 256>>>(W_out_w,  DMODEL*DMODEL/4);

    // 1) learned column topology mask
    adj_kernel<<<dim3(SEQ, HEADS), 128>>>(col_head, col_tail);

    // 2) projections
    bf_gemm<0><<<dim3(8, 128), 256, BFG_DSM>>>(W_head_b, rel_emb, nullptr, DMODEL);
    bf_gemm<1><<<dim3(8, 128), 256, BFG_DSM>>>(W_head_b, rel_emb, nullptr, DMODEL);
    bf_gemm<2><<<dim3(8, 128), 256, BFG_DSM>>>(W_v_b,    nullptr, nullptr, DMODEL);

    // 3) scores + mask -> fr region of d_out (raw logits)
    bf_gemm<3><<<dim3(4, 4, BHS), 256, BFG_DSM>>>(nullptr, nullptr, out_fr, DHEAD);

    // 4+5) fused softmax + P @ V (double-buffered) -> fr final, attn hi/lo
    gemm_sm_pv<<<dim3(1, 4, BHS), 256, PV_DSM>>>(out_fr, SEQ);

    // 6) output projection
    bf_gemm<5><<<dim3(8, 128), 256, BFG_DSM>>>(W_out_b, nullptr, out_x, DMODEL);
}

// round 9
// speedup vs baseline: 1.0746x; 1.0090x over previous
#include <cuda_runtime.h>
#include <cuda_bf16.h>
#include <math.h>
#include <cstdint>

#define BATCH   32
#define HEADS   8
#define SEQ     512
#define DMODEL  1024
#define DHEAD   128
#define DCOL    18
#define BHS     (BATCH*HEADS)   // 256
#define BSD     ((size_t)BATCH*SEQ*DMODEL)   // 16777216
#define SCALE   0.08838834764831845f

// ---------------- scratch (static device globals; no allocation) ----------------
__device__ __align__(256) __nv_bfloat16 g_xqh[BSD], g_xql[BSD];
__device__ __align__(256) __nv_bfloat16 g_xkh[BSD], g_xkl[BSD];
__device__ __align__(256) __nv_bfloat16 g_Whh[DMODEL*DMODEL], g_Whl[DMODEL*DMODEL];
__device__ __align__(256) __nv_bfloat16 g_Wvh[DMODEL*DMODEL], g_Wvl[DMODEL*DMODEL];
__device__ __align__(256) __nv_bfloat16 g_Woh[DMODEL*DMODEL], g_Wol[DMODEL*DMODEL];
__device__ __align__(256) __nv_bfloat16 g_fhh[BSD], g_fhl[BSD];   // f_head hi/lo [b,h,q,dh]
__device__ __align__(256) __nv_bfloat16 g_fth[BSD], g_ftl[BSD];   // f_tail hi/lo [b,h,k,dh]
__device__ __align__(256) float        g_fv [BSD];                 // f_v fp32 [b,h,k,dh]
__device__ __align__(256) __nv_bfloat16 g_ath[BSD], g_atl[BSD];    // attn hi/lo [b,q,h*dh]
__device__ __align__(256) float        g_adjm[(size_t)HEADS*SEQ*SEQ];
__device__ __align__(256) float        g_smax[(size_t)BHS*4*SEQ];  // per (z, ktile, row) max
__device__ __align__(256) float        g_ssum[(size_t)BHS*4*SEQ];  // per (z, ktile, row) sumexp

// ---------------- small helpers ----------------
__device__ __forceinline__ unsigned packbf(float f0, float f1) {   // f0 -> low half
    unsigned d;
    asm("cvt.rn.bf16x2.f32 %0, %1, %2;" : "=r"(d) : "f"(f1), "f"(f0));
    return d;
}
__device__ __forceinline__ float bf_lo(unsigned p) { return __uint_as_float(p << 16); }
__device__ __forceinline__ float bf_up(unsigned p) { return __uint_as_float(p & 0xFFFF0000u); }

__device__ __forceinline__ unsigned smem_u32(const void* p) {
    unsigned a;
    asm("{ .reg .u64 t; cvta.to.shared.u64 t, %1; cvt.u32.u64 %0, t; }" : "=r"(a) : "l"(p));
    return a;
}
__device__ __forceinline__ void cpa16s(unsigned dst, const void* src) {
    asm volatile("cp.async.ca.shared.global [%0], [%1], 16;" :: "r"(dst), "l"(src));
}
__device__ __forceinline__ void cpa_commit() { asm volatile("cp.async.commit_group;"); }
template<int N>
__device__ __forceinline__ void cpa_wait() { asm volatile("cp.async.wait_group %0;" :: "n"(N)); }

__device__ __forceinline__ void ldm4(unsigned& r0, unsigned& r1, unsigned& r2, unsigned& r3,
                                     unsigned addr) {
    asm volatile("ldmatrix.sync.aligned.m8n8.x4.shared.b16 {%0,%1,%2,%3}, [%4];"
                 : "=r"(r0), "=r"(r1), "=r"(r2), "=r"(r3) : "r"(addr));
}

__device__ __forceinline__ void mmabf(float* c, unsigned a0, unsigned a1, unsigned a2,
                                      unsigned a3, unsigned b0, unsigned b1) {
    asm volatile(
        "mma.sync.aligned.m16n8k16.row.col.f32.bf16.bf16.f32 "
        "{%0,%1,%2,%3}, {%4,%5,%6,%7}, {%8,%9}, {%0,%1,%2,%3};\n"
        : "+f"(c[0]), "+f"(c[1]), "+f"(c[2]), "+f"(c[3])
        : "r"(a0), "r"(a1), "r"(a2), "r"(a3), "r"(b0), "r"(b1));
}

__device__ __forceinline__ void cvt8(const float* f, unsigned* ph, unsigned* pl) {
#pragma unroll
    for (int j = 0; j < 4; j++) {
        unsigned h = packbf(f[2*j], f[2*j+1]);
        ph[j] = h;
        pl[j] = packbf(f[2*j] - bf_lo(h), f[2*j+1] - bf_up(h));
    }
}

// ---------------- fp32 -> bf16 hi/lo: x inputs (y selects), weights (y selects) ----------------
__global__ void cvt_x(const float* __restrict__ xq, const float* __restrict__ xkv)
{
    const int sel = blockIdx.y;
    const float4* s4 = reinterpret_cast<const float4*>(sel ? xkv : xq);
    uint2* hu = reinterpret_cast<uint2*>(sel ? g_xkh : g_xqh);
    uint2* lu = reinterpret_cast<uint2*>(sel ? g_xkl : g_xql);
    const int n4 = (int)(BSD/4);
    for (int i = blockIdx.x * blockDim.x + threadIdx.x; i < n4; i += gridDim.x * blockDim.x) {
        float4 v = s4[i];
        unsigned h0 = packbf(v.x, v.y), h1 = packbf(v.z, v.w);
        unsigned l0 = packbf(v.x - bf_lo(h0), v.y - bf_up(h0));
        unsigned l1 = packbf(v.z - bf_lo(h1), v.w - bf_up(h1));
        hu[i] = make_uint2(h0, h1);
        lu[i] = make_uint2(l0, l1);
    }
}

__global__ void cvt_w(const float* __restrict__ wh, const float* __restrict__ wv,
                      const float* __restrict__ wo)
{
    const int sel = blockIdx.y;
    const float4* s4 = reinterpret_cast<const float4*>(sel == 0 ? wh : sel == 1 ? wv : wo);
    uint2* hu = reinterpret_cast<uint2*>(sel == 0 ? g_Whh : sel == 1 ? g_Wvh : g_Woh);
    uint2* lu = reinterpret_cast<uint2*>(sel == 0 ? g_Whl : sel == 1 ? g_Wvl : g_Wol);
    const int n4 = DMODEL*DMODEL/4;
    for (int i = blockIdx.x * blockDim.x + threadIdx.x; i < n4; i += gridDim.x * blockDim.x) {
        float4 v = s4[i];
        unsigned h0 = packbf(v.x, v.y), h1 = packbf(v.z, v.w);
        unsigned l0 = packbf(v.x - bf_lo(h0), v.y - bf_up(h0));
        unsigned l1 = packbf(v.z - bf_lo(h1), v.w - bf_up(h1));
        hu[i] = make_uint2(h0, h1);
        lu[i] = make_uint2(l0, l1);
    }
}

// ---------------- adjacency: softmax(col_head @ col_tail^T, diag=0) ----------------
__global__ void adj_kernel(const float* __restrict__ col_head,
                           const float* __restrict__ col_tail)
{
    const int q = blockIdx.x;
    const int h = blockIdx.y;
    const int t = threadIdx.x;                 // 128 threads
    __shared__ float ch[DCOL];
    __shared__ float sred[4];

    if (t < DCOL) ch[t] = col_head[((size_t)h*SEQ + q)*DCOL + t];
    __syncthreads();

    float l[4];
#pragma unroll
    for (int i = 0; i < 4; i++) {
        const int k = t + i*128;
        const float* ct = col_tail + ((size_t)h*SEQ + k)*DCOL;
        float s = 0.f;
#pragma unroll
        for (int c = 0; c < DCOL; c++) s += ch[c]*ct[c];
        l[i] = (k == q) ? 0.f : s;
    }

    float mx = fmaxf(fmaxf(l[0],l[1]), fmaxf(l[2],l[3]));
#pragma unroll
    for (int o = 16; o; o >>= 1) mx = fmaxf(mx, __shfl_xor_sync(0xffffffffu, mx, o));
    if ((t & 31) == 0) sred[t >> 5] = mx;
    __syncthreads();
    mx = fmaxf(fmaxf(sred[0],sred[1]), fmaxf(sred[2],sred[3]));
    __syncthreads();

    float e[4]; float sum = 0.f;
#pragma unroll
    for (int i = 0; i < 4; i++) { e[i] = expf(l[i]-mx); sum += e[i]; }
#pragma unroll
    for (int o = 16; o; o >>= 1) sum += __shfl_xor_sync(0xffffffffu, sum, o);
    if ((t & 31) == 0) sred[t >> 5] = sum;
    __syncthreads();
    sum = sred[0]+sred[1]+sred[2]+sred[3];
    const float inv = 1.f/sum;

    float* dst = g_adjm + ((size_t)h*SEQ + q)*SEQ;
#pragma unroll
    for (int i = 0; i < 4; i++) {
        const int k = t + i*128;
        dst[k] = (1.f - e[i]*inv) * (-10000.f);
    }
}

// ---------------- common tile constants ----------------
#define LDK    40                 // padded smem row (bf16 elems), 80 bytes
#define TILEB  (128*LDK*2)        // 10240 B per tile
#define STAGEB (4*TILEB)          // Ah, Al, Bh, Bl
#define BFG_DSM (2*STAGEB)        // 81920 B

// The proven R5 inner loop as a macro-shaped device routine is risky; duplicate instead.

// ---------------- merged projection GEMM: blockIdx.z = mode (0,1,2) ----------------
__global__ void __launch_bounds__(256, 2)
proj_gemm(const float* __restrict__ biasH, const float* __restrict__ biasV,
          const float* __restrict__ aux, int K)
{
    extern __shared__ char sm[];
    const unsigned sbase = smem_u32(sm);

    const int tid  = threadIdx.x;
    const int lane = tid & 31;
    const int warp = tid >> 5;
    const int wm   = warp >> 2, wn = warp & 3;
    const int mode = blockIdx.z;
    const int m0   = blockIdx.y * 128;
    const int n0   = blockIdx.x * 128;

    const __nv_bfloat16* Ah = (mode == 0) ? g_xqh : g_xkh;
    const __nv_bfloat16* Al = (mode == 0) ? g_xql : g_xkl;
    const __nv_bfloat16* Bh = (mode == 2) ? g_Wvh : g_Whh;
    const __nv_bfloat16* Bl = (mode == 2) ? g_Wvl : g_Whl;
    const float* bias = (mode == 2) ? biasV : biasH;

    auto load_stage = [&](int st, int kt) {
        const unsigned sb = sbase + st*STAGEB;
#pragma unroll
        for (int i = 0; i < 8; i++) {
            const int idx  = tid + i*256;
            const int tile = idx >> 9;
            const int r    = (idx >> 2) & 127;
            const int c    = idx & 3;
            const __nv_bfloat16* s = (tile == 0) ? Ah : (tile == 1) ? Al :
                                     (tile == 2) ? Bh : Bl;
            const int rg = ((tile < 2) ? m0 : n0) + r;
            cpa16s(sb + tile*TILEB + r*(LDK*2) + c*16,
                   s + (size_t)rg*K + kt + c*8);
        }
    };

    float acc[4][4][4];
#pragma unroll
    for (int i = 0; i < 4; i++)
#pragma unroll
        for (int j = 0; j < 4; j++)
#pragma unroll
            for (int f = 0; f < 4; f++) acc[i][j][f] = 0.f;

    const int rowA = (lane & 7) + ((lane >> 3) & 1) * 8;
    const int colA = ((lane >> 4) & 1) * 8;
    const int rowB = (lane & 7) + ((lane >> 4) & 1) * 8;
    const int colB = ((lane >> 3) & 1) * 8;

    const int iters = K >> 5;
    load_stage(0, 0);
    cpa_commit();

    for (int it = 0; it < iters; ++it) {
        const int cur = it & 1;
        if (it + 1 < iters) { load_stage(cur ^ 1, (it + 1) << 5); cpa_commit(); cpa_wait<1>(); }
        else                { cpa_wait<0>(); }
        __syncthreads();

        const unsigned sb  = sbase + cur*STAGEB;
        const unsigned aAh = sb + (wm*64 + rowA)*(LDK*2) + colA*2;
        const unsigned aAl = aAh + TILEB;
        const unsigned aBh = sb + 2*TILEB + (wn*32 + rowB)*(LDK*2) + colB*2;
        const unsigned aBl = aBh + TILEB;

#pragma unroll
        for (int ks = 0; ks < 2; ks++) {
            const unsigned ko = ks*32;
            unsigned bh[4][2], bl[4][2];
#pragma unroll
            for (int p = 0; p < 2; p++) {
                unsigned r0, r1, r2, r3;
                ldm4(r0, r1, r2, r3, aBh + p*16*(LDK*2) + ko);
                bh[2*p][0]=r0; bh[2*p][1]=r1; bh[2*p+1][0]=r2; bh[2*p+1][1]=r3;
                ldm4(r0, r1, r2, r3, aBl + p*16*(LDK*2) + ko);
                bl[2*p][0]=r0; bl[2*p][1]=r1; bl[2*p+1][0]=r2; bl[2*p+1][1]=r3;
            }
#pragma unroll
            for (int mt = 0; mt < 4; mt++) {
                unsigned a[4], al_[4];
                ldm4(a[0], a[1], a[2], a[3],     aAh + mt*16*(LDK*2) + ko);
                ldm4(al_[0], al_[1], al_[2], al_[3], aAl + mt*16*(LDK*2) + ko);
#pragma unroll
                for (int nt = 0; nt < 4; nt++) {
                    mmabf(acc[mt][nt], a[0],a[1],a[2],a[3],     bh[nt][0], bh[nt][1]);
                    mmabf(acc[mt][nt], a[0],a[1],a[2],a[3],     bl[nt][0], bl[nt][1]);
                    mmabf(acc[mt][nt], al_[0],al_[1],al_[2],al_[3], bh[nt][0], bh[nt][1]);
                }
            }
        }
        __syncthreads();
    }

    const int lr2 = lane >> 2;
    const int lc2 = (lane & 3) << 1;
#pragma unroll
    for (int mt = 0; mt < 4; mt++)
#pragma unroll
        for (int nt = 0; nt < 4; nt++) {
#pragma unroll
            for (int hh = 0; hh < 2; hh++) {
                const int m = m0 + wm*64 + mt*16 + lr2 + hh*8;
                const int n = n0 + wn*32 + nt*8 + lc2;
                float v0 = acc[mt][nt][hh*2+0] + bias[n];
                float v1 = acc[mt][nt][hh*2+1] + bias[n+1];
                const int b = m >> 9, q = m & 511, h = n >> 7, dh = n & 127;
                const size_t idx = (((size_t)((b<<3)|h))*SEQ + q)*DHEAD + dh;
                if (mode < 2) {
                    v0 *= aux[n]; v1 *= aux[n+1];
                    const unsigned ph = packbf(v0, v1);
                    const unsigned pl = packbf(v0 - bf_lo(ph), v1 - bf_up(ph));
                    __nv_bfloat16* dh_a = (mode == 0) ? g_fhh : g_fth;
                    __nv_bfloat16* dl_a = (mode == 0) ? g_fhl : g_ftl;
                    *reinterpret_cast<unsigned*>(&dh_a[idx]) = ph;
                    *reinterpret_cast<unsigned*>(&dl_a[idx]) = pl;
                } else {
                    float2 o; o.x = v0; o.y = v1;
                    *reinterpret_cast<float2*>(&g_fv[idx]) = o;
                }
            }
        }
}

// ---------------- scores GEMM + fused softmax stats (per 128-col tile) ----------------
__global__ void __launch_bounds__(256, 2)
score_gemm(float* __restrict__ Cext, int K)
{
    extern __shared__ char sm[];
    const unsigned sbase = smem_u32(sm);

    const int tid  = threadIdx.x;
    const int lane = tid & 31;
    const int warp = tid >> 5;
    const int wm   = warp >> 2, wn = warp & 3;
    const int z    = blockIdx.z;
    const int m0   = blockIdx.y * 128;
    const int n0   = blockIdx.x * 128;

    const __nv_bfloat16* Ah = g_fhh + (size_t)z*SEQ*DHEAD;
    const __nv_bfloat16* Al = g_fhl + (size_t)z*SEQ*DHEAD;
    const __nv_bfloat16* Bh = g_fth + (size_t)z*SEQ*DHEAD;
    const __nv_bfloat16* Bl = g_ftl + (size_t)z*SEQ*DHEAD;

    auto load_stage = [&](int st, int kt) {
        const unsigned sb = sbase + st*STAGEB;
#pragma unroll
        for (int i = 0; i < 8; i++) {
            const int idx  = tid + i*256;
            const int tile = idx >> 9;
            const int r    = (idx >> 2) & 127;
            const int c    = idx & 3;
            const __nv_bfloat16* s = (tile == 0) ? Ah : (tile == 1) ? Al :
                                     (tile == 2) ? Bh : Bl;
            const int rg = ((tile < 2) ? m0 : n0) + r;
            cpa16s(sb + tile*TILEB + r*(LDK*2) + c*16,
                   s + (size_t)rg*K + kt + c*8);
        }
    };

    float acc[4][4][4];
#pragma unroll
    for (int i = 0; i < 4; i++)
#pragma unroll
        for (int j = 0; j < 4; j++)
#pragma unroll
            for (int f = 0; f < 4; f++) acc[i][j][f] = 0.f;

    const int rowA = (lane & 7) + ((lane >> 3) & 1) * 8;
    const int colA = ((lane >> 4) & 1) * 8;
    const int rowB = (lane & 7) + ((lane >> 4) & 1) * 8;
    const int colB = ((lane >> 3) & 1) * 8;

    const int iters = K >> 5;
    load_stage(0, 0);
    cpa_commit();

    for (int it = 0; it < iters; ++it) {
        const int cur = it & 1;
        if (it + 1 < iters) { load_stage(cur ^ 1, (it + 1) << 5); cpa_commit(); cpa_wait<1>(); }
        else                { cpa_wait<0>(); }
        __syncthreads();

        const unsigned sb  = sbase + cur*STAGEB;
        const unsigned aAh = sb + (wm*64 + rowA)*(LDK*2) + colA*2;
        const unsigned aAl = aAh + TILEB;
        const unsigned aBh = sb + 2*TILEB + (wn*32 + rowB)*(LDK*2) + colB*2;
        const unsigned aBl = aBh + TILEB;

#pragma unroll
        for (int ks = 0; ks < 2; ks++) {
            const unsigned ko = ks*32;
            unsigned bh[4][2], bl[4][2];
#pragma unroll
            for (int p = 0; p < 2; p++) {
                unsigned r0, r1, r2, r3;
                ldm4(r0, r1, r2, r3, aBh + p*16*(LDK*2) + ko);
                bh[2*p][0]=r0; bh[2*p][1]=r1; bh[2*p+1][0]=r2; bh[2*p+1][1]=r3;
                ldm4(r0, r1, r2, r3, aBl + p*16*(LDK*2) + ko);
                bl[2*p][0]=r0; bl[2*p][1]=r1; bl[2*p+1][0]=r2; bl[2*p+1][1]=r3;
            }
#pragma unroll
            for (int mt = 0; mt < 4; mt++) {
                unsigned a[4], al_[4];
                ldm4(a[0], a[1], a[2], a[3],     aAh + mt*16*(LDK*2) + ko);
                ldm4(al_[0], al_[1], al_[2], al_[3], aAl + mt*16*(LDK*2) + ko);
#pragma unroll
                for (int nt = 0; nt < 4; nt++) {
                    mmabf(acc[mt][nt], a[0],a[1],a[2],a[3],     bh[nt][0], bh[nt][1]);
                    mmabf(acc[mt][nt], a[0],a[1],a[2],a[3],     bl[nt][0], bl[nt][1]);
                    mmabf(acc[mt][nt], al_[0],al_[1],al_[2],al_[3], bh[nt][0], bh[nt][1]);
                }
            }
        }
        __syncthreads();
    }

    // epilogue: final logits -> gmem + stage smem (reuse, loop is done), then row stats
    float* s_v = reinterpret_cast<float*>(sm);   // [128][129] fp32, 66048 B <= 81920
    const int h = z & 7;
    const int lr2 = lane >> 2;
    const int lc2 = (lane & 3) << 1;
#pragma unroll
    for (int mt = 0; mt < 4; mt++)
#pragma unroll
        for (int nt = 0; nt < 4; nt++) {
#pragma unroll
            for (int hh = 0; hh < 2; hh++) {
                const int ml = wm*64 + mt*16 + lr2 + hh*8;   // local row
                const int nl = wn*32 + nt*8 + lc2;           // local col
                const int mg = m0 + ml, ng = n0 + nl;
                const size_t off = (size_t)mg*SEQ + ng;
                float2 am = *reinterpret_cast<const float2*>(&g_adjm[(size_t)h*SEQ*SEQ + off]);
                float v0 = acc[mt][nt][hh*2+0] * SCALE + am.x;
                float v1 = acc[mt][nt][hh*2+1] * SCALE + am.y;
                float2 o; o.x = v0; o.y = v1;
                *reinterpret_cast<float2*>(&Cext[(size_t)z*SEQ*SEQ + off]) = o;
                s_v[ml*129 + nl] = v0;
                s_v[ml*129 + nl + 1] = v1;
            }
        }
    __syncthreads();

    if (tid < 128) {
        const float* row = s_v + tid*129;
        float mx = -3.4e38f;
#pragma unroll 8
        for (int c = 0; c < 128; c++) mx = fmaxf(mx, row[c]);
        float s = 0.f;
#pragma unroll 8
        for (int c = 0; c < 128; c++) s += __expf(row[c] - mx);
        const size_t sidx = ((size_t)z*4 + blockIdx.x)*SEQ + (m0 + tid);
        g_smax[sidx] = mx;
        g_ssum[sidx] = s;
    }
}

// ---------------- output projection GEMM (mode 5) ----------------
__global__ void __launch_bounds__(256, 2)
out_gemm(const float* __restrict__ bias, float* __restrict__ Cext, int K)
{
    extern __shared__ char sm[];
    const unsigned sbase = smem_u32(sm);

    const int tid  = threadIdx.x;
    const int lane = tid & 31;
    const int warp = tid >> 5;
    const int wm   = warp >> 2, wn = warp & 3;
    const int m0   = blockIdx.y * 128;
    const int n0   = blockIdx.x * 128;

    const __nv_bfloat16* Ah = g_ath;
    const __nv_bfloat16* Al = g_atl;
    const __nv_bfloat16* Bh = g_Woh;
    const __nv_bfloat16* Bl = g_Wol;

    auto load_stage = [&](int st, int kt) {
        const unsigned sb = sbase + st*STAGEB;
#pragma unroll
        for (int i = 0; i < 8; i++) {
            const int idx  = tid + i*256;
            const int tile = idx >> 9;
            const int r    = (idx >> 2) & 127;
            const int c    = idx & 3;
            const __nv_bfloat16* s = (tile == 0) ? Ah : (tile == 1) ? Al :
                                     (tile == 2) ? Bh : Bl;
            const int rg = ((tile < 2) ? m0 : n0) + r;
            cpa16s(sb + tile*TILEB + r*(LDK*2) + c*16,
                   s + (size_t)rg*K + kt + c*8);
        }
    };

    float acc[4][4][4];
#pragma unroll
    for (int i = 0; i < 4; i++)
#pragma unroll
        for (int j = 0; j < 4; j++)
#pragma unroll
            for (int f = 0; f < 4; f++) acc[i][j][f] = 0.f;

    const int rowA = (lane & 7) + ((lane >> 3) & 1) * 8;
    const int colA = ((lane >> 4) & 1) * 8;
    const int rowB = (lane & 7) + ((lane >> 4) & 1) * 8;
    const int colB = ((lane >> 3) & 1) * 8;

    const int iters = K >> 5;
    load_stage(0, 0);
    cpa_commit();

    for (int it = 0; it < iters; ++it) {
        const int cur = it & 1;
        if (it + 1 < iters) { load_stage(cur ^ 1, (it + 1) << 5); cpa_commit(); cpa_wait<1>(); }
        else                { cpa_wait<0>(); }
        __syncthreads();

        const unsigned sb  = sbase + cur*STAGEB;
        const unsigned aAh = sb + (wm*64 + rowA)*(LDK*2) + colA*2;
        const unsigned aAl = aAh + TILEB;
        const unsigned aBh = sb + 2*TILEB + (wn*32 + rowB)*(LDK*2) + colB*2;
        const unsigned aBl = aBh + TILEB;

#pragma unroll
        for (int ks = 0; ks < 2; ks++) {
            const unsigned ko = ks*32;
            unsigned bh[4][2], bl[4][2];
#pragma unroll
            for (int p = 0; p < 2; p++) {
                unsigned r0, r1, r2, r3;
                ldm4(r0, r1, r2, r3, aBh + p*16*(LDK*2) + ko);
                bh[2*p][0]=r0; bh[2*p][1]=r1; bh[2*p+1][0]=r2; bh[2*p+1][1]=r3;
                ldm4(r0, r1, r2, r3, aBl + p*16*(LDK*2) + ko);
                bl[2*p][0]=r0; bl[2*p][1]=r1; bl[2*p+1][0]=r2; bl[2*p+1][1]=r3;
            }
#pragma unroll
            for (int mt = 0; mt < 4; mt++) {
                unsigned a[4], al_[4];
                ldm4(a[0], a[1], a[2], a[3],     aAh + mt*16*(LDK*2) + ko);
                ldm4(al_[0], al_[1], al_[2], al_[3], aAl + mt*16*(LDK*2) + ko);
#pragma unroll
                for (int nt = 0; nt < 4; nt++) {
                    mmabf(acc[mt][nt], a[0],a[1],a[2],a[3],     bh[nt][0], bh[nt][1]);
                    mmabf(acc[mt][nt], a[0],a[1],a[2],a[3],     bl[nt][0], bl[nt][1]);
                    mmabf(acc[mt][nt], al_[0],al_[1],al_[2],al_[3], bh[nt][0], bh[nt][1]);
                }
            }
        }
        __syncthreads();
    }

    const int lr2 = lane >> 2;
    const int lc2 = (lane & 3) << 1;
#pragma unroll
    for (int mt = 0; mt < 4; mt++)
#pragma unroll
        for (int nt = 0; nt < 4; nt++) {
#pragma unroll
            for (int hh = 0; hh < 2; hh++) {
                const int m = m0 + wm*64 + mt*16 + lr2 + hh*8;
                const int n = n0 + wn*32 + nt*8 + lc2;
                float2 o;
                o.x = acc[mt][nt][hh*2+0] + bias[n];
                o.y = acc[mt][nt][hh*2+1] + bias[n+1];
                *reinterpret_cast<float2*>(&Cext[(size_t)m*DMODEL + n]) = o;
            }
        }
}

// ---------------- fused softmax-apply + P @ V (stats from score_gemm) ----------------
#define PV_DSM 49152

__global__ void __launch_bounds__(256, 2)
gemm_sm_pv(float* __restrict__ fr, int K)
{
    extern __shared__ char sm[];
    unsigned* pW = reinterpret_cast<unsigned*>(sm);

    const int tid  = threadIdx.x;
    const int lane = tid & 31;
    const int warp = tid >> 5;
    const int wm   = warp >> 2, wn = warp & 3;
    const int lr   = lane >> 2, lc = lane & 3;
    const int z    = blockIdx.z;

    float* A        = fr + (size_t)z*SEQ*SEQ;
    const float* Bp = g_fv + (size_t)z*SEQ*DHEAD;

    const int m0 = blockIdx.y * 128;

    const int arow  = tid >> 1;          // 0..127
    const int akoff = (tid & 1) << 3;    // 0 or 8
    const int bn    = tid & 127;
    const int bhalf = tid >> 7;

    // ---- reconstruct global row stats from per-tile stats ----
    float mr, ir;
    {
        const int grow = m0 + arow;
        float mt4[4], st4[4];
#pragma unroll
        for (int t = 0; t < 4; t++) {
            const size_t sidx = ((size_t)z*4 + t)*SEQ + grow;
            mt4[t] = g_smax[sidx];
            st4[t] = g_ssum[sidx];
        }
        mr = fmaxf(fmaxf(mt4[0], mt4[1]), fmaxf(mt4[2], mt4[3]));
        float den = st4[0]*__expf(mt4[0]-mr) + st4[1]*__expf(mt4[1]-mr)
                  + st4[2]*__expf(mt4[2]-mr) + st4[3]*__expf(mt4[3]-mr);
        ir = 1.f/den;
    }

    float fa[8], fb[8];

    auto ldg_stage = [&](int kt) {
        const float* ap = A + (size_t)(m0 + arow)*K + kt + akoff;
        float4 v0 = *reinterpret_cast<const float4*>(ap);
        float4 v1 = *reinterpret_cast<const float4*>(ap + 4);
        fa[0]=v0.x; fa[1]=v0.y; fa[2]=v0.z; fa[3]=v0.w;
        fa[4]=v1.x; fa[5]=v1.y; fa[6]=v1.z; fa[7]=v1.w;
#pragma unroll
        for (int j = 0; j < 8; j++)
            fb[j] = Bp[(size_t)(kt + 8*bhalf + j)*DHEAD + bn];
    };

    ldg_stage(0);

    float acc[4][4][4];
#pragma unroll
    for (int i = 0; i < 4; i++)
#pragma unroll
        for (int j = 0; j < 4; j++)
#pragma unroll
            for (int f = 0; f < 4; f++) acc[i][j][f] = 0.f;

    const int iters = K / 16;   // 32

    for (int it = 0; it < iters; ++it) {
        const unsigned b0 = (unsigned)(it & 1) * 6144;

        // ---- pack(it): logits -> probabilities, in-place writeback, bf16 hi/lo smem ----
        {
#pragma unroll
            for (int j = 0; j < 8; j++) fa[j] = __expf(fa[j] - mr) * ir;

            float* ap = A + (size_t)(m0 + arow)*K + it*16 + akoff;
            *reinterpret_cast<float4*>(ap)     = make_float4(fa[0], fa[1], fa[2], fa[3]);
            *reinterpret_cast<float4*>(ap + 4) = make_float4(fa[4], fa[5], fa[6], fa[7]);

            unsigned ph[4], pl[4];
            cvt8(fa, ph, pl);
            *reinterpret_cast<uint4*>(&pW[b0 +        arow*12 + (akoff >> 1)]) =
                make_uint4(ph[0], ph[1], ph[2], ph[3]);
            *reinterpret_cast<uint4*>(&pW[b0 + 1536 + arow*12 + (akoff >> 1)]) =
                make_uint4(pl[0], pl[1], pl[2], pl[3]);
            cvt8(fb, ph, pl);
            *reinterpret_cast<uint4*>(&pW[b0 + 3072 + bn*12 + 4*bhalf]) =
                make_uint4(ph[0], ph[1], ph[2], ph[3]);
            *reinterpret_cast<uint4*>(&pW[b0 + 4608 + bn*12 + 4*bhalf]) =
                make_uint4(pl[0], pl[1], pl[2], pl[3]);
        }
        __syncthreads();

        if (it + 1 < iters) ldg_stage((it + 1) * 16);

        // ---- compute(it) ----
        uint2 a0[4], a1[4], b_h[4], b_l[4];
#pragma unroll
        for (int mt = 0; mt < 4; mt++) {
            const int r = wm*64 + mt*16 + lr;
            a0[mt] = *reinterpret_cast<const uint2*>(&pW[b0 + r*12 + 2*lc]);
            a1[mt] = *reinterpret_cast<const uint2*>(&pW[b0 + (r+8)*12 + 2*lc]);
        }
#pragma unroll
        for (int nt = 0; nt < 4; nt++) {
            const int c = wn*32 + nt*8 + lr;
            b_h[nt] = *reinterpret_cast<const uint2*>(&pW[b0 + 3072 + c*12 + 2*lc]);
            b_l[nt] = *reinterpret_cast<const uint2*>(&pW[b0 + 4608 + c*12 + 2*lc]);
        }
#pragma unroll
        for (int mt = 0; mt < 4; mt++)
#pragma unroll
            for (int nt = 0; nt < 4; nt++) {
                mmabf(acc[mt][nt], a0[mt].x, a1[mt].x, a0[mt].y, a1[mt].y, b_h[nt].x, b_h[nt].y);
                mmabf(acc[mt][nt], a0[mt].x, a1[mt].x, a0[mt].y, a1[mt].y, b_l[nt].x, b_l[nt].y);
            }
#pragma unroll
        for (int mt = 0; mt < 4; mt++) {
            const int r = wm*64 + mt*16 + lr;
            a0[mt] = *reinterpret_cast<const uint2*>(&pW[b0 + 1536 + r*12 + 2*lc]);
            a1[mt] = *reinterpret_cast<const uint2*>(&pW[b0 + 1536 + (r+8)*12 + 2*lc]);
        }
#pragma unroll
        for (int mt = 0; mt < 4; mt++)
#pragma unroll
            for (int nt = 0; nt < 4; nt++)
                mmabf(acc[mt][nt], a0[mt].x, a1[mt].x, a0[mt].y, a1[mt].y, b_h[nt].x, b_h[nt].y);
    }

    // epilogue: emit attn hi/lo bf16 pairs
    const int b = z >> 3, h = z & 7;
    const int lc2 = (lane & 3) << 1;
#pragma unroll
    for (int mt = 0; mt < 4; mt++)
#pragma unroll
        for (int nt = 0; nt < 4; nt++) {
            const int mb = m0 + wm*64 + mt*16 + lr;
            const int nb = wn*32 + nt*8 + lc2;
#pragma unroll
            for (int hh = 0; hh < 2; hh++) {
                const float v0 = acc[mt][nt][hh*2+0];
                const float v1 = acc[mt][nt][hh*2+1];
                const size_t idx = ((size_t)(b*SEQ + mb + hh*8))*DMODEL + h*DHEAD + nb;
                const unsigned ph = packbf(v0, v1);
                const unsigned pl = packbf(v0 - bf_lo(ph), v1 - bf_up(ph));
                *reinterpret_cast<unsigned*>(&g_ath[idx]) = ph;
                *reinterpret_cast<unsigned*>(&g_atl[idx]) = pl;
            }
        }
}

// ---------------- launch ----------------
extern "C" void kernel_launch(void* const* d_in, const int* in_sizes, int n_in,
                              void* d_out, int out_size)
{
    const float* x_q      = (const float*)d_in[0];
    const float* x_kv     = (const float*)d_in[1];
    const float* W_head_w = (const float*)d_in[2];
    const float* W_head_b = (const float*)d_in[3];
    const float* W_v_w    = (const float*)d_in[4];
    const float* W_v_b    = (const float*)d_in[5];
    const float* W_out_w  = (const float*)d_in[6];
    const float* W_out_b  = (const float*)d_in[7];
    const float* rel_emb  = (const float*)d_in[8];
    const float* col_head = (const float*)d_in[9];
    const float* col_tail = (const float*)d_in[10];

    float* out_x  = (float*)d_out;                          // [32,512,1024]
    float* out_fr = out_x + (size_t)BATCH*SEQ*DMODEL;       // [256,512,512]

    static bool attr_done = false;
    if (!attr_done) {
        cudaFuncSetAttribute(proj_gemm,  cudaFuncAttributeMaxDynamicSharedMemorySize, BFG_DSM);
        cudaFuncSetAttribute(score_gemm, cudaFuncAttributeMaxDynamicSharedMemorySize, BFG_DSM);
        cudaFuncSetAttribute(out_gemm,   cudaFuncAttributeMaxDynamicSharedMemorySize, BFG_DSM);
        cudaFuncSetAttribute(gemm_sm_pv, cudaFuncAttributeMaxDynamicSharedMemorySize, PV_DSM);
        attr_done = true;
    }

    // 1) pre-convert inputs to bf16 hi/lo (merged launches)
    cvt_x<<<dim3(2048, 2), 256>>>(x_q, x_kv);
    cvt_w<<<dim3(512, 3),  256>>>(W_head_w, W_v_w, W_out_w);

    // 2) learned column topology mask
    adj_kernel<<<dim3(SEQ, HEADS), 128>>>(col_head, col_tail);

    // 3) all three projections in one launch (z = mode)
    proj_gemm<<<dim3(8, 128, 3), 256, BFG_DSM>>>(W_head_b, W_v_b, rel_emb, DMODEL);

    // 4) scores + mask -> fr (raw logits) + per-tile softmax stats
    score_gemm<<<dim3(4, 4, BHS), 256, BFG_DSM>>>(out_fr, DHEAD);

    // 5) softmax-apply + P @ V (stats-driven; no extra fr pass) -> fr final, attn hi/lo
    gemm_sm_pv<<<dim3(1, 4, BHS), 256, PV_DSM>>>(out_fr, SEQ);

    // 6) output projection
    out_gemm<<<dim3(8, 128), 256, BFG_DSM>>>(W_out_b, out_x, DMODEL);
}

// round 10
// speedup vs baseline: 1.5479x; 1.4405x over previous
#include <cuda_runtime.h>
#include <cuda_bf16.h>
#include <cuda_fp16.h>
#include <math.h>
#include <cstdint>

#define BATCH   32
#define HEADS   8
#define SEQ     512
#define DMODEL  1024
#define DHEAD   128
#define DCOL    18
#define BHS     (BATCH*HEADS)   // 256
#define BSD     ((size_t)BATCH*SEQ*DMODEL)   // 16777216
#define SCALE   0.08838834764831845f

// ---------------- scratch (static device globals; no allocation) ----------------
__device__ __align__(256) __half        g_xqf[BSD], g_xkf[BSD];          // fp16 inputs
__device__ __align__(256) __half        g_Whf[DMODEL*DMODEL], g_Wvf[DMODEL*DMODEL];
__device__ __align__(256) __nv_bfloat16 g_Woh[DMODEL*DMODEL], g_Wol[DMODEL*DMODEL];
__device__ __align__(256) __half        g_fhf[BSD], g_ftf[BSD];          // f_head/f_tail fp16
__device__ __align__(256) float         g_fv [BSD];                      // f_v fp32
__device__ __align__(256) __nv_bfloat16 g_ath[BSD], g_atl[BSD];          // attn hi/lo
__device__ __align__(256) float         g_adjm[(size_t)HEADS*SEQ*SEQ];
__device__ __align__(256) float         g_smax[(size_t)BHS*4*SEQ];
__device__ __align__(256) float         g_ssum[(size_t)BHS*4*SEQ];

// ---------------- small helpers ----------------
__device__ __forceinline__ unsigned packbf(float f0, float f1) {   // f0 -> low half
    unsigned d;
    asm("cvt.rn.bf16x2.f32 %0, %1, %2;" : "=r"(d) : "f"(f1), "f"(f0));
    return d;
}
__device__ __forceinline__ unsigned packh(float f0, float f1) {    // f0 -> low half
    unsigned d;
    asm("cvt.rn.f16x2.f32 %0, %1, %2;" : "=r"(d) : "f"(f1), "f"(f0));
    return d;
}
__device__ __forceinline__ float bf_lo(unsigned p) { return __uint_as_float(p << 16); }
__device__ __forceinline__ float bf_up(unsigned p) { return __uint_as_float(p & 0xFFFF0000u); }

__device__ __forceinline__ unsigned smem_u32(const void* p) {
    unsigned a;
    asm("{ .reg .u64 t; cvta.to.shared.u64 t, %1; cvt.u32.u64 %0, t; }" : "=r"(a) : "l"(p));
    return a;
}
__device__ __forceinline__ void cpa16s(unsigned dst, const void* src) {
    asm volatile("cp.async.ca.shared.global [%0], [%1], 16;" :: "r"(dst), "l"(src));
}
__device__ __forceinline__ void cpa_commit() { asm volatile("cp.async.commit_group;"); }
template<int N>
__device__ __forceinline__ void cpa_wait() { asm volatile("cp.async.wait_group %0;" :: "n"(N)); }

__device__ __forceinline__ void ldm4(unsigned& r0, unsigned& r1, unsigned& r2, unsigned& r3,
                                     unsigned addr) {
    asm volatile("ldmatrix.sync.aligned.m8n8.x4.shared.b16 {%0,%1,%2,%3}, [%4];"
                 : "=r"(r0), "=r"(r1), "=r"(r2), "=r"(r3) : "r"(addr));
}

__device__ __forceinline__ void mmabf(float* c, unsigned a0, unsigned a1, unsigned a2,
                                      unsigned a3, unsigned b0, unsigned b1) {
    asm volatile(
        "mma.sync.aligned.m16n8k16.row.col.f32.bf16.bf16.f32 "
        "{%0,%1,%2,%3}, {%4,%5,%6,%7}, {%8,%9}, {%0,%1,%2,%3};\n"
        : "+f"(c[0]), "+f"(c[1]), "+f"(c[2]), "+f"(c[3])
        : "r"(a0), "r"(a1), "r"(a2), "r"(a3), "r"(b0), "r"(b1));
}

__device__ __forceinline__ void mmah(float* c, unsigned a0, unsigned a1, unsigned a2,
                                     unsigned a3, unsigned b0, unsigned b1) {
    asm volatile(
        "mma.sync.aligned.m16n8k16.row.col.f32.f16.f16.f32 "
        "{%0,%1,%2,%3}, {%4,%5,%6,%7}, {%8,%9}, {%0,%1,%2,%3};\n"
        : "+f"(c[0]), "+f"(c[1]), "+f"(c[2]), "+f"(c[3])
        : "r"(a0), "r"(a1), "r"(a2), "r"(a3), "r"(b0), "r"(b1));
}

__device__ __forceinline__ void cvt8(const float* f, unsigned* ph, unsigned* pl) {
#pragma unroll
    for (int j = 0; j < 4; j++) {
        unsigned h = packbf(f[2*j], f[2*j+1]);
        ph[j] = h;
        pl[j] = packbf(f[2*j] - bf_lo(h), f[2*j+1] - bf_up(h));
    }
}

// ---------------- conversions ----------------
__global__ void cvt_x(const float* __restrict__ xq, const float* __restrict__ xkv)
{
    const int sel = blockIdx.y;
    const float4* s4 = reinterpret_cast<const float4*>(sel ? xkv : xq);
    uint2* out = reinterpret_cast<uint2*>(sel ? g_xkf : g_xqf);
    const int n4 = (int)(BSD/4);
    for (int i = blockIdx.x * blockDim.x + threadIdx.x; i < n4; i += gridDim.x * blockDim.x) {
        float4 v = s4[i];
        out[i] = make_uint2(packh(v.x, v.y), packh(v.z, v.w));
    }
}

__global__ void cvt_w(const float* __restrict__ wh, const float* __restrict__ wv,
                      const float* __restrict__ wo)
{
    const int sel = blockIdx.y;
    const int n4 = DMODEL*DMODEL/4;
    if (sel < 2) {
        const float4* s4 = reinterpret_cast<const float4*>(sel == 0 ? wh : wv);
        uint2* out = reinterpret_cast<uint2*>(sel == 0 ? g_Whf : g_Wvf);
        for (int i = blockIdx.x * blockDim.x + threadIdx.x; i < n4; i += gridDim.x * blockDim.x) {
            float4 v = s4[i];
            out[i] = make_uint2(packh(v.x, v.y), packh(v.z, v.w));
        }
    } else {
        const float4* s4 = reinterpret_cast<const float4*>(wo);
        uint2* hu = reinterpret_cast<uint2*>(g_Woh);
        uint2* lu = reinterpret_cast<uint2*>(g_Wol);
        for (int i = blockIdx.x * blockDim.x + threadIdx.x; i < n4; i += gridDim.x * blockDim.x) {
            float4 v = s4[i];
            unsigned h0 = packbf(v.x, v.y), h1 = packbf(v.z, v.w);
            unsigned l0 = packbf(v.x - bf_lo(h0), v.y - bf_up(h0));
            unsigned l1 = packbf(v.z - bf_lo(h1), v.w - bf_up(h1));
            hu[i] = make_uint2(h0, h1);
            lu[i] = make_uint2(l0, l1);
        }
    }
}

// ---------------- adjacency: softmax(col_head @ col_tail^T, diag=0) ----------------
__global__ void adj_kernel(const float* __restrict__ col_head,
                           const float* __restrict__ col_tail)
{
    const int q = blockIdx.x;
    const int h = blockIdx.y;
    const int t = threadIdx.x;                 // 128 threads
    __shared__ float ch[DCOL];
    __shared__ float sred[4];

    if (t < DCOL) ch[t] = col_head[((size_t)h*SEQ + q)*DCOL + t];
    __syncthreads();

    float l[4];
#pragma unroll
    for (int i = 0; i < 4; i++) {
        const int k = t + i*128;
        const float* ct = col_tail + ((size_t)h*SEQ + k)*DCOL;
        float s = 0.f;
#pragma unroll
        for (int c = 0; c < DCOL; c++) s += ch[c]*ct[c];
        l[i] = (k == q) ? 0.f : s;
    }

    float mx = fmaxf(fmaxf(l[0],l[1]), fmaxf(l[2],l[3]));
#pragma unroll
    for (int o = 16; o; o >>= 1) mx = fmaxf(mx, __shfl_xor_sync(0xffffffffu, mx, o));
    if ((t & 31) == 0) sred[t >> 5] = mx;
    __syncthreads();
    mx = fmaxf(fmaxf(sred[0],sred[1]), fmaxf(sred[2],sred[3]));
    __syncthreads();

    float e[4]; float sum = 0.f;
#pragma unroll
    for (int i = 0; i < 4; i++) { e[i] = expf(l[i]-mx); sum += e[i]; }
#pragma unroll
    for (int o = 16; o; o >>= 1) sum += __shfl_xor_sync(0xffffffffu, sum, o);
    if ((t & 31) == 0) sred[t >> 5] = sum;
    __syncthreads();
    sum = sred[0]+sred[1]+sred[2]+sred[3];
    const float inv = 1.f/sum;

    float* dst = g_adjm + ((size_t)h*SEQ + q)*SEQ;
#pragma unroll
    for (int i = 0; i < 4; i++) {
        const int k = t + i*128;
        dst[k] = (1.f - e[i]*inv) * (-10000.f);
    }
}

// ---------------- tile constants ----------------
#define LDK     40                  // padded smem row (16b elems), 80 B
#define TILEB   (128*LDK*2)         // 10240 B
#define HSTAGE  (2*TILEB)           // fp16 single: A + B
#define HG_DSM  66560               // max(2*HSTAGE, 128*129*4 stats) padded
#define BSTAGE  (4*TILEB)           // bf16 hi/lo: Ah,Al,Bh,Bl
#define BFG_DSM (2*BSTAGE)          // 81920

// ---------------- fp16 single-pass projections: blockIdx.z = mode (0,1,2) ----------------
__global__ void __launch_bounds__(256, 2)
proj_h(const float* __restrict__ biasH, const float* __restrict__ biasV,
       const float* __restrict__ aux, int K)
{
    extern __shared__ char sm[];
    const unsigned sbase = smem_u32(sm);

    const int tid  = threadIdx.x;
    const int lane = tid & 31;
    const int warp = tid >> 5;
    const int wm   = warp >> 2, wn = warp & 3;
    const int mode = blockIdx.z;
    const int m0   = blockIdx.y * 128;
    const int n0   = blockIdx.x * 128;

    const __half* A = (mode == 0) ? g_xqf : g_xkf;
    const __half* B = (mode == 2) ? g_Wvf : g_Whf;
    const float* bias = (mode == 2) ? biasV : biasH;

    auto load_stage = [&](int st, int kt) {
        const unsigned sb = sbase + st*HSTAGE;
#pragma unroll
        for (int i = 0; i < 4; i++) {
            const int idx  = tid + i*256;          // 0..1023 chunks
            const int tile = idx >> 9;             // 0:A 1:B
            const int r    = (idx >> 2) & 127;
            const int c    = idx & 3;
            const __half* s = tile ? B : A;
            const int rg = (tile ? n0 : m0) + r;
            cpa16s(sb + tile*TILEB + r*(LDK*2) + c*16,
                   s + (size_t)rg*K + kt + c*8);
        }
    };

    float acc[4][4][4];
#pragma unroll
    for (int i = 0; i < 4; i++)
#pragma unroll
        for (int j = 0; j < 4; j++)
#pragma unroll
            for (int f = 0; f < 4; f++) acc[i][j][f] = 0.f;

    const int rowA = (lane & 7) + ((lane >> 3) & 1) * 8;
    const int colA = ((lane >> 4) & 1) * 8;
    const int rowB = (lane & 7) + ((lane >> 4) & 1) * 8;
    const int colB = ((lane >> 3) & 1) * 8;

    const int iters = K >> 5;
    load_stage(0, 0);
    cpa_commit();

    for (int it = 0; it < iters; ++it) {
        const int cur = it & 1;
        if (it + 1 < iters) { load_stage(cur ^ 1, (it + 1) << 5); cpa_commit(); cpa_wait<1>(); }
        else                { cpa_wait<0>(); }
        __syncthreads();

        const unsigned sb = sbase + cur*HSTAGE;
        const unsigned aA = sb + (wm*64 + rowA)*(LDK*2) + colA*2;
        const unsigned aB = sb + TILEB + (wn*32 + rowB)*(LDK*2) + colB*2;

#pragma unroll
        for (int ks = 0; ks < 2; ks++) {
            const unsigned ko = ks*32;
            unsigned bh[4][2];
#pragma unroll
            for (int p = 0; p < 2; p++) {
                unsigned r0, r1, r2, r3;
                ldm4(r0, r1, r2, r3, aB + p*16*(LDK*2) + ko);
                bh[2*p][0]=r0; bh[2*p][1]=r1; bh[2*p+1][0]=r2; bh[2*p+1][1]=r3;
            }
#pragma unroll
            for (int mt = 0; mt < 4; mt++) {
                unsigned a[4];
                ldm4(a[0], a[1], a[2], a[3], aA + mt*16*(LDK*2) + ko);
#pragma unroll
                for (int nt = 0; nt < 4; nt++)
                    mmah(acc[mt][nt], a[0],a[1],a[2],a[3], bh[nt][0], bh[nt][1]);
            }
        }
        __syncthreads();
    }

    const int lr2 = lane >> 2;
    const int lc2 = (lane & 3) << 1;
#pragma unroll
    for (int mt = 0; mt < 4; mt++)
#pragma unroll
        for (int nt = 0; nt < 4; nt++) {
#pragma unroll
            for (int hh = 0; hh < 2; hh++) {
                const int m = m0 + wm*64 + mt*16 + lr2 + hh*8;
                const int n = n0 + wn*32 + nt*8 + lc2;
                float v0 = acc[mt][nt][hh*2+0] + bias[n];
                float v1 = acc[mt][nt][hh*2+1] + bias[n+1];
                const int b = m >> 9, q = m & 511, h = n >> 7, dh = n & 127;
                const size_t idx = (((size_t)((b<<3)|h))*SEQ + q)*DHEAD + dh;
                if (mode < 2) {
                    v0 *= aux[n]; v1 *= aux[n+1];
                    __half* dst = (mode == 0) ? g_fhf : g_ftf;
                    *reinterpret_cast<unsigned*>(&dst[idx]) = packh(v0, v1);
                } else {
                    float2 o; o.x = v0; o.y = v1;
                    *reinterpret_cast<float2*>(&g_fv[idx]) = o;
                }
            }
        }
}

// ---------------- fp16 single-pass scores + fused softmax stats ----------------
__global__ void __launch_bounds__(256, 2)
score_h(float* __restrict__ Cext, int K)
{
    extern __shared__ char sm[];
    const unsigned sbase = smem_u32(sm);

    const int tid  = threadIdx.x;
    const int lane = tid & 31;
    const int warp = tid >> 5;
    const int wm   = warp >> 2, wn = warp & 3;
    const int z    = blockIdx.z;
    const int m0   = blockIdx.y * 128;
    const int n0   = blockIdx.x * 128;

    const __half* A = g_fhf + (size_t)z*SEQ*DHEAD;
    const __half* B = g_ftf + (size_t)z*SEQ*DHEAD;

    auto load_stage = [&](int st, int kt) {
        const unsigned sb = sbase + st*HSTAGE;
#pragma unroll
        for (int i = 0; i < 4; i++) {
            const int idx  = tid + i*256;
            const int tile = idx >> 9;
            const int r    = (idx >> 2) & 127;
            const int c    = idx & 3;
            const __half* s = tile ? B : A;
            const int rg = (tile ? n0 : m0) + r;
            cpa16s(sb + tile*TILEB + r*(LDK*2) + c*16,
                   s + (size_t)rg*K + kt + c*8);
        }
    };

    float acc[4][4][4];
#pragma unroll
    for (int i = 0; i < 4; i++)
#pragma unroll
        for (int j = 0; j < 4; j++)
#pragma unroll
            for (int f = 0; f < 4; f++) acc[i][j][f] = 0.f;

    const int rowA = (lane & 7) + ((lane >> 3) & 1) * 8;
    const int colA = ((lane >> 4) & 1) * 8;
    const int rowB = (lane & 7) + ((lane >> 4) & 1) * 8;
    const int colB = ((lane >> 3) & 1) * 8;

    const int iters = K >> 5;   // 4
    load_stage(0, 0);
    cpa_commit();

    for (int it = 0; it < iters; ++it) {
        const int cur = it & 1;
        if (it + 1 < iters) { load_stage(cur ^ 1, (it + 1) << 5); cpa_commit(); cpa_wait<1>(); }
        else                { cpa_wait<0>(); }
        __syncthreads();

        const unsigned sb = sbase + cur*HSTAGE;
        const unsigned aA = sb + (wm*64 + rowA)*(LDK*2) + colA*2;
        const unsigned aB = sb + TILEB + (wn*32 + rowB)*(LDK*2) + colB*2;

#pragma unroll
        for (int ks = 0; ks < 2; ks++) {
            const unsigned ko = ks*32;
            unsigned bh[4][2];
#pragma unroll
            for (int p = 0; p < 2; p++) {
                unsigned r0, r1, r2, r3;
                ldm4(r0, r1, r2, r3, aB + p*16*(LDK*2) + ko);
                bh[2*p][0]=r0; bh[2*p][1]=r1; bh[2*p+1][0]=r2; bh[2*p+1][1]=r3;
            }
#pragma unroll
            for (int mt = 0; mt < 4; mt++) {
                unsigned a[4];
                ldm4(a[0], a[1], a[2], a[3], aA + mt*16*(LDK*2) + ko);
#pragma unroll
                for (int nt = 0; nt < 4; nt++)
                    mmah(acc[mt][nt], a[0],a[1],a[2],a[3], bh[nt][0], bh[nt][1]);
            }
        }
        __syncthreads();
    }

    // epilogue: final logits -> gmem + smem staging, then per-row tile stats
    float* s_v = reinterpret_cast<float*>(sm);   // [128][129] fp32 = 66048 B
    const int h = z & 7;
    const int lr2 = lane >> 2;
    const int lc2 = (lane & 3) << 1;
#pragma unroll
    for (int mt = 0; mt < 4; mt++)
#pragma unroll
        for (int nt = 0; nt < 4; nt++) {
#pragma unroll
            for (int hh = 0; hh < 2; hh++) {
                const int ml = wm*64 + mt*16 + lr2 + hh*8;
                const int nl = wn*32 + nt*8 + lc2;
                const int mg = m0 + ml, ng = n0 + nl;
                const size_t off = (size_t)mg*SEQ + ng;
                float2 am = *reinterpret_cast<const float2*>(&g_adjm[(size_t)h*SEQ*SEQ + off]);
                float v0 = acc[mt][nt][hh*2+0] * SCALE + am.x;
                float v1 = acc[mt][nt][hh*2+1] * SCALE + am.y;
                float2 o; o.x = v0; o.y = v1;
                *reinterpret_cast<float2*>(&Cext[(size_t)z*SEQ*SEQ + off]) = o;
                s_v[ml*129 + nl] = v0;
                s_v[ml*129 + nl + 1] = v1;
            }
        }
    __syncthreads();

    if (tid < 128) {
        const float* row = s_v + tid*129;
        float mx = -3.4e38f;
#pragma unroll 8
        for (int c = 0; c < 128; c++) mx = fmaxf(mx, row[c]);
        float s = 0.f;
#pragma unroll 8
        for (int c = 0; c < 128; c++) s += __expf(row[c] - mx);
        const size_t sidx = ((size_t)z*4 + blockIdx.x)*SEQ + (m0 + tid);
        g_smax[sidx] = mx;
        g_ssum[sidx] = s;
    }
}

// ---------------- output projection GEMM (bf16 3-term, unchanged) ----------------
__global__ void __launch_bounds__(256, 2)
out_gemm(const float* __restrict__ bias, float* __restrict__ Cext, int K)
{
    extern __shared__ char sm[];
    const unsigned sbase = smem_u32(sm);

    const int tid  = threadIdx.x;
    const int lane = tid & 31;
    const int warp = tid >> 5;
    const int wm   = warp >> 2, wn = warp & 3;
    const int m0   = blockIdx.y * 128;
    const int n0   = blockIdx.x * 128;

    const __nv_bfloat16* Ah = g_ath;
    const __nv_bfloat16* Al = g_atl;
    const __nv_bfloat16* Bh = g_Woh;
    const __nv_bfloat16* Bl = g_Wol;

    auto load_stage = [&](int st, int kt) {
        const unsigned sb = sbase + st*BSTAGE;
#pragma unroll
        for (int i = 0; i < 8; i++) {
            const int idx  = tid + i*256;
            const int tile = idx >> 9;
            const int r    = (idx >> 2) & 127;
            const int c    = idx & 3;
            const __nv_bfloat16* s = (tile == 0) ? Ah : (tile == 1) ? Al :
                                     (tile == 2) ? Bh : Bl;
            const int rg = ((tile < 2) ? m0 : n0) + r;
            cpa16s(sb + tile*TILEB + r*(LDK*2) + c*16,
                   s + (size_t)rg*K + kt + c*8);
        }
    };

    float acc[4][4][4];
#pragma unroll
    for (int i = 0; i < 4; i++)
#pragma unroll
        for (int j = 0; j < 4; j++)
#pragma unroll
            for (int f = 0; f < 4; f++) acc[i][j][f] = 0.f;

    const int rowA = (lane & 7) + ((lane >> 3) & 1) * 8;
    const int colA = ((lane >> 4) & 1) * 8;
    const int rowB = (lane & 7) + ((lane >> 4) & 1) * 8;
    const int colB = ((lane >> 3) & 1) * 8;

    const int iters = K >> 5;
    load_stage(0, 0);
    cpa_commit();

    for (int it = 0; it < iters; ++it) {
        const int cur = it & 1;
        if (it + 1 < iters) { load_stage(cur ^ 1, (it + 1) << 5); cpa_commit(); cpa_wait<1>(); }
        else                { cpa_wait<0>(); }
        __syncthreads();

        const unsigned sb  = sbase + cur*BSTAGE;
        const unsigned aAh = sb + (wm*64 + rowA)*(LDK*2) + colA*2;
        const unsigned aAl = aAh + TILEB;
        const unsigned aBh = sb + 2*TILEB + (wn*32 + rowB)*(LDK*2) + colB*2;
        const unsigned aBl = aBh + TILEB;

#pragma unroll
        for (int ks = 0; ks < 2; ks++) {
            const unsigned ko = ks*32;
            unsigned bh[4][2], bl[4][2];
#pragma unroll
            for (int p = 0; p < 2; p++) {
                unsigned r0, r1, r2, r3;
                ldm4(r0, r1, r2, r3, aBh + p*16*(LDK*2) + ko);
                bh[2*p][0]=r0; bh[2*p][1]=r1; bh[2*p+1][0]=r2; bh[2*p+1][1]=r3;
                ldm4(r0, r1, r2, r3, aBl + p*16*(LDK*2) + ko);
                bl[2*p][0]=r0; bl[2*p][1]=r1; bl[2*p+1][0]=r2; bl[2*p+1][1]=r3;
            }
#pragma unroll
            for (int mt = 0; mt < 4; mt++) {
                unsigned a[4], al_[4];
                ldm4(a[0], a[1], a[2], a[3],     aAh + mt*16*(LDK*2) + ko);
                ldm4(al_[0], al_[1], al_[2], al_[3], aAl + mt*16*(LDK*2) + ko);
#pragma unroll
                for (int nt = 0; nt < 4; nt++) {
                    mmabf(acc[mt][nt], a[0],a[1],a[2],a[3],     bh[nt][0], bh[nt][1]);
                    mmabf(acc[mt][nt], a[0],a[1],a[2],a[3],     bl[nt][0], bl[nt][1]);
                    mmabf(acc[mt][nt], al_[0],al_[1],al_[2],al_[3], bh[nt][0], bh[nt][1]);
                }
            }
        }
        __syncthreads();
    }

    const int lr2 = lane >> 2;
    const int lc2 = (lane & 3) << 1;
#pragma unroll
    for (int mt = 0; mt < 4; mt++)
#pragma unroll
        for (int nt = 0; nt < 4; nt++) {
#pragma unroll
            for (int hh = 0; hh < 2; hh++) {
                const int m = m0 + wm*64 + mt*16 + lr2 + hh*8;
                const int n = n0 + wn*32 + nt*8 + lc2;
                float2 o;
                o.x = acc[mt][nt][hh*2+0] + bias[n];
                o.y = acc[mt][nt][hh*2+1] + bias[n+1];
                *reinterpret_cast<float2*>(&Cext[(size_t)m*DMODEL + n]) = o;
            }
        }
}

// ---------------- fused softmax-apply + P @ V (stats from score_h; unchanged) ----------------
#define PV_DSM 49152

__global__ void __launch_bounds__(256, 2)
gemm_sm_pv(float* __restrict__ fr, int K)
{
    extern __shared__ char sm[];
    unsigned* pW = reinterpret_cast<unsigned*>(sm);

    const int tid  = threadIdx.x;
    const int lane = tid & 31;
    const int warp = tid >> 5;
    const int wm   = warp >> 2, wn = warp & 3;
    const int lr   = lane >> 2, lc = lane & 3;
    const int z    = blockIdx.z;

    float* A        = fr + (size_t)z*SEQ*SEQ;
    const float* Bp = g_fv + (size_t)z*SEQ*DHEAD;

    const int m0 = blockIdx.y * 128;

    const int arow  = tid >> 1;
    const int akoff = (tid & 1) << 3;
    const int bn    = tid & 127;
    const int bhalf = tid >> 7;

    float mr, ir;
    {
        const int grow = m0 + arow;
        float mt4[4], st4[4];
#pragma unroll
        for (int t = 0; t < 4; t++) {
            const size_t sidx = ((size_t)z*4 + t)*SEQ + grow;
            mt4[t] = g_smax[sidx];
            st4[t] = g_ssum[sidx];
        }
        mr = fmaxf(fmaxf(mt4[0], mt4[1]), fmaxf(mt4[2], mt4[3]));
        float den = st4[0]*__expf(mt4[0]-mr) + st4[1]*__expf(mt4[1]-mr)
                  + st4[2]*__expf(mt4[2]-mr) + st4[3]*__expf(mt4[3]-mr);
        ir = 1.f/den;
    }

    float fa[8], fb[8];

    auto ldg_stage = [&](int kt) {
        const float* ap = A + (size_t)(m0 + arow)*K + kt + akoff;
        float4 v0 = *reinterpret_cast<const float4*>(ap);
        float4 v1 = *reinterpret_cast<const float4*>(ap + 4);
        fa[0]=v0.x; fa[1]=v0.y; fa[2]=v0.z; fa[3]=v0.w;
        fa[4]=v1.x; fa[5]=v1.y; fa[6]=v1.z; fa[7]=v1.w;
#pragma unroll
        for (int j = 0; j < 8; j++)
            fb[j] = Bp[(size_t)(kt + 8*bhalf + j)*DHEAD + bn];
    };

    ldg_stage(0);

    float acc[4][4][4];
#pragma unroll
    for (int i = 0; i < 4; i++)
#pragma unroll
        for (int j = 0; j < 4; j++)
#pragma unroll
            for (int f = 0; f < 4; f++) acc[i][j][f] = 0.f;

    const int iters = K / 16;

    for (int it = 0; it < iters; ++it) {
        const unsigned b0 = (unsigned)(it & 1) * 6144;
        {
#pragma unroll
            for (int j = 0; j < 8; j++) fa[j] = __expf(fa[j] - mr) * ir;

            float* ap = A + (size_t)(m0 + arow)*K + it*16 + akoff;
            *reinterpret_cast<float4*>(ap)     = make_float4(fa[0], fa[1], fa[2], fa[3]);
            *reinterpret_cast<float4*>(ap + 4) = make_float4(fa[4], fa[5], fa[6], fa[7]);

            unsigned ph[4], pl[4];
            cvt8(fa, ph, pl);
            *reinterpret_cast<uint4*>(&pW[b0 +        arow*12 + (akoff >> 1)]) =
                make_uint4(ph[0], ph[1], ph[2], ph[3]);
            *reinterpret_cast<uint4*>(&pW[b0 + 1536 + arow*12 + (akoff >> 1)]) =
                make_uint4(pl[0], pl[1], pl[2], pl[3]);
            cvt8(fb, ph, pl);
            *reinterpret_cast<uint4*>(&pW[b0 + 3072 + bn*12 + 4*bhalf]) =
                make_uint4(ph[0], ph[1], ph[2], ph[3]);
            *reinterpret_cast<uint4*>(&pW[b0 + 4608 + bn*12 + 4*bhalf]) =
                make_uint4(pl[0], pl[1], pl[2], pl[3]);
        }
        __syncthreads();

        if (it + 1 < iters) ldg_stage((it + 1) * 16);

        uint2 a0[4], a1[4], b_h[4], b_l[4];
#pragma unroll
        for (int mt = 0; mt < 4; mt++) {
            const int r = wm*64 + mt*16 + lr;
            a0[mt] = *reinterpret_cast<const uint2*>(&pW[b0 + r*12 + 2*lc]);
            a1[mt] = *reinterpret_cast<const uint2*>(&pW[b0 + (r+8)*12 + 2*lc]);
        }
#pragma unroll
        for (int nt = 0; nt < 4; nt++) {
            const int c = wn*32 + nt*8 + lr;
            b_h[nt] = *reinterpret_cast<const uint2*>(&pW[b0 + 3072 + c*12 + 2*lc]);
            b_l[nt] = *reinterpret_cast<const uint2*>(&pW[b0 + 4608 + c*12 + 2*lc]);
        }
#pragma unroll
        for (int mt = 0; mt < 4; mt++)
#pragma unroll
            for (int nt = 0; nt < 4; nt++) {
                mmabf(acc[mt][nt], a0[mt].x, a1[mt].x, a0[mt].y, a1[mt].y, b_h[nt].x, b_h[nt].y);
                mmabf(acc[mt][nt], a0[mt].x, a1[mt].x, a0[mt].y, a1[mt].y, b_l[nt].x, b_l[nt].y);
            }
#pragma unroll
        for (int mt = 0; mt < 4; mt++) {
            const int r = wm*64 + mt*16 + lr;
            a0[mt] = *reinterpret_cast<const uint2*>(&pW[b0 + 1536 + r*12 + 2*lc]);
            a1[mt] = *reinterpret_cast<const uint2*>(&pW[b0 + 1536 + (r+8)*12 + 2*lc]);
        }
#pragma unroll
        for (int mt = 0; mt < 4; mt++)
#pragma unroll
            for (int nt = 0; nt < 4; nt++)
                mmabf(acc[mt][nt], a0[mt].x, a1[mt].x, a0[mt].y, a1[mt].y, b_h[nt].x, b_h[nt].y);
    }

    const int b = z >> 3, h = z & 7;
    const int lc2 = (lane & 3) << 1;
#pragma unroll
    for (int mt = 0; mt < 4; mt++)
#pragma unroll
        for (int nt = 0; nt < 4; nt++) {
            const int mb = m0 + wm*64 + mt*16 + lr;
            const int nb = wn*32 + nt*8 + lc2;
#pragma unroll
            for (int hh = 0; hh < 2; hh++) {
                const float v0 = acc[mt][nt][hh*2+0];
                const float v1 = acc[mt][nt][hh*2+1];
                const size_t idx = ((size_t)(b*SEQ + mb + hh*8))*DMODEL + h*DHEAD + nb;
                const unsigned ph = packbf(v0, v1);
                const unsigned pl = packbf(v0 - bf_lo(ph), v1 - bf_up(ph));
                *reinterpret_cast<unsigned*>(&g_ath[idx]) = ph;
                *reinterpret_cast<unsigned*>(&g_atl[idx]) = pl;
            }
        }
}

// ---------------- launch ----------------
extern "C" void kernel_launch(void* const* d_in, const int* in_sizes, int n_in,
                              void* d_out, int out_size)
{
    const float* x_q      = (const float*)d_in[0];
    const float* x_kv     = (const float*)d_in[1];
    const float* W_head_w = (const float*)d_in[2];
    const float* W_head_b = (const float*)d_in[3];
    const float* W_v_w    = (const float*)d_in[4];
    const float* W_v_b    = (const float*)d_in[5];
    const float* W_out_w  = (const float*)d_in[6];
    const float* W_out_b  = (const float*)d_in[7];
    const float* rel_emb  = (const float*)d_in[8];
    const float* col_head = (const float*)d_in[9];
    const float* col_tail = (const float*)d_in[10];

    float* out_x  = (float*)d_out;                          // [32,512,1024]
    float* out_fr = out_x + (size_t)BATCH*SEQ*DMODEL;       // [256,512,512]

    static bool attr_done = false;
    if (!attr_done) {
        cudaFuncSetAttribute(proj_h,     cudaFuncAttributeMaxDynamicSharedMemorySize, HG_DSM);
        cudaFuncSetAttribute(score_h,    cudaFuncAttributeMaxDynamicSharedMemorySize, HG_DSM);
        cudaFuncSetAttribute(out_gemm,   cudaFuncAttributeMaxDynamicSharedMemorySize, BFG_DSM);
        cudaFuncSetAttribute(gemm_sm_pv, cudaFuncAttributeMaxDynamicSharedMemorySize, PV_DSM);
        attr_done = true;
    }

    // 1) conversions
    cvt_x<<<dim3(2048, 2), 256>>>(x_q, x_kv);
    cvt_w<<<dim3(512, 3),  256>>>(W_head_w, W_v_w, W_out_w);

    // 2) learned column topology mask
    adj_kernel<<<dim3(SEQ, HEADS), 128>>>(col_head, col_tail);

    // 3) projections (fp16 single-pass, merged)
    proj_h<<<dim3(8, 128, 3), 256, HG_DSM>>>(W_head_b, W_v_b, rel_emb, DMODEL);

    // 4) scores + mask + per-tile softmax stats (fp16 single-pass)
    score_h<<<dim3(4, 4, BHS), 256, HG_DSM>>>(out_fr, DHEAD);

    // 5) softmax-apply + P @ V (bf16 3-term) -> fr final, attn hi/lo
    gemm_sm_pv<<<dim3(1, 4, BHS), 256, PV_DSM>>>(out_fr, SEQ);

    // 6) output projection (bf16 3-term)
    out_gemm<<<dim3(8, 128), 256, BFG_DSM>>>(W_out_b, out_x, DMODEL);
}

// round 11
// speedup vs baseline: 1.5605x; 1.0081x over previous
#include <cuda_runtime.h>
#include <cuda_bf16.h>
#include <cuda_fp16.h>
#include <math.h>
#include <cstdint>

#define BATCH   32
#define HEADS   8
#define SEQ     512
#define DMODEL  1024
#define DHEAD   128
#define DCOL    18
#define BHS     (BATCH*HEADS)   // 256
#define BSD     ((size_t)BATCH*SEQ*DMODEL)   // 16777216
#define SCALE   0.08838834764831845f

// ---------------- scratch (static device globals; no allocation) ----------------
__device__ __align__(256) __half        g_xqf[BSD], g_xkf[BSD];          // fp16 inputs
__device__ __align__(256) __half        g_Whf[DMODEL*DMODEL], g_Wvf[DMODEL*DMODEL];
__device__ __align__(256) __nv_bfloat16 g_Woh[DMODEL*DMODEL], g_Wol[DMODEL*DMODEL];
__device__ __align__(256) __half        g_fhf[BSD], g_ftf[BSD];          // f_head/f_tail fp16
__device__ __align__(256) float         g_fv [BSD];                      // f_v fp32
__device__ __align__(256) __nv_bfloat16 g_ath[BSD], g_atl[BSD];          // attn hi/lo
__device__ __align__(256) float         g_adjm[(size_t)HEADS*SEQ*SEQ];

// ---------------- small helpers ----------------
__device__ __forceinline__ unsigned packbf(float f0, float f1) {   // f0 -> low half
    unsigned d;
    asm("cvt.rn.bf16x2.f32 %0, %1, %2;" : "=r"(d) : "f"(f1), "f"(f0));
    return d;
}
__device__ __forceinline__ unsigned packh(float f0, float f1) {    // f0 -> low half
    unsigned d;
    asm("cvt.rn.f16x2.f32 %0, %1, %2;" : "=r"(d) : "f"(f1), "f"(f0));
    return d;
}
__device__ __forceinline__ float bf_lo(unsigned p) { return __uint_as_float(p << 16); }
__device__ __forceinline__ float bf_up(unsigned p) { return __uint_as_float(p & 0xFFFF0000u); }

__device__ __forceinline__ unsigned smem_u32(const void* p) {
    unsigned a;
    asm("{ .reg .u64 t; cvta.to.shared.u64 t, %1; cvt.u32.u64 %0, t; }" : "=r"(a) : "l"(p));
    return a;
}
__device__ __forceinline__ void cpa16s(unsigned dst, const void* src) {
    asm volatile("cp.async.ca.shared.global [%0], [%1], 16;" :: "r"(dst), "l"(src));
}
__device__ __forceinline__ void cpa_commit() { asm volatile("cp.async.commit_group;"); }
template<int N>
__device__ __forceinline__ void cpa_wait() { asm volatile("cp.async.wait_group %0;" :: "n"(N)); }

__device__ __forceinline__ void ldm4(unsigned& r0, unsigned& r1, unsigned& r2, unsigned& r3,
                                     unsigned addr) {
    asm volatile("ldmatrix.sync.aligned.m8n8.x4.shared.b16 {%0,%1,%2,%3}, [%4];"
                 : "=r"(r0), "=r"(r1), "=r"(r2), "=r"(r3) : "r"(addr));
}

__device__ __forceinline__ void mmabf(float* c, unsigned a0, unsigned a1, unsigned a2,
                                      unsigned a3, unsigned b0, unsigned b1) {
    asm volatile(
        "mma.sync.aligned.m16n8k16.row.col.f32.bf16.bf16.f32 "
        "{%0,%1,%2,%3}, {%4,%5,%6,%7}, {%8,%9}, {%0,%1,%2,%3};\n"
        : "+f"(c[0]), "+f"(c[1]), "+f"(c[2]), "+f"(c[3])
        : "r"(a0), "r"(a1), "r"(a2), "r"(a3), "r"(b0), "r"(b1));
}

__device__ __forceinline__ void mmah(float* c, unsigned a0, unsigned a1, unsigned a2,
                                     unsigned a3, unsigned b0, unsigned b1) {
    asm volatile(
        "mma.sync.aligned.m16n8k16.row.col.f32.f16.f16.f32 "
        "{%0,%1,%2,%3}, {%4,%5,%6,%7}, {%8,%9}, {%0,%1,%2,%3};\n"
        : "+f"(c[0]), "+f"(c[1]), "+f"(c[2]), "+f"(c[3])
        : "r"(a0), "r"(a1), "r"(a2), "r"(a3), "r"(b0), "r"(b1));
}

__device__ __forceinline__ void cvt8(const float* f, unsigned* ph, unsigned* pl) {
#pragma unroll
    for (int j = 0; j < 4; j++) {
        unsigned h = packbf(f[2*j], f[2*j+1]);
        ph[j] = h;
        pl[j] = packbf(f[2*j] - bf_lo(h), f[2*j+1] - bf_up(h));
    }
}

// ---------------- conversions ----------------
__global__ void cvt_x(const float* __restrict__ xq, const float* __restrict__ xkv)
{
    const int sel = blockIdx.y;
    const float4* s4 = reinterpret_cast<const float4*>(sel ? xkv : xq);
    uint2* out = reinterpret_cast<uint2*>(sel ? g_xkf : g_xqf);
    const int n4 = (int)(BSD/4);
    for (int i = blockIdx.x * blockDim.x + threadIdx.x; i < n4; i += gridDim.x * blockDim.x) {
        float4 v = s4[i];
        out[i] = make_uint2(packh(v.x, v.y), packh(v.z, v.w));
    }
}

__global__ void cvt_w(const float* __restrict__ wh, const float* __restrict__ wv,
                      const float* __restrict__ wo)
{
    const int sel = blockIdx.y;
    const int n4 = DMODEL*DMODEL/4;
    if (sel < 2) {
        const float4* s4 = reinterpret_cast<const float4*>(sel == 0 ? wh : wv);
        uint2* out = reinterpret_cast<uint2*>(sel == 0 ? g_Whf : g_Wvf);
        for (int i = blockIdx.x * blockDim.x + threadIdx.x; i < n4; i += gridDim.x * blockDim.x) {
            float4 v = s4[i];
            out[i] = make_uint2(packh(v.x, v.y), packh(v.z, v.w));
        }
    } else {
        const float4* s4 = reinterpret_cast<const float4*>(wo);
        uint2* hu = reinterpret_cast<uint2*>(g_Woh);
        uint2* lu = reinterpret_cast<uint2*>(g_Wol);
        for (int i = blockIdx.x * blockDim.x + threadIdx.x; i < n4; i += gridDim.x * blockDim.x) {
            float4 v = s4[i];
            unsigned h0 = packbf(v.x, v.y), h1 = packbf(v.z, v.w);
            unsigned l0 = packbf(v.x - bf_lo(h0), v.y - bf_up(h0));
            unsigned l1 = packbf(v.z - bf_lo(h1), v.w - bf_up(h1));
            hu[i] = make_uint2(h0, h1);
            lu[i] = make_uint2(l0, l1);
        }
    }
}

// ---------------- adjacency: softmax(col_head @ col_tail^T, diag=0) ----------------
__global__ void adj_kernel(const float* __restrict__ col_head,
                           const float* __restrict__ col_tail)
{
    const int q = blockIdx.x;
    const int h = blockIdx.y;
    const int t = threadIdx.x;                 // 128 threads
    __shared__ float ch[DCOL];
    __shared__ float sred[4];

    if (t < DCOL) ch[t] = col_head[((size_t)h*SEQ + q)*DCOL + t];
    __syncthreads();

    float l[4];
#pragma unroll
    for (int i = 0; i < 4; i++) {
        const int k = t + i*128;
        const float* ct = col_tail + ((size_t)h*SEQ + k)*DCOL;
        float s = 0.f;
#pragma unroll
        for (int c = 0; c < DCOL; c++) s += ch[c]*ct[c];
        l[i] = (k == q) ? 0.f : s;
    }

    float mx = fmaxf(fmaxf(l[0],l[1]), fmaxf(l[2],l[3]));
#pragma unroll
    for (int o = 16; o; o >>= 1) mx = fmaxf(mx, __shfl_xor_sync(0xffffffffu, mx, o));
    if ((t & 31) == 0) sred[t >> 5] = mx;
    __syncthreads();
    mx = fmaxf(fmaxf(sred[0],sred[1]), fmaxf(sred[2],sred[3]));
    __syncthreads();

    float e[4]; float sum = 0.f;
#pragma unroll
    for (int i = 0; i < 4; i++) { e[i] = expf(l[i]-mx); sum += e[i]; }
#pragma unroll
    for (int o = 16; o; o >>= 1) sum += __shfl_xor_sync(0xffffffffu, sum, o);
    if ((t & 31) == 0) sred[t >> 5] = sum;
    __syncthreads();
    sum = sred[0]+sred[1]+sred[2]+sred[3];
    const float inv = 1.f/sum;

    float* dst = g_adjm + ((size_t)h*SEQ + q)*SEQ;
#pragma unroll
    for (int i = 0; i < 4; i++) {
        const int k = t + i*128;
        dst[k] = (1.f - e[i]*inv) * (-10000.f);
    }
}

// ---------------- tile constants ----------------
#define LDK     40                  // padded smem row (16b elems), 80 B
#define TILEB   (128*LDK*2)         // 10240 B
#define HSTAGE  (2*TILEB)           // fp16 single: A + B
#define HG_DSM  (2*HSTAGE)          // 40960
#define BSTAGE  (4*TILEB)           // bf16 hi/lo: Ah,Al,Bh,Bl
#define BFG_DSM (2*BSTAGE)          // 81920

// ---------------- fp16 single-pass projections: blockIdx.z = mode (0,1,2) ----------------
__global__ void __launch_bounds__(256, 2)
proj_h(const float* __restrict__ biasH, const float* __restrict__ biasV,
       const float* __restrict__ aux, int K)
{
    extern __shared__ char sm[];
    const unsigned sbase = smem_u32(sm);

    const int tid  = threadIdx.x;
    const int lane = tid & 31;
    const int warp = tid >> 5;
    const int wm   = warp >> 2, wn = warp & 3;
    const int mode = blockIdx.z;
    const int m0   = blockIdx.y * 128;
    const int n0   = blockIdx.x * 128;

    const __half* A = (mode == 0) ? g_xqf : g_xkf;
    const __half* B = (mode == 2) ? g_Wvf : g_Whf;
    const float* bias = (mode == 2) ? biasV : biasH;

    auto load_stage = [&](int st, int kt) {
        const unsigned sb = sbase + st*HSTAGE;
#pragma unroll
        for (int i = 0; i < 4; i++) {
            const int idx  = tid + i*256;
            const int tile = idx >> 9;
            const int r    = (idx >> 2) & 127;
            const int c    = idx & 3;
            const __half* s = tile ? B : A;
            const int rg = (tile ? n0 : m0) + r;
            cpa16s(sb + tile*TILEB + r*(LDK*2) + c*16,
                   s + (size_t)rg*K + kt + c*8);
        }
    };

    float acc[4][4][4];
#pragma unroll
    for (int i = 0; i < 4; i++)
#pragma unroll
        for (int j = 0; j < 4; j++)
#pragma unroll
            for (int f = 0; f < 4; f++) acc[i][j][f] = 0.f;

    const int rowA = (lane & 7) + ((lane >> 3) & 1) * 8;
    const int colA = ((lane >> 4) & 1) * 8;
    const int rowB = (lane & 7) + ((lane >> 4) & 1) * 8;
    const int colB = ((lane >> 3) & 1) * 8;

    const int iters = K >> 5;
    load_stage(0, 0);
    cpa_commit();

    for (int it = 0; it < iters; ++it) {
        const int cur = it & 1;
        if (it + 1 < iters) { load_stage(cur ^ 1, (it + 1) << 5); cpa_commit(); cpa_wait<1>(); }
        else                { cpa_wait<0>(); }
        __syncthreads();

        const unsigned sb = sbase + cur*HSTAGE;
        const unsigned aA = sb + (wm*64 + rowA)*(LDK*2) + colA*2;
        const unsigned aB = sb + TILEB + (wn*32 + rowB)*(LDK*2) + colB*2;

#pragma unroll
        for (int ks = 0; ks < 2; ks++) {
            const unsigned ko = ks*32;
            unsigned bh[4][2];
#pragma unroll
            for (int p = 0; p < 2; p++) {
                unsigned r0, r1, r2, r3;
                ldm4(r0, r1, r2, r3, aB + p*16*(LDK*2) + ko);
                bh[2*p][0]=r0; bh[2*p][1]=r1; bh[2*p+1][0]=r2; bh[2*p+1][1]=r3;
            }
#pragma unroll
            for (int mt = 0; mt < 4; mt++) {
                unsigned a[4];
                ldm4(a[0], a[1], a[2], a[3], aA + mt*16*(LDK*2) + ko);
#pragma unroll
                for (int nt = 0; nt < 4; nt++)
                    mmah(acc[mt][nt], a[0],a[1],a[2],a[3], bh[nt][0], bh[nt][1]);
            }
        }
        __syncthreads();
    }

    const int lr2 = lane >> 2;
    const int lc2 = (lane & 3) << 1;
#pragma unroll
    for (int mt = 0; mt < 4; mt++)
#pragma unroll
        for (int nt = 0; nt < 4; nt++) {
#pragma unroll
            for (int hh = 0; hh < 2; hh++) {
                const int m = m0 + wm*64 + mt*16 + lr2 + hh*8;
                const int n = n0 + wn*32 + nt*8 + lc2;
                float v0 = acc[mt][nt][hh*2+0] + bias[n];
                float v1 = acc[mt][nt][hh*2+1] + bias[n+1];
                const int b = m >> 9, q = m & 511, h = n >> 7, dh = n & 127;
                const size_t idx = (((size_t)((b<<3)|h))*SEQ + q)*DHEAD + dh;
                if (mode < 2) {
                    v0 *= aux[n]; v1 *= aux[n+1];
                    __half* dst = (mode == 0) ? g_fhf : g_ftf;
                    *reinterpret_cast<unsigned*>(&dst[idx]) = packh(v0, v1);
                } else {
                    float2 o; o.x = v0; o.y = v1;
                    *reinterpret_cast<float2*>(&g_fv[idx]) = o;
                }
            }
        }
}

// ---------------- fused scores + softmax + P @ V ----------------
// Per CTA (z, m-strip of 128 rows):
//   pass 1 (x4 n-tiles): S = fhead @ ftail^T (fp16 mma), *SCALE + adjm -> fr (logits),
//           per-row running (max, sumexp) in smem via quad shuffles + online combine.
//   pass 2: read logits back (L2-hot), P = exp(l-m)/den, write P to fr in place,
//           pack bf16 hi/lo, P @ V (3-term bf16) -> attn hi/lo.
// smem: [0,49152) pass1 tiles / pass2 packed buffers; stats above.
#define FU_RUNM  49152
#define FU_RUNS  (FU_RUNM + 512)
#define FU_MPART (FU_RUNM + 1024)
#define FU_SPART (FU_MPART + 2048)
#define FU_DSM   (FU_MPART + 4096)   // 54272

__global__ void __launch_bounds__(256, 2)
attn_fused(float* __restrict__ fr)
{
    extern __shared__ char sm[];
    const unsigned sbase = smem_u32(sm);
    unsigned* pW  = reinterpret_cast<unsigned*>(sm);
    float* run_m  = reinterpret_cast<float*>(sm + FU_RUNM);
    float* run_s  = reinterpret_cast<float*>(sm + FU_RUNS);
    float* m_part = reinterpret_cast<float*>(sm + FU_MPART);
    float* s_part = reinterpret_cast<float*>(sm + FU_SPART);

    const int tid  = threadIdx.x;
    const int lane = tid & 31;
    const int warp = tid >> 5;
    const int wm   = warp >> 2, wn = warp & 3;
    const int lr2  = lane >> 2;
    const int lc2  = (lane & 3) << 1;
    const int lc   = lane & 3;
    const int z    = blockIdx.z;
    const int m0   = blockIdx.y * 128;
    const int h    = z & 7;

    const __half* Af = g_fhf + (size_t)z*SEQ*DHEAD;
    const __half* Bf = g_ftf + (size_t)z*SEQ*DHEAD;
    float* frz = fr + (size_t)z*SEQ*SEQ;

    if (tid < 128) { run_m[tid] = -3.4e38f; run_s[tid] = 0.f; }
    __syncthreads();

    const int rowA = (lane & 7) + ((lane >> 3) & 1) * 8;
    const int colA = ((lane >> 4) & 1) * 8;
    const int rowB = (lane & 7) + ((lane >> 4) & 1) * 8;
    const int colB = ((lane >> 3) & 1) * 8;

    // ================= pass 1 =================
    for (int ntile = 0; ntile < 4; ++ntile) {
        const int n0 = ntile * 128;

        auto load_stage = [&](int st, int kt) {
            const unsigned sb = sbase + st*HSTAGE;
#pragma unroll
            for (int i = 0; i < 4; i++) {
                const int idx  = tid + i*256;
                const int tile = idx >> 9;
                const int r    = (idx >> 2) & 127;
                const int c    = idx & 3;
                const __half* s = tile ? Bf : Af;
                const int rg = (tile ? n0 : m0) + r;
                cpa16s(sb + tile*TILEB + r*(LDK*2) + c*16,
                       s + (size_t)rg*DHEAD + kt + c*8);
            }
        };

        float acc[4][4][4];
#pragma unroll
        for (int i = 0; i < 4; i++)
#pragma unroll
            for (int j = 0; j < 4; j++)
#pragma unroll
                for (int f = 0; f < 4; f++) acc[i][j][f] = 0.f;

        load_stage(0, 0);
        cpa_commit();

        for (int it = 0; it < 4; ++it) {            // K = DHEAD = 128, BK32
            const int cur = it & 1;
            if (it + 1 < 4) { load_stage(cur ^ 1, (it + 1) << 5); cpa_commit(); cpa_wait<1>(); }
            else            { cpa_wait<0>(); }
            __syncthreads();

            const unsigned sb = sbase + cur*HSTAGE;
            const unsigned aA = sb + (wm*64 + rowA)*(LDK*2) + colA*2;
            const unsigned aB = sb + TILEB + (wn*32 + rowB)*(LDK*2) + colB*2;

#pragma unroll
            for (int ks = 0; ks < 2; ks++) {
                const unsigned ko = ks*32;
                unsigned bh[4][2];
#pragma unroll
                for (int p = 0; p < 2; p++) {
                    unsigned r0, r1, r2, r3;
                    ldm4(r0, r1, r2, r3, aB + p*16*(LDK*2) + ko);
                    bh[2*p][0]=r0; bh[2*p][1]=r1; bh[2*p+1][0]=r2; bh[2*p+1][1]=r3;
                }
#pragma unroll
                for (int mt = 0; mt < 4; mt++) {
                    unsigned a[4];
                    ldm4(a[0], a[1], a[2], a[3], aA + mt*16*(LDK*2) + ko);
#pragma unroll
                    for (int nt = 0; nt < 4; nt++)
                        mmah(acc[mt][nt], a[0],a[1],a[2],a[3], bh[nt][0], bh[nt][1]);
                }
            }
            __syncthreads();
        }

        // epilogue: logits -> fr + per-32col row stats via quad shuffles
#pragma unroll
        for (int mt = 0; mt < 4; mt++) {
#pragma unroll
            for (int hh = 0; hh < 2; hh++) {
                const int ml = wm*64 + mt*16 + lr2 + hh*8;
                float vv[8];
                float mx = -3.4e38f;
#pragma unroll
                for (int nt = 0; nt < 4; nt++) {
                    const int nl = wn*32 + nt*8 + lc2;
                    const size_t off = (size_t)(m0 + ml)*SEQ + n0 + nl;
                    float2 am = *reinterpret_cast<const float2*>(&g_adjm[(size_t)h*SEQ*SEQ + off]);
                    float v0 = acc[mt][nt][hh*2+0] * SCALE + am.x;
                    float v1 = acc[mt][nt][hh*2+1] * SCALE + am.y;
                    float2 o; o.x = v0; o.y = v1;
                    *reinterpret_cast<float2*>(&frz[off]) = o;
                    vv[nt*2]   = v0;
                    vv[nt*2+1] = v1;
                    mx = fmaxf(mx, fmaxf(v0, v1));
                }
                mx = fmaxf(mx, __shfl_xor_sync(0xffffffffu, mx, 1));
                mx = fmaxf(mx, __shfl_xor_sync(0xffffffffu, mx, 2));
                float s = 0.f;
#pragma unroll
                for (int j = 0; j < 8; j++) s += __expf(vv[j] - mx);
                s += __shfl_xor_sync(0xffffffffu, s, 1);
                s += __shfl_xor_sync(0xffffffffu, s, 2);
                if (lc == 0) { m_part[ml*4 + wn] = mx; s_part[ml*4 + wn] = s; }
            }
        }
        __syncthreads();

        if (tid < 128) {
            float m4 = -3.4e38f;
#pragma unroll
            for (int w = 0; w < 4; w++) m4 = fmaxf(m4, m_part[tid*4 + w]);
            float s4 = 0.f;
#pragma unroll
            for (int w = 0; w < 4; w++) s4 += s_part[tid*4 + w] * __expf(m_part[tid*4 + w] - m4);
            const float mo = run_m[tid], so = run_s[tid];
            const float mn = fmaxf(mo, m4);
            run_s[tid] = so * __expf(mo - mn) + s4 * __expf(m4 - mn);
            run_m[tid] = mn;
        }
        __syncthreads();
    }

    // ================= pass 2: softmax-apply + P @ V =================
    const float* Bp = g_fv + (size_t)z*SEQ*DHEAD;
    const int arow  = tid >> 1;
    const int akoff = (tid & 1) << 3;
    const int bn    = tid & 127;
    const int bhalf = tid >> 7;

    const float mr = run_m[arow];
    const float ir = 1.f / run_s[arow];

    float fa[8], fb[8];
    auto ldg_stage = [&](int kt) {
        const float* ap = frz + (size_t)(m0 + arow)*SEQ + kt + akoff;
        float4 v0 = *reinterpret_cast<const float4*>(ap);
        float4 v1 = *reinterpret_cast<const float4*>(ap + 4);
        fa[0]=v0.x; fa[1]=v0.y; fa[2]=v0.z; fa[3]=v0.w;
        fa[4]=v1.x; fa[5]=v1.y; fa[6]=v1.z; fa[7]=v1.w;
#pragma unroll
        for (int j = 0; j < 8; j++)
            fb[j] = Bp[(size_t)(kt + 8*bhalf + j)*DHEAD + bn];
    };

    ldg_stage(0);

    float acc[4][4][4];
#pragma unroll
    for (int i = 0; i < 4; i++)
#pragma unroll
        for (int j = 0; j < 4; j++)
#pragma unroll
            for (int f = 0; f < 4; f++) acc[i][j][f] = 0.f;

    for (int it = 0; it < 32; ++it) {               // K = SEQ, BK16
        const unsigned b0 = (unsigned)(it & 1) * 6144;
        {
#pragma unroll
            for (int j = 0; j < 8; j++) fa[j] = __expf(fa[j] - mr) * ir;

            float* ap = frz + (size_t)(m0 + arow)*SEQ + it*16 + akoff;
            *reinterpret_cast<float4*>(ap)     = make_float4(fa[0], fa[1], fa[2], fa[3]);
            *reinterpret_cast<float4*>(ap + 4) = make_float4(fa[4], fa[5], fa[6], fa[7]);

            unsigned ph[4], pl[4];
            cvt8(fa, ph, pl);
            *reinterpret_cast<uint4*>(&pW[b0 +        arow*12 + (akoff >> 1)]) =
                make_uint4(ph[0], ph[1], ph[2], ph[3]);
            *reinterpret_cast<uint4*>(&pW[b0 + 1536 + arow*12 + (akoff >> 1)]) =
                make_uint4(pl[0], pl[1], pl[2], pl[3]);
            cvt8(fb, ph, pl);
            *reinterpret_cast<uint4*>(&pW[b0 + 3072 + bn*12 + 4*bhalf]) =
                make_uint4(ph[0], ph[1], ph[2], ph[3]);
            *reinterpret_cast<uint4*>(&pW[b0 + 4608 + bn*12 + 4*bhalf]) =
                make_uint4(pl[0], pl[1], pl[2], pl[3]);
        }
        __syncthreads();

        if (it + 1 < 32) ldg_stage((it + 1) * 16);

        uint2 a0[4], a1[4], b_h[4], b_l[4];
#pragma unroll
        for (int mt = 0; mt < 4; mt++) {
            const int r = wm*64 + mt*16 + lr2;
            a0[mt] = *reinterpret_cast<const uint2*>(&pW[b0 + r*12 + 2*lc]);
            a1[mt] = *reinterpret_cast<const uint2*>(&pW[b0 + (r+8)*12 + 2*lc]);
        }
#pragma unroll
        for (int nt = 0; nt < 4; nt++) {
            const int c = wn*32 + nt*8 + lr2;
            b_h[nt] = *reinterpret_cast<const uint2*>(&pW[b0 + 3072 + c*12 + 2*lc]);
            b_l[nt] = *reinterpret_cast<const uint2*>(&pW[b0 + 4608 + c*12 + 2*lc]);
        }
#pragma unroll
        for (int mt = 0; mt < 4; mt++)
#pragma unroll
            for (int nt = 0; nt < 4; nt++) {
                mmabf(acc[mt][nt], a0[mt].x, a1[mt].x, a0[mt].y, a1[mt].y, b_h[nt].x, b_h[nt].y);
                mmabf(acc[mt][nt], a0[mt].x, a1[mt].x, a0[mt].y, a1[mt].y, b_l[nt].x, b_l[nt].y);
            }
#pragma unroll
        for (int mt = 0; mt < 4; mt++) {
            const int r = wm*64 + mt*16 + lr2;
            a0[mt] = *reinterpret_cast<const uint2*>(&pW[b0 + 1536 + r*12 + 2*lc]);
            a1[mt] = *reinterpret_cast<const uint2*>(&pW[b0 + 1536 + (r+8)*12 + 2*lc]);
        }
#pragma unroll
        for (int mt = 0; mt < 4; mt++)
#pragma unroll
            for (int nt = 0; nt < 4; nt++)
                mmabf(acc[mt][nt], a0[mt].x, a1[mt].x, a0[mt].y, a1[mt].y, b_h[nt].x, b_h[nt].y);
    }

    // epilogue: emit attn hi/lo bf16 pairs
    const int b = z >> 3;
#pragma unroll
    for (int mt = 0; mt < 4; mt++)
#pragma unroll
        for (int nt = 0; nt < 4; nt++) {
            const int mb = m0 + wm*64 + mt*16 + lr2;
            const int nb = wn*32 + nt*8 + lc2;
#pragma unroll
            for (int hh = 0; hh < 2; hh++) {
                const float v0 = acc[mt][nt][hh*2+0];
                const float v1 = acc[mt][nt][hh*2+1];
                const size_t idx = ((size_t)(b*SEQ + mb + hh*8))*DMODEL + h*DHEAD + nb;
                const unsigned ph = packbf(v0, v1);
                const unsigned pl = packbf(v0 - bf_lo(ph), v1 - bf_up(ph));
                *reinterpret_cast<unsigned*>(&g_ath[idx]) = ph;
                *reinterpret_cast<unsigned*>(&g_atl[idx]) = pl;
            }
        }
}

// ---------------- output projection GEMM (bf16 3-term) ----------------
__global__ void __launch_bounds__(256, 2)
out_gemm(const float* __restrict__ bias, float* __restrict__ Cext, int K)
{
    extern __shared__ char sm[];
    const unsigned sbase = smem_u32(sm);

    const int tid  = threadIdx.x;
    const int lane = tid & 31;
    const int warp = tid >> 5;
    const int wm   = warp >> 2, wn = warp & 3;
    const int m0   = blockIdx.y * 128;
    const int n0   = blockIdx.x * 128;

    const __nv_bfloat16* Ah = g_ath;
    const __nv_bfloat16* Al = g_atl;
    const __nv_bfloat16* Bh = g_Woh;
    const __nv_bfloat16* Bl = g_Wol;

    auto load_stage = [&](int st, int kt) {
        const unsigned sb = sbase + st*BSTAGE;
#pragma unroll
        for (int i = 0; i < 8; i++) {
            const int idx  = tid + i*256;
            const int tile = idx >> 9;
            const int r    = (idx >> 2) & 127;
            const int c    = idx & 3;
            const __nv_bfloat16* s = (tile == 0) ? Ah : (tile == 1) ? Al :
                                     (tile == 2) ? Bh : Bl;
            const int rg = ((tile < 2) ? m0 : n0) + r;
            cpa16s(sb + tile*TILEB + r*(LDK*2) + c*16,
                   s + (size_t)rg*K + kt + c*8);
        }
    };

    float acc[4][4][4];
#pragma unroll
    for (int i = 0; i < 4; i++)
#pragma unroll
        for (int j = 0; j < 4; j++)
#pragma unroll
            for (int f = 0; f < 4; f++) acc[i][j][f] = 0.f;

    const int rowA = (lane & 7) + ((lane >> 3) & 1) * 8;
    const int colA = ((lane >> 4) & 1) * 8;
    const int rowB = (lane & 7) + ((lane >> 4) & 1) * 8;
    const int colB = ((lane >> 3) & 1) * 8;

    const int iters = K >> 5;
    load_stage(0, 0);
    cpa_commit();

    for (int it = 0; it < iters; ++it) {
        const int cur = it & 1;
        if (it + 1 < iters) { load_stage(cur ^ 1, (it + 1) << 5); cpa_commit(); cpa_wait<1>(); }
        else                { cpa_wait<0>(); }
        __syncthreads();

        const unsigned sb  = sbase + cur*BSTAGE;
        const unsigned aAh = sb + (wm*64 + rowA)*(LDK*2) + colA*2;
        const unsigned aAl = aAh + TILEB;
        const unsigned aBh = sb + 2*TILEB + (wn*32 + rowB)*(LDK*2) + colB*2;
        const unsigned aBl = aBh + TILEB;

#pragma unroll
        for (int ks = 0; ks < 2; ks++) {
            const unsigned ko = ks*32;
            unsigned bh[4][2], bl[4][2];
#pragma unroll
            for (int p = 0; p < 2; p++) {
                unsigned r0, r1, r2, r3;
                ldm4(r0, r1, r2, r3, aBh + p*16*(LDK*2) + ko);
                bh[2*p][0]=r0; bh[2*p][1]=r1; bh[2*p+1][0]=r2; bh[2*p+1][1]=r3;
                ldm4(r0, r1, r2, r3, aBl + p*16*(LDK*2) + ko);
                bl[2*p][0]=r0; bl[2*p][1]=r1; bl[2*p+1][0]=r2; bl[2*p+1][1]=r3;
            }
#pragma unroll
            for (int mt = 0; mt < 4; mt++) {
                unsigned a[4], al_[4];
                ldm4(a[0], a[1], a[2], a[3],     aAh + mt*16*(LDK*2) + ko);
                ldm4(al_[0], al_[1], al_[2], al_[3], aAl + mt*16*(LDK*2) + ko);
#pragma unroll
                for (int nt = 0; nt < 4; nt++) {
                    mmabf(acc[mt][nt], a[0],a[1],a[2],a[3],     bh[nt][0], bh[nt][1]);
                    mmabf(acc[mt][nt], a[0],a[1],a[2],a[3],     bl[nt][0], bl[nt][1]);
                    mmabf(acc[mt][nt], al_[0],al_[1],al_[2],al_[3], bh[nt][0], bh[nt][1]);
                }
            }
        }
        __syncthreads();
    }

    const int lr2 = lane >> 2;
    const int lc2 = (lane & 3) << 1;
#pragma unroll
    for (int mt = 0; mt < 4; mt++)
#pragma unroll
        for (int nt = 0; nt < 4; nt++) {
#pragma unroll
            for (int hh = 0; hh < 2; hh++) {
                const int m = m0 + wm*64 + mt*16 + lr2 + hh*8;
                const int n = n0 + wn*32 + nt*8 + lc2;
                float2 o;
                o.x = acc[mt][nt][hh*2+0] + bias[n];
                o.y = acc[mt][nt][hh*2+1] + bias[n+1];
                *reinterpret_cast<float2*>(&Cext[(size_t)m*DMODEL + n]) = o;
            }
        }
}

// ---------------- launch ----------------
extern "C" void kernel_launch(void* const* d_in, const int* in_sizes, int n_in,
                              void* d_out, int out_size)
{
    const float* x_q      = (const float*)d_in[0];
    const float* x_kv     = (const float*)d_in[1];
    const float* W_head_w = (const float*)d_in[2];
    const float* W_head_b = (const float*)d_in[3];
    const float* W_v_w    = (const float*)d_in[4];
    const float* W_v_b    = (const float*)d_in[5];
    const float* W_out_w  = (const float*)d_in[6];
    const float* W_out_b  = (const float*)d_in[7];
    const float* rel_emb  = (const float*)d_in[8];
    const float* col_head = (const float*)d_in[9];
    const float* col_tail = (const float*)d_in[10];

    float* out_x  = (float*)d_out;                          // [32,512,1024]
    float* out_fr = out_x + (size_t)BATCH*SEQ*DMODEL;       // [256,512,512]

    static bool attr_done = false;
    if (!attr_done) {
        cudaFuncSetAttribute(proj_h,     cudaFuncAttributeMaxDynamicSharedMemorySize, HG_DSM);
        cudaFuncSetAttribute(attn_fused, cudaFuncAttributeMaxDynamicSharedMemorySize, FU_DSM);
        cudaFuncSetAttribute(out_gemm,   cudaFuncAttributeMaxDynamicSharedMemorySize, BFG_DSM);
        attr_done = true;
    }

    // 1) conversions
    cvt_x<<<dim3(2048, 2), 256>>>(x_q, x_kv);
    cvt_w<<<dim3(512, 3),  256>>>(W_head_w, W_v_w, W_out_w);

    // 2) learned column topology mask
    adj_kernel<<<dim3(SEQ, HEADS), 128>>>(col_head, col_tail);

    // 3) projections (fp16 single-pass, merged)
    proj_h<<<dim3(8, 128, 3), 256, HG_DSM>>>(W_head_b, W_v_b, rel_emb, DMODEL);

    // 4) fused scores + softmax + P @ V -> fr final probs, attn hi/lo
    attn_fused<<<dim3(1, 4, BHS), 256, FU_DSM>>>(out_fr);

    // 5) output projection (bf16 3-term)
    out_gemm<<<dim3(8, 128), 256, BFG_DSM>>>(W_out_b, out_x, DMODEL);
}

// round 12
// speedup vs baseline: 1.7899x; 1.1470x over previous
#include <cuda_runtime.h>
#include <cuda_bf16.h>
#include <cuda_fp16.h>
#include <math.h>
#include <cstdint>

#define BATCH   32
#define HEADS   8
#define SEQ     512
#define DMODEL  1024
#define DHEAD   128
#define DCOL    18
#define BHS     (BATCH*HEADS)   // 256
#define BSD     ((size_t)BATCH*SEQ*DMODEL)   // 16777216
#define SCALE   0.08838834764831845f

// ---------------- scratch (static device globals; no allocation) ----------------
__device__ __align__(256) __half        g_xqf[BSD], g_xkf[BSD];          // fp16 inputs
__device__ __align__(256) __half        g_Whf[DMODEL*DMODEL], g_Wvf[DMODEL*DMODEL];
__device__ __align__(256) __half        g_Wof[DMODEL*DMODEL];
__device__ __align__(256) __half        g_fhf[BSD], g_ftf[BSD];          // f_head/f_tail fp16
__device__ __align__(256) float         g_fv [BSD];                      // f_v fp32
__device__ __align__(256) __half        g_atf[BSD];                      // attn fp16
__device__ __align__(256) float         g_adjm[(size_t)HEADS*SEQ*SEQ];

// ---------------- small helpers ----------------
__device__ __forceinline__ unsigned packbf(float f0, float f1) {   // f0 -> low half
    unsigned d;
    asm("cvt.rn.bf16x2.f32 %0, %1, %2;" : "=r"(d) : "f"(f1), "f"(f0));
    return d;
}
__device__ __forceinline__ unsigned packh(float f0, float f1) {    // f0 -> low half
    unsigned d;
    asm("cvt.rn.f16x2.f32 %0, %1, %2;" : "=r"(d) : "f"(f1), "f"(f0));
    return d;
}
__device__ __forceinline__ float bf_lo(unsigned p) { return __uint_as_float(p << 16); }
__device__ __forceinline__ float bf_up(unsigned p) { return __uint_as_float(p & 0xFFFF0000u); }

__device__ __forceinline__ unsigned smem_u32(const void* p) {
    unsigned a;
    asm("{ .reg .u64 t; cvta.to.shared.u64 t, %1; cvt.u32.u64 %0, t; }" : "=r"(a) : "l"(p));
    return a;
}
__device__ __forceinline__ void cpa16s(unsigned dst, const void* src) {
    asm volatile("cp.async.ca.shared.global [%0], [%1], 16;" :: "r"(dst), "l"(src));
}
__device__ __forceinline__ void cpa_commit() { asm volatile("cp.async.commit_group;"); }
template<int N>
__device__ __forceinline__ void cpa_wait() { asm volatile("cp.async.wait_group %0;" :: "n"(N)); }

__device__ __forceinline__ void ldm4(unsigned& r0, unsigned& r1, unsigned& r2, unsigned& r3,
                                     unsigned addr) {
    asm volatile("ldmatrix.sync.aligned.m8n8.x4.shared.b16 {%0,%1,%2,%3}, [%4];"
                 : "=r"(r0), "=r"(r1), "=r"(r2), "=r"(r3) : "r"(addr));
}

__device__ __forceinline__ void mmabf(float* c, unsigned a0, unsigned a1, unsigned a2,
                                      unsigned a3, unsigned b0, unsigned b1) {
    asm volatile(
        "mma.sync.aligned.m16n8k16.row.col.f32.bf16.bf16.f32 "
        "{%0,%1,%2,%3}, {%4,%5,%6,%7}, {%8,%9}, {%0,%1,%2,%3};\n"
        : "+f"(c[0]), "+f"(c[1]), "+f"(c[2]), "+f"(c[3])
        : "r"(a0), "r"(a1), "r"(a2), "r"(a3), "r"(b0), "r"(b1));
}

__device__ __forceinline__ void mmah(float* c, unsigned a0, unsigned a1, unsigned a2,
                                     unsigned a3, unsigned b0, unsigned b1) {
    asm volatile(
        "mma.sync.aligned.m16n8k16.row.col.f32.f16.f16.f32 "
        "{%0,%1,%2,%3}, {%4,%5,%6,%7}, {%8,%9}, {%0,%1,%2,%3};\n"
        : "+f"(c[0]), "+f"(c[1]), "+f"(c[2]), "+f"(c[3])
        : "r"(a0), "r"(a1), "r"(a2), "r"(a3), "r"(b0), "r"(b1));
}

__device__ __forceinline__ void cvt8(const float* f, unsigned* ph, unsigned* pl) {
#pragma unroll
    for (int j = 0; j < 4; j++) {
        unsigned h = packbf(f[2*j], f[2*j+1]);
        ph[j] = h;
        pl[j] = packbf(f[2*j] - bf_lo(h), f[2*j+1] - bf_up(h));
    }
}

// ---------------- conversions (all fp16 now) ----------------
__global__ void cvt_x(const float* __restrict__ xq, const float* __restrict__ xkv)
{
    const int sel = blockIdx.y;
    const float4* s4 = reinterpret_cast<const float4*>(sel ? xkv : xq);
    uint2* out = reinterpret_cast<uint2*>(sel ? g_xkf : g_xqf);
    const int n4 = (int)(BSD/4);
    for (int i = blockIdx.x * blockDim.x + threadIdx.x; i < n4; i += gridDim.x * blockDim.x) {
        float4 v = s4[i];
        out[i] = make_uint2(packh(v.x, v.y), packh(v.z, v.w));
    }
}

__global__ void cvt_w(const float* __restrict__ wh, const float* __restrict__ wv,
                      const float* __restrict__ wo)
{
    const int sel = blockIdx.y;
    const float4* s4 = reinterpret_cast<const float4*>(sel == 0 ? wh : sel == 1 ? wv : wo);
    uint2* out = reinterpret_cast<uint2*>(sel == 0 ? g_Whf : sel == 1 ? g_Wvf : g_Wof);
    const int n4 = DMODEL*DMODEL/4;
    for (int i = blockIdx.x * blockDim.x + threadIdx.x; i < n4; i += gridDim.x * blockDim.x) {
        float4 v = s4[i];
        out[i] = make_uint2(packh(v.x, v.y), packh(v.z, v.w));
    }
}

// ---------------- adjacency: softmax(col_head @ col_tail^T, diag=0) ----------------
__global__ void adj_kernel(const float* __restrict__ col_head,
                           const float* __restrict__ col_tail)
{
    const int q = blockIdx.x;
    const int h = blockIdx.y;
    const int t = threadIdx.x;                 // 128 threads
    __shared__ float ch[DCOL];
    __shared__ float sred[4];

    if (t < DCOL) ch[t] = col_head[((size_t)h*SEQ + q)*DCOL + t];
    __syncthreads();

    float l[4];
#pragma unroll
    for (int i = 0; i < 4; i++) {
        const int k = t + i*128;
        const float* ct = col_tail + ((size_t)h*SEQ + k)*DCOL;
        float s = 0.f;
#pragma unroll
        for (int c = 0; c < DCOL; c++) s += ch[c]*ct[c];
        l[i] = (k == q) ? 0.f : s;
    }

    float mx = fmaxf(fmaxf(l[0],l[1]), fmaxf(l[2],l[3]));
#pragma unroll
    for (int o = 16; o; o >>= 1) mx = fmaxf(mx, __shfl_xor_sync(0xffffffffu, mx, o));
    if ((t & 31) == 0) sred[t >> 5] = mx;
    __syncthreads();
    mx = fmaxf(fmaxf(sred[0],sred[1]), fmaxf(sred[2],sred[3]));
    __syncthreads();

    float e[4]; float sum = 0.f;
#pragma unroll
    for (int i = 0; i < 4; i++) { e[i] = expf(l[i]-mx); sum += e[i]; }
#pragma unroll
    for (int o = 16; o; o >>= 1) sum += __shfl_xor_sync(0xffffffffu, sum, o);
    if ((t & 31) == 0) sred[t >> 5] = sum;
    __syncthreads();
    sum = sred[0]+sred[1]+sred[2]+sred[3];
    const float inv = 1.f/sum;

    float* dst = g_adjm + ((size_t)h*SEQ + q)*SEQ;
#pragma unroll
    for (int i = 0; i < 4; i++) {
        const int k = t + i*128;
        dst[k] = (1.f - e[i]*inv) * (-10000.f);
    }
}

// ---------------- tile constants ----------------
#define LDK     40                  // padded smem row (16b elems), 80 B
#define TILEB   (128*LDK*2)         // 10240 B
#define HSTAGE  (2*TILEB)           // fp16 single: A + B
#define HG_DSM  (2*HSTAGE)          // 40960

// ---------------- fp16 single-pass projections: blockIdx.z = mode (0,1,2) ----------------
__global__ void __launch_bounds__(256, 2)
proj_h(const float* __restrict__ biasH, const float* __restrict__ biasV,
       const float* __restrict__ aux, int K)
{
    extern __shared__ char sm[];
    const unsigned sbase = smem_u32(sm);

    const int tid  = threadIdx.x;
    const int lane = tid & 31;
    const int warp = tid >> 5;
    const int wm   = warp >> 2, wn = warp & 3;
    const int mode = blockIdx.z;
    const int m0   = blockIdx.y * 128;
    const int n0   = blockIdx.x * 128;

    const __half* A = (mode == 0) ? g_xqf : g_xkf;
    const __half* B = (mode == 2) ? g_Wvf : g_Whf;
    const float* bias = (mode == 2) ? biasV : biasH;

    auto load_stage = [&](int st, int kt) {
        const unsigned sb = sbase + st*HSTAGE;
#pragma unroll
        for (int i = 0; i < 4; i++) {
            const int idx  = tid + i*256;
            const int tile = idx >> 9;
            const int r    = (idx >> 2) & 127;
            const int c    = idx & 3;
            const __half* s = tile ? B : A;
            const int rg = (tile ? n0 : m0) + r;
            cpa16s(sb + tile*TILEB + r*(LDK*2) + c*16,
                   s + (size_t)rg*K + kt + c*8);
        }
    };

    float acc[4][4][4];
#pragma unroll
    for (int i = 0; i < 4; i++)
#pragma unroll
        for (int j = 0; j < 4; j++)
#pragma unroll
            for (int f = 0; f < 4; f++) acc[i][j][f] = 0.f;

    const int rowA = (lane & 7) + ((lane >> 3) & 1) * 8;
    const int colA = ((lane >> 4) & 1) * 8;
    const int rowB = (lane & 7) + ((lane >> 4) & 1) * 8;
    const int colB = ((lane >> 3) & 1) * 8;

    const int iters = K >> 5;
    load_stage(0, 0);
    cpa_commit();

    for (int it = 0; it < iters; ++it) {
        const int cur = it & 1;
        if (it + 1 < iters) { load_stage(cur ^ 1, (it + 1) << 5); cpa_commit(); cpa_wait<1>(); }
        else                { cpa_wait<0>(); }
        __syncthreads();

        const unsigned sb = sbase + cur*HSTAGE;
        const unsigned aA = sb + (wm*64 + rowA)*(LDK*2) + colA*2;
        const unsigned aB = sb + TILEB + (wn*32 + rowB)*(LDK*2) + colB*2;

#pragma unroll
        for (int ks = 0; ks < 2; ks++) {
            const unsigned ko = ks*32;
            unsigned bh[4][2];
#pragma unroll
            for (int p = 0; p < 2; p++) {
                unsigned r0, r1, r2, r3;
                ldm4(r0, r1, r2, r3, aB + p*16*(LDK*2) + ko);
                bh[2*p][0]=r0; bh[2*p][1]=r1; bh[2*p+1][0]=r2; bh[2*p+1][1]=r3;
            }
#pragma unroll
            for (int mt = 0; mt < 4; mt++) {
                unsigned a[4];
                ldm4(a[0], a[1], a[2], a[3], aA + mt*16*(LDK*2) + ko);
#pragma unroll
                for (int nt = 0; nt < 4; nt++)
                    mmah(acc[mt][nt], a[0],a[1],a[2],a[3], bh[nt][0], bh[nt][1]);
            }
        }
        __syncthreads();
    }

    const int lr2 = lane >> 2;
    const int lc2 = (lane & 3) << 1;
#pragma unroll
    for (int mt = 0; mt < 4; mt++)
#pragma unroll
        for (int nt = 0; nt < 4; nt++) {
#pragma unroll
            for (int hh = 0; hh < 2; hh++) {
                const int m = m0 + wm*64 + mt*16 + lr2 + hh*8;
                const int n = n0 + wn*32 + nt*8 + lc2;
                float v0 = acc[mt][nt][hh*2+0] + bias[n];
                float v1 = acc[mt][nt][hh*2+1] + bias[n+1];
                const int b = m >> 9, q = m & 511, h = n >> 7, dh = n & 127;
                const size_t idx = (((size_t)((b<<3)|h))*SEQ + q)*DHEAD + dh;
                if (mode < 2) {
                    v0 *= aux[n]; v1 *= aux[n+1];
                    __half* dst = (mode == 0) ? g_fhf : g_ftf;
                    *reinterpret_cast<unsigned*>(&dst[idx]) = packh(v0, v1);
                } else {
                    float2 o; o.x = v0; o.y = v1;
                    *reinterpret_cast<float2*>(&g_fv[idx]) = o;
                }
            }
        }
}

// ---------------- fused scores + softmax + P @ V ----------------
#define FU_RUNM  49152
#define FU_RUNS  (FU_RUNM + 512)
#define FU_MPART (FU_RUNM + 1024)
#define FU_SPART (FU_MPART + 2048)
#define FU_DSM   (FU_MPART + 4096)   // 54272

__global__ void __launch_bounds__(256, 2)
attn_fused(float* __restrict__ fr)
{
    extern __shared__ char sm[];
    const unsigned sbase = smem_u32(sm);
    unsigned* pW  = reinterpret_cast<unsigned*>(sm);
    float* run_m  = reinterpret_cast<float*>(sm + FU_RUNM);
    float* run_s  = reinterpret_cast<float*>(sm + FU_RUNS);
    float* m_part = reinterpret_cast<float*>(sm + FU_MPART);
    float* s_part = reinterpret_cast<float*>(sm + FU_SPART);

    const int tid  = threadIdx.x;
    const int lane = tid & 31;
    const int warp = tid >> 5;
    const int wm   = warp >> 2, wn = warp & 3;
    const int lr2  = lane >> 2;
    const int lc2  = (lane & 3) << 1;
    const int lc   = lane & 3;
    const int z    = blockIdx.z;
    const int m0   = blockIdx.y * 128;
    const int h    = z & 7;

    const __half* Af = g_fhf + (size_t)z*SEQ*DHEAD;
    const __half* Bf = g_ftf + (size_t)z*SEQ*DHEAD;
    float* frz = fr + (size_t)z*SEQ*SEQ;

    if (tid < 128) { run_m[tid] = -3.4e38f; run_s[tid] = 0.f; }
    __syncthreads();

    const int rowA = (lane & 7) + ((lane >> 3) & 1) * 8;
    const int colA = ((lane >> 4) & 1) * 8;
    const int rowB = (lane & 7) + ((lane >> 4) & 1) * 8;
    const int colB = ((lane >> 3) & 1) * 8;

    // ================= pass 1 =================
    for (int ntile = 0; ntile < 4; ++ntile) {
        const int n0 = ntile * 128;

        auto load_stage = [&](int st, int kt) {
            const unsigned sb = sbase + st*HSTAGE;
#pragma unroll
            for (int i = 0; i < 4; i++) {
                const int idx  = tid + i*256;
                const int tile = idx >> 9;
                const int r    = (idx >> 2) & 127;
                const int c    = idx & 3;
                const __half* s = tile ? Bf : Af;
                const int rg = (tile ? n0 : m0) + r;
                cpa16s(sb + tile*TILEB + r*(LDK*2) + c*16,
                       s + (size_t)rg*DHEAD + kt + c*8);
            }
        };

        float acc[4][4][4];
#pragma unroll
        for (int i = 0; i < 4; i++)
#pragma unroll
            for (int j = 0; j < 4; j++)
#pragma unroll
                for (int f = 0; f < 4; f++) acc[i][j][f] = 0.f;

        load_stage(0, 0);
        cpa_commit();

        for (int it = 0; it < 4; ++it) {
            const int cur = it & 1;
            if (it + 1 < 4) { load_stage(cur ^ 1, (it + 1) << 5); cpa_commit(); cpa_wait<1>(); }
            else            { cpa_wait<0>(); }
            __syncthreads();

            const unsigned sb = sbase + cur*HSTAGE;
            const unsigned aA = sb + (wm*64 + rowA)*(LDK*2) + colA*2;
            const unsigned aB = sb + TILEB + (wn*32 + rowB)*(LDK*2) + colB*2;

#pragma unroll
            for (int ks = 0; ks < 2; ks++) {
                const unsigned ko = ks*32;
                unsigned bh[4][2];
#pragma unroll
                for (int p = 0; p < 2; p++) {
                    unsigned r0, r1, r2, r3;
                    ldm4(r0, r1, r2, r3, aB + p*16*(LDK*2) + ko);
                    bh[2*p][0]=r0; bh[2*p][1]=r1; bh[2*p+1][0]=r2; bh[2*p+1][1]=r3;
                }
#pragma unroll
                for (int mt = 0; mt < 4; mt++) {
                    unsigned a[4];
                    ldm4(a[0], a[1], a[2], a[3], aA + mt*16*(LDK*2) + ko);
#pragma unroll
                    for (int nt = 0; nt < 4; nt++)
                        mmah(acc[mt][nt], a[0],a[1],a[2],a[3], bh[nt][0], bh[nt][1]);
                }
            }
            __syncthreads();
        }

        // epilogue: logits -> fr + per-32col row stats via quad shuffles
#pragma unroll
        for (int mt = 0; mt < 4; mt++) {
#pragma unroll
            for (int hh = 0; hh < 2; hh++) {
                const int ml = wm*64 + mt*16 + lr2 + hh*8;
                float vv[8];
                float mx = -3.4e38f;
#pragma unroll
                for (int nt = 0; nt < 4; nt++) {
                    const int nl = wn*32 + nt*8 + lc2;
                    const size_t off = (size_t)(m0 + ml)*SEQ + n0 + nl;
                    float2 am = *reinterpret_cast<const float2*>(&g_adjm[(size_t)h*SEQ*SEQ + off]);
                    float v0 = acc[mt][nt][hh*2+0] * SCALE + am.x;
                    float v1 = acc[mt][nt][hh*2+1] * SCALE + am.y;
                    float2 o; o.x = v0; o.y = v1;
                    *reinterpret_cast<float2*>(&frz[off]) = o;
                    vv[nt*2]   = v0;
                    vv[nt*2+1] = v1;
                    mx = fmaxf(mx, fmaxf(v0, v1));
                }
                mx = fmaxf(mx, __shfl_xor_sync(0xffffffffu, mx, 1));
                mx = fmaxf(mx, __shfl_xor_sync(0xffffffffu, mx, 2));
                float s = 0.f;
#pragma unroll
                for (int j = 0; j < 8; j++) s += __expf(vv[j] - mx);
                s += __shfl_xor_sync(0xffffffffu, s, 1);
                s += __shfl_xor_sync(0xffffffffu, s, 2);
                if (lc == 0) { m_part[ml*4 + wn] = mx; s_part[ml*4 + wn] = s; }
            }
        }
        __syncthreads();

        if (tid < 128) {
            float m4 = -3.4e38f;
#pragma unroll
            for (int w = 0; w < 4; w++) m4 = fmaxf(m4, m_part[tid*4 + w]);
            float s4 = 0.f;
#pragma unroll
            for (int w = 0; w < 4; w++) s4 += s_part[tid*4 + w] * __expf(m_part[tid*4 + w] - m4);
            const float mo = run_m[tid], so = run_s[tid];
            const float mn = fmaxf(mo, m4);
            run_s[tid] = so * __expf(mo - mn) + s4 * __expf(m4 - mn);
            run_m[tid] = mn;
        }
        __syncthreads();
    }

    // ================= pass 2: softmax-apply + P @ V =================
    const float* Bp = g_fv + (size_t)z*SEQ*DHEAD;
    const int arow  = tid >> 1;
    const int akoff = (tid & 1) << 3;
    const int bn    = tid & 127;
    const int bhalf = tid >> 7;

    const float mr = run_m[arow];
    const float ir = 1.f / run_s[arow];

    float fa[8], fb[8];
    auto ldg_stage = [&](int kt) {
        const float* ap = frz + (size_t)(m0 + arow)*SEQ + kt + akoff;
        float4 v0 = *reinterpret_cast<const float4*>(ap);
        float4 v1 = *reinterpret_cast<const float4*>(ap + 4);
        fa[0]=v0.x; fa[1]=v0.y; fa[2]=v0.z; fa[3]=v0.w;
        fa[4]=v1.x; fa[5]=v1.y; fa[6]=v1.z; fa[7]=v1.w;
#pragma unroll
        for (int j = 0; j < 8; j++)
            fb[j] = Bp[(size_t)(kt + 8*bhalf + j)*DHEAD + bn];
    };

    ldg_stage(0);

    float acc[4][4][4];
#pragma unroll
    for (int i = 0; i < 4; i++)
#pragma unroll
        for (int j = 0; j < 4; j++)
#pragma unroll
            for (int f = 0; f < 4; f++) acc[i][j][f] = 0.f;

    for (int it = 0; it < 32; ++it) {
        const unsigned b0 = (unsigned)(it & 1) * 6144;
        {
#pragma unroll
            for (int j = 0; j < 8; j++) fa[j] = __expf(fa[j] - mr) * ir;

            float* ap = frz + (size_t)(m0 + arow)*SEQ + it*16 + akoff;
            *reinterpret_cast<float4*>(ap)     = make_float4(fa[0], fa[1], fa[2], fa[3]);
            *reinterpret_cast<float4*>(ap + 4) = make_float4(fa[4], fa[5], fa[6], fa[7]);

            unsigned ph[4], pl[4];
            cvt8(fa, ph, pl);
            *reinterpret_cast<uint4*>(&pW[b0 +        arow*12 + (akoff >> 1)]) =
                make_uint4(ph[0], ph[1], ph[2], ph[3]);
            *reinterpret_cast<uint4*>(&pW[b0 + 1536 + arow*12 + (akoff >> 1)]) =
                make_uint4(pl[0], pl[1], pl[2], pl[3]);
            cvt8(fb, ph, pl);
            *reinterpret_cast<uint4*>(&pW[b0 + 3072 + bn*12 + 4*bhalf]) =
                make_uint4(ph[0], ph[1], ph[2], ph[3]);
            *reinterpret_cast<uint4*>(&pW[b0 + 4608 + bn*12 + 4*bhalf]) =
                make_uint4(pl[0], pl[1], pl[2], pl[3]);
        }
        __syncthreads();

        if (it + 1 < 32) ldg_stage((it + 1) * 16);

        uint2 a0[4], a1[4], b_h[4], b_l[4];
#pragma unroll
        for (int mt = 0; mt < 4; mt++) {
            const int r = wm*64 + mt*16 + lr2;
            a0[mt] = *reinterpret_cast<const uint2*>(&pW[b0 + r*12 + 2*lc]);
            a1[mt] = *reinterpret_cast<const uint2*>(&pW[b0 + (r+8)*12 + 2*lc]);
        }
#pragma unroll
        for (int nt = 0; nt < 4; nt++) {
            const int c = wn*32 + nt*8 + lr2;
            b_h[nt] = *reinterpret_cast<const uint2*>(&pW[b0 + 3072 + c*12 + 2*lc]);
            b_l[nt] = *reinterpret_cast<const uint2*>(&pW[b0 + 4608 + c*12 + 2*lc]);
        }
#pragma unroll
        for (int mt = 0; mt < 4; mt++)
#pragma unroll
            for (int nt = 0; nt < 4; nt++) {
                mmabf(acc[mt][nt], a0[mt].x, a1[mt].x, a0[mt].y, a1[mt].y, b_h[nt].x, b_h[nt].y);
                mmabf(acc[mt][nt], a0[mt].x, a1[mt].x, a0[mt].y, a1[mt].y, b_l[nt].x, b_l[nt].y);
            }
#pragma unroll
        for (int mt = 0; mt < 4; mt++) {
            const int r = wm*64 + mt*16 + lr2;
            a0[mt] = *reinterpret_cast<const uint2*>(&pW[b0 + 1536 + r*12 + 2*lc]);
            a1[mt] = *reinterpret_cast<const uint2*>(&pW[b0 + 1536 + (r+8)*12 + 2*lc]);
        }
#pragma unroll
        for (int mt = 0; mt < 4; mt++)
#pragma unroll
            for (int nt = 0; nt < 4; nt++)
                mmabf(acc[mt][nt], a0[mt].x, a1[mt].x, a0[mt].y, a1[mt].y, b_h[nt].x, b_h[nt].y);
    }

    // epilogue: emit attn fp16
    const int b = z >> 3;
#pragma unroll
    for (int mt = 0; mt < 4; mt++)
#pragma unroll
        for (int nt = 0; nt < 4; nt++) {
            const int mb = m0 + wm*64 + mt*16 + lr2;
            const int nb = wn*32 + nt*8 + lc2;
#pragma unroll
            for (int hh = 0; hh < 2; hh++) {
                const size_t idx = ((size_t)(b*SEQ + mb + hh*8))*DMODEL + h*DHEAD + nb;
                *reinterpret_cast<unsigned*>(&g_atf[idx]) =
                    packh(acc[mt][nt][hh*2+0], acc[mt][nt][hh*2+1]);
            }
        }
}

// ---------------- output projection (fp16 single-pass) ----------------
__global__ void __launch_bounds__(256, 2)
out_h(const float* __restrict__ bias, float* __restrict__ Cext, int K)
{
    extern __shared__ char sm[];
    const unsigned sbase = smem_u32(sm);

    const int tid  = threadIdx.x;
    const int lane = tid & 31;
    const int warp = tid >> 5;
    const int wm   = warp >> 2, wn = warp & 3;
    const int m0   = blockIdx.y * 128;
    const int n0   = blockIdx.x * 128;

    const __half* A = g_atf;
    const __half* B = g_Wof;

    auto load_stage = [&](int st, int kt) {
        const unsigned sb = sbase + st*HSTAGE;
#pragma unroll
        for (int i = 0; i < 4; i++) {
            const int idx  = tid + i*256;
            const int tile = idx >> 9;
            const int r    = (idx >> 2) & 127;
            const int c    = idx & 3;
            const __half* s = tile ? B : A;
            const int rg = (tile ? n0 : m0) + r;
            cpa16s(sb + tile*TILEB + r*(LDK*2) + c*16,
                   s + (size_t)rg*K + kt + c*8);
        }
    };

    float acc[4][4][4];
#pragma unroll
    for (int i = 0; i < 4; i++)
#pragma unroll
        for (int j = 0; j < 4; j++)
#pragma unroll
            for (int f = 0; f < 4; f++) acc[i][j][f] = 0.f;

    const int rowA = (lane & 7) + ((lane >> 3) & 1) * 8;
    const int colA = ((lane >> 4) & 1) * 8;
    const int rowB = (lane & 7) + ((lane >> 4) & 1) * 8;
    const int colB = ((lane >> 3) & 1) * 8;

    const int iters = K >> 5;
    load_stage(0, 0);
    cpa_commit();

    for (int it = 0; it < iters; ++it) {
        const int cur = it & 1;
        if (it + 1 < iters) { load_stage(cur ^ 1, (it + 1) << 5); cpa_commit(); cpa_wait<1>(); }
        else                { cpa_wait<0>(); }
        __syncthreads();

        const unsigned sb = sbase + cur*HSTAGE;
        const unsigned aA = sb + (wm*64 + rowA)*(LDK*2) + colA*2;
        const unsigned aB = sb + TILEB + (wn*32 + rowB)*(LDK*2) + colB*2;

#pragma unroll
        for (int ks = 0; ks < 2; ks++) {
            const unsigned ko = ks*32;
            unsigned bh[4][2];
#pragma unroll
            for (int p = 0; p < 2; p++) {
                unsigned r0, r1, r2, r3;
                ldm4(r0, r1, r2, r3, aB + p*16*(LDK*2) + ko);
                bh[2*p][0]=r0; bh[2*p][1]=r1; bh[2*p+1][0]=r2; bh[2*p+1][1]=r3;
            }
#pragma unroll
            for (int mt = 0; mt < 4; mt++) {
                unsigned a[4];
                ldm4(a[0], a[1], a[2], a[3], aA + mt*16*(LDK*2) + ko);
#pragma unroll
                for (int nt = 0; nt < 4; nt++)
                    mmah(acc[mt][nt], a[0],a[1],a[2],a[3], bh[nt][0], bh[nt][1]);
            }
        }
        __syncthreads();
    }

    const int lr2 = lane >> 2;
    const int lc2 = (lane & 3) << 1;
#pragma unroll
    for (int mt = 0; mt < 4; mt++)
#pragma unroll
        for (int nt = 0; nt < 4; nt++) {
#pragma unroll
            for (int hh = 0; hh < 2; hh++) {
                const int m = m0 + wm*64 + mt*16 + lr2 + hh*8;
                const int n = n0 + wn*32 + nt*8 + lc2;
                float2 o;
                o.x = acc[mt][nt][hh*2+0] + bias[n];
                o.y = acc[mt][nt][hh*2+1] + bias[n+1];
                *reinterpret_cast<float2*>(&Cext[(size_t)m*DMODEL + n]) = o;
            }
        }
}

// ---------------- launch ----------------
extern "C" void kernel_launch(void* const* d_in, const int* in_sizes, int n_in,
                              void* d_out, int out_size)
{
    const float* x_q      = (const float*)d_in[0];
    const float* x_kv     = (const float*)d_in[1];
    const float* W_head_w = (const float*)d_in[2];
    const float* W_head_b = (const float*)d_in[3];
    const float* W_v_w    = (const float*)d_in[4];
    const float* W_v_b    = (const float*)d_in[5];
    const float* W_out_w  = (const float*)d_in[6];
    const float* W_out_b  = (const float*)d_in[7];
    const float* rel_emb  = (const float*)d_in[8];
    const float* col_head = (const float*)d_in[9];
    const float* col_tail = (const float*)d_in[10];

    float* out_x  = (float*)d_out;                          // [32,512,1024]
    float* out_fr = out_x + (size_t)BATCH*SEQ*DMODEL;       // [256,512,512]

    static bool attr_done = false;
    if (!attr_done) {
        cudaFuncSetAttribute(proj_h,     cudaFuncAttributeMaxDynamicSharedMemorySize, HG_DSM);
        cudaFuncSetAttribute(attn_fused, cudaFuncAttributeMaxDynamicSharedMemorySize, FU_DSM);
        cudaFuncSetAttribute(out_h,      cudaFuncAttributeMaxDynamicSharedMemorySize, HG_DSM);
        attr_done = true;
    }

    // 1) conversions (all fp16)
    cvt_x<<<dim3(2048, 2), 256>>>(x_q, x_kv);
    cvt_w<<<dim3(512, 3),  256>>>(W_head_w, W_v_w, W_out_w);

    // 2) learned column topology mask
    adj_kernel<<<dim3(SEQ, HEADS), 128>>>(col_head, col_tail);

    // 3) projections (fp16 single-pass, merged)
    proj_h<<<dim3(8, 128, 3), 256, HG_DSM>>>(W_head_b, W_v_b, rel_emb, DMODEL);

    // 4) fused scores + softmax + P @ V -> fr final probs, attn fp16
    attn_fused<<<dim3(1, 4, BHS), 256, FU_DSM>>>(out_fr);

    // 5) output projection (fp16 single-pass)
    out_h<<<dim3(8, 128), 256, HG_DSM>>>(W_out_b, out_x, DMODEL);
}

// round 13
// speedup vs baseline: 1.8230x; 1.0185x over previous
#include <cuda_runtime.h>
#include <cuda_bf16.h>
#include <cuda_fp16.h>
#include <math.h>
#include <cstdint>

#define BATCH   32
#define HEADS   8
#define SEQ     512
#define DMODEL  1024
#define DHEAD   128
#define DCOL    18
#define BHS     (BATCH*HEADS)   // 256
#define BSD     ((size_t)BATCH*SEQ*DMODEL)   // 16777216
#define SCALE   0.08838834764831845f

// ---------------- scratch (static device globals; no allocation) ----------------
__device__ __align__(256) __half        g_xqf[BSD], g_xkf[BSD];          // fp16 inputs
__device__ __align__(256) __half        g_Whf[DMODEL*DMODEL], g_Wvf[DMODEL*DMODEL];
__device__ __align__(256) __half        g_Wof[DMODEL*DMODEL];
__device__ __align__(256) __half        g_fhf[BSD], g_ftf[BSD];          // f_head/f_tail fp16
__device__ __align__(256) float         g_fv [BSD];                      // f_v fp32
__device__ __align__(256) __half        g_atf[BSD];                      // attn fp16
__device__ __align__(256) float         g_adjm[(size_t)HEADS*SEQ*SEQ];

// ---------------- small helpers ----------------
__device__ __forceinline__ unsigned packh(float f0, float f1) {    // f0 -> low half
    unsigned d;
    asm("cvt.rn.f16x2.f32 %0, %1, %2;" : "=r"(d) : "f"(f1), "f"(f0));
    return d;
}

__device__ __forceinline__ unsigned smem_u32(const void* p) {
    unsigned a;
    asm("{ .reg .u64 t; cvta.to.shared.u64 t, %1; cvt.u32.u64 %0, t; }" : "=r"(a) : "l"(p));
    return a;
}
__device__ __forceinline__ void cpa16s(unsigned dst, const void* src) {
    asm volatile("cp.async.ca.shared.global [%0], [%1], 16;" :: "r"(dst), "l"(src));
}
__device__ __forceinline__ void cpa_commit() { asm volatile("cp.async.commit_group;"); }
template<int N>
__device__ __forceinline__ void cpa_wait() { asm volatile("cp.async.wait_group %0;" :: "n"(N)); }

__device__ __forceinline__ void ldm4(unsigned& r0, unsigned& r1, unsigned& r2, unsigned& r3,
                                     unsigned addr) {
    asm volatile("ldmatrix.sync.aligned.m8n8.x4.shared.b16 {%0,%1,%2,%3}, [%4];"
                 : "=r"(r0), "=r"(r1), "=r"(r2), "=r"(r3) : "r"(addr));
}

__device__ __forceinline__ void mmah(float* c, unsigned a0, unsigned a1, unsigned a2,
                                     unsigned a3, unsigned b0, unsigned b1) {
    asm volatile(
        "mma.sync.aligned.m16n8k16.row.col.f32.f16.f16.f32 "
        "{%0,%1,%2,%3}, {%4,%5,%6,%7}, {%8,%9}, {%0,%1,%2,%3};\n"
        : "+f"(c[0]), "+f"(c[1]), "+f"(c[2]), "+f"(c[3])
        : "r"(a0), "r"(a1), "r"(a2), "r"(a3), "r"(b0), "r"(b1));
}

// ---------------- conversions (all fp16) ----------------
__global__ void cvt_x(const float* __restrict__ xq, const float* __restrict__ xkv)
{
    const int sel = blockIdx.y;
    const float4* s4 = reinterpret_cast<const float4*>(sel ? xkv : xq);
    uint2* out = reinterpret_cast<uint2*>(sel ? g_xkf : g_xqf);
    const int n4 = (int)(BSD/4);
    for (int i = blockIdx.x * blockDim.x + threadIdx.x; i < n4; i += gridDim.x * blockDim.x) {
        float4 v = s4[i];
        out[i] = make_uint2(packh(v.x, v.y), packh(v.z, v.w));
    }
}

__global__ void cvt_w(const float* __restrict__ wh, const float* __restrict__ wv,
                      const float* __restrict__ wo)
{
    const int sel = blockIdx.y;
    const float4* s4 = reinterpret_cast<const float4*>(sel == 0 ? wh : sel == 1 ? wv : wo);
    uint2* out = reinterpret_cast<uint2*>(sel == 0 ? g_Whf : sel == 1 ? g_Wvf : g_Wof);
    const int n4 = DMODEL*DMODEL/4;
    for (int i = blockIdx.x * blockDim.x + threadIdx.x; i < n4; i += gridDim.x * blockDim.x) {
        float4 v = s4[i];
        out[i] = make_uint2(packh(v.x, v.y), packh(v.z, v.w));
    }
}

// ---------------- adjacency: softmax(col_head @ col_tail^T, diag=0) ----------------
__global__ void adj_kernel(const float* __restrict__ col_head,
                           const float* __restrict__ col_tail)
{
    const int q = blockIdx.x;
    const int h = blockIdx.y;
    const int t = threadIdx.x;                 // 128 threads
    __shared__ float ch[DCOL];
    __shared__ float sred[4];

    if (t < DCOL) ch[t] = col_head[((size_t)h*SEQ + q)*DCOL + t];
    __syncthreads();

    float l[4];
#pragma unroll
    for (int i = 0; i < 4; i++) {
        const int k = t + i*128;
        const float* ct = col_tail + ((size_t)h*SEQ + k)*DCOL;
        float s = 0.f;
#pragma unroll
        for (int c = 0; c < DCOL; c++) s += ch[c]*ct[c];
        l[i] = (k == q) ? 0.f : s;
    }

    float mx = fmaxf(fmaxf(l[0],l[1]), fmaxf(l[2],l[3]));
#pragma unroll
    for (int o = 16; o; o >>= 1) mx = fmaxf(mx, __shfl_xor_sync(0xffffffffu, mx, o));
    if ((t & 31) == 0) sred[t >> 5] = mx;
    __syncthreads();
    mx = fmaxf(fmaxf(sred[0],sred[1]), fmaxf(sred[2],sred[3]));
    __syncthreads();

    float e[4]; float sum = 0.f;
#pragma unroll
    for (int i = 0; i < 4; i++) { e[i] = expf(l[i]-mx); sum += e[i]; }
#pragma unroll
    for (int o = 16; o; o >>= 1) sum += __shfl_xor_sync(0xffffffffu, sum, o);
    if ((t & 31) == 0) sred[t >> 5] = sum;
    __syncthreads();
    sum = sred[0]+sred[1]+sred[2]+sred[3];
    const float inv = 1.f/sum;

    float* dst = g_adjm + ((size_t)h*SEQ + q)*SEQ;
#pragma unroll
    for (int i = 0; i < 4; i++) {
        const int k = t + i*128;
        dst[k] = (1.f - e[i]*inv) * (-10000.f);
    }
}

// ---------------- tile constants ----------------
#define LDK     40                  // padded smem row (16b elems), 80 B
#define TILEB   (128*LDK*2)         // 10240 B
#define HSTAGE  (2*TILEB)           // fp16 single: A + B
#define HG_DSM  (2*HSTAGE)          // 40960

// ---------------- fp16 single-pass projections: blockIdx.z = mode (0,1,2) ----------------
__global__ void __launch_bounds__(256, 2)
proj_h(const float* __restrict__ biasH, const float* __restrict__ biasV,
       const float* __restrict__ aux, int K)
{
    extern __shared__ char sm[];
    const unsigned sbase = smem_u32(sm);

    const int tid  = threadIdx.x;
    const int lane = tid & 31;
    const int warp = tid >> 5;
    const int wm   = warp >> 2, wn = warp & 3;
    const int mode = blockIdx.z;
    const int m0   = blockIdx.y * 128;
    const int n0   = blockIdx.x * 128;

    const __half* A = (mode == 0) ? g_xqf : g_xkf;
    const __half* B = (mode == 2) ? g_Wvf : g_Whf;
    const float* bias = (mode == 2) ? biasV : biasH;

    auto load_stage = [&](int st, int kt) {
        const unsigned sb = sbase + st*HSTAGE;
#pragma unroll
        for (int i = 0; i < 4; i++) {
            const int idx  = tid + i*256;
            const int tile = idx >> 9;
            const int r    = (idx >> 2) & 127;
            const int c    = idx & 3;
            const __half* s = tile ? B : A;
            const int rg = (tile ? n0 : m0) + r;
            cpa16s(sb + tile*TILEB + r*(LDK*2) + c*16,
                   s + (size_t)rg*K + kt + c*8);
        }
    };

    float acc[4][4][4];
#pragma unroll
    for (int i = 0; i < 4; i++)
#pragma unroll
        for (int j = 0; j < 4; j++)
#pragma unroll
            for (int f = 0; f < 4; f++) acc[i][j][f] = 0.f;

    const int rowA = (lane & 7) + ((lane >> 3) & 1) * 8;
    const int colA = ((lane >> 4) & 1) * 8;
    const int rowB = (lane & 7) + ((lane >> 4) & 1) * 8;
    const int colB = ((lane >> 3) & 1) * 8;

    const int iters = K >> 5;
    load_stage(0, 0);
    cpa_commit();

    for (int it = 0; it < iters; ++it) {
        const int cur = it & 1;
        if (it + 1 < iters) { load_stage(cur ^ 1, (it + 1) << 5); cpa_commit(); cpa_wait<1>(); }
        else                { cpa_wait<0>(); }
        __syncthreads();

        const unsigned sb = sbase + cur*HSTAGE;
        const unsigned aA = sb + (wm*64 + rowA)*(LDK*2) + colA*2;
        const unsigned aB = sb + TILEB + (wn*32 + rowB)*(LDK*2) + colB*2;

#pragma unroll
        for (int ks = 0; ks < 2; ks++) {
            const unsigned ko = ks*32;
            unsigned bh[4][2];
#pragma unroll
            for (int p = 0; p < 2; p++) {
                unsigned r0, r1, r2, r3;
                ldm4(r0, r1, r2, r3, aB + p*16*(LDK*2) + ko);
                bh[2*p][0]=r0; bh[2*p][1]=r1; bh[2*p+1][0]=r2; bh[2*p+1][1]=r3;
            }
#pragma unroll
            for (int mt = 0; mt < 4; mt++) {
                unsigned a[4];
                ldm4(a[0], a[1], a[2], a[3], aA + mt*16*(LDK*2) + ko);
#pragma unroll
                for (int nt = 0; nt < 4; nt++)
                    mmah(acc[mt][nt], a[0],a[1],a[2],a[3], bh[nt][0], bh[nt][1]);
            }
        }
        __syncthreads();
    }

    const int lr2 = lane >> 2;
    const int lc2 = (lane & 3) << 1;
#pragma unroll
    for (int mt = 0; mt < 4; mt++)
#pragma unroll
        for (int nt = 0; nt < 4; nt++) {
#pragma unroll
            for (int hh = 0; hh < 2; hh++) {
                const int m = m0 + wm*64 + mt*16 + lr2 + hh*8;
                const int n = n0 + wn*32 + nt*8 + lc2;
                float v0 = acc[mt][nt][hh*2+0] + bias[n];
                float v1 = acc[mt][nt][hh*2+1] + bias[n+1];
                const int b = m >> 9, q = m & 511, h = n >> 7, dh = n & 127;
                const size_t idx = (((size_t)((b<<3)|h))*SEQ + q)*DHEAD + dh;
                if (mode < 2) {
                    v0 *= aux[n]; v1 *= aux[n+1];
                    __half* dst = (mode == 0) ? g_fhf : g_ftf;
                    *reinterpret_cast<unsigned*>(&dst[idx]) = packh(v0, v1);
                } else {
                    float2 o; o.x = v0; o.y = v1;
                    *reinterpret_cast<float2*>(&g_fv[idx]) = o;
                }
            }
        }
}

// ---------------- fused scores + softmax + P @ V ----------------
// pass 2 now single-pass fp16: packed buffers pA (P fp16) + pB (V fp16),
// double-buffered at 12 KB each (3072 words stride).
#define FU_RUNM  49152
#define FU_RUNS  (FU_RUNM + 512)
#define FU_MPART (FU_RUNM + 1024)
#define FU_SPART (FU_MPART + 2048)
#define FU_DSM   (FU_MPART + 4096)   // 54272

__global__ void __launch_bounds__(256, 2)
attn_fused(float* __restrict__ fr)
{
    extern __shared__ char sm[];
    const unsigned sbase = smem_u32(sm);
    unsigned* pW  = reinterpret_cast<unsigned*>(sm);
    float* run_m  = reinterpret_cast<float*>(sm + FU_RUNM);
    float* run_s  = reinterpret_cast<float*>(sm + FU_RUNS);
    float* m_part = reinterpret_cast<float*>(sm + FU_MPART);
    float* s_part = reinterpret_cast<float*>(sm + FU_SPART);

    const int tid  = threadIdx.x;
    const int lane = tid & 31;
    const int warp = tid >> 5;
    const int wm   = warp >> 2, wn = warp & 3;
    const int lr2  = lane >> 2;
    const int lc2  = (lane & 3) << 1;
    const int lc   = lane & 3;
    const int z    = blockIdx.z;
    const int m0   = blockIdx.y * 128;
    const int h    = z & 7;

    const __half* Af = g_fhf + (size_t)z*SEQ*DHEAD;
    const __half* Bf = g_ftf + (size_t)z*SEQ*DHEAD;
    float* frz = fr + (size_t)z*SEQ*SEQ;

    if (tid < 128) { run_m[tid] = -3.4e38f; run_s[tid] = 0.f; }
    __syncthreads();

    const int rowA = (lane & 7) + ((lane >> 3) & 1) * 8;
    const int colA = ((lane >> 4) & 1) * 8;
    const int rowB = (lane & 7) + ((lane >> 4) & 1) * 8;
    const int colB = ((lane >> 3) & 1) * 8;

    // ================= pass 1: scores + running row stats =================
    for (int ntile = 0; ntile < 4; ++ntile) {
        const int n0 = ntile * 128;

        auto load_stage = [&](int st, int kt) {
            const unsigned sb = sbase + st*HSTAGE;
#pragma unroll
            for (int i = 0; i < 4; i++) {
                const int idx  = tid + i*256;
                const int tile = idx >> 9;
                const int r    = (idx >> 2) & 127;
                const int c    = idx & 3;
                const __half* s = tile ? Bf : Af;
                const int rg = (tile ? n0 : m0) + r;
                cpa16s(sb + tile*TILEB + r*(LDK*2) + c*16,
                       s + (size_t)rg*DHEAD + kt + c*8);
            }
        };

        float acc[4][4][4];
#pragma unroll
        for (int i = 0; i < 4; i++)
#pragma unroll
            for (int j = 0; j < 4; j++)
#pragma unroll
                for (int f = 0; f < 4; f++) acc[i][j][f] = 0.f;

        load_stage(0, 0);
        cpa_commit();

        for (int it = 0; it < 4; ++it) {
            const int cur = it & 1;
            if (it + 1 < 4) { load_stage(cur ^ 1, (it + 1) << 5); cpa_commit(); cpa_wait<1>(); }
            else            { cpa_wait<0>(); }
            __syncthreads();

            const unsigned sb = sbase + cur*HSTAGE;
            const unsigned aA = sb + (wm*64 + rowA)*(LDK*2) + colA*2;
            const unsigned aB = sb + TILEB + (wn*32 + rowB)*(LDK*2) + colB*2;

#pragma unroll
            for (int ks = 0; ks < 2; ks++) {
                const unsigned ko = ks*32;
                unsigned bh[4][2];
#pragma unroll
                for (int p = 0; p < 2; p++) {
                    unsigned r0, r1, r2, r3;
                    ldm4(r0, r1, r2, r3, aB + p*16*(LDK*2) + ko);
                    bh[2*p][0]=r0; bh[2*p][1]=r1; bh[2*p+1][0]=r2; bh[2*p+1][1]=r3;
                }
#pragma unroll
                for (int mt = 0; mt < 4; mt++) {
                    unsigned a[4];
                    ldm4(a[0], a[1], a[2], a[3], aA + mt*16*(LDK*2) + ko);
#pragma unroll
                    for (int nt = 0; nt < 4; nt++)
                        mmah(acc[mt][nt], a[0],a[1],a[2],a[3], bh[nt][0], bh[nt][1]);
                }
            }
            __syncthreads();
        }

        // epilogue: logits -> fr + per-32col row stats via quad shuffles
#pragma unroll
        for (int mt = 0; mt < 4; mt++) {
#pragma unroll
            for (int hh = 0; hh < 2; hh++) {
                const int ml = wm*64 + mt*16 + lr2 + hh*8;
                float vv[8];
                float mx = -3.4e38f;
#pragma unroll
                for (int nt = 0; nt < 4; nt++) {
                    const int nl = wn*32 + nt*8 + lc2;
                    const size_t off = (size_t)(m0 + ml)*SEQ + n0 + nl;
                    float2 am = *reinterpret_cast<const float2*>(&g_adjm[(size_t)h*SEQ*SEQ + off]);
                    float v0 = acc[mt][nt][hh*2+0] * SCALE + am.x;
                    float v1 = acc[mt][nt][hh*2+1] * SCALE + am.y;
                    float2 o; o.x = v0; o.y = v1;
                    *reinterpret_cast<float2*>(&frz[off]) = o;
                    vv[nt*2]   = v0;
                    vv[nt*2+1] = v1;
                    mx = fmaxf(mx, fmaxf(v0, v1));
                }
                mx = fmaxf(mx, __shfl_xor_sync(0xffffffffu, mx, 1));
                mx = fmaxf(mx, __shfl_xor_sync(0xffffffffu, mx, 2));
                float s = 0.f;
#pragma unroll
                for (int j = 0; j < 8; j++) s += __expf(vv[j] - mx);
                s += __shfl_xor_sync(0xffffffffu, s, 1);
                s += __shfl_xor_sync(0xffffffffu, s, 2);
                if (lc == 0) { m_part[ml*4 + wn] = mx; s_part[ml*4 + wn] = s; }
            }
        }
        __syncthreads();

        if (tid < 128) {
            float m4 = -3.4e38f;
#pragma unroll
            for (int w = 0; w < 4; w++) m4 = fmaxf(m4, m_part[tid*4 + w]);
            float s4 = 0.f;
#pragma unroll
            for (int w = 0; w < 4; w++) s4 += s_part[tid*4 + w] * __expf(m_part[tid*4 + w] - m4);
            const float mo = run_m[tid], so = run_s[tid];
            const float mn = fmaxf(mo, m4);
            run_s[tid] = so * __expf(mo - mn) + s4 * __expf(m4 - mn);
            run_m[tid] = mn;
        }
        __syncthreads();
    }

    // ================= pass 2: softmax-apply + P @ V (fp16 single) =================
    const float* Bp = g_fv + (size_t)z*SEQ*DHEAD;
    const int arow  = tid >> 1;
    const int akoff = (tid & 1) << 3;
    const int bn    = tid & 127;
    const int bhalf = tid >> 7;

    const float mr = run_m[arow];
    const float ir = 1.f / run_s[arow];

    float fa[8], fb[8];
    auto ldg_stage = [&](int kt) {
        const float* ap = frz + (size_t)(m0 + arow)*SEQ + kt + akoff;
        float4 v0 = *reinterpret_cast<const float4*>(ap);
        float4 v1 = *reinterpret_cast<const float4*>(ap + 4);
        fa[0]=v0.x; fa[1]=v0.y; fa[2]=v0.z; fa[3]=v0.w;
        fa[4]=v1.x; fa[5]=v1.y; fa[6]=v1.z; fa[7]=v1.w;
#pragma unroll
        for (int j = 0; j < 8; j++)
            fb[j] = Bp[(size_t)(kt + 8*bhalf + j)*DHEAD + bn];
    };

    ldg_stage(0);

    float acc[4][4][4];
#pragma unroll
    for (int i = 0; i < 4; i++)
#pragma unroll
        for (int j = 0; j < 4; j++)
#pragma unroll
            for (int f = 0; f < 4; f++) acc[i][j][f] = 0.f;

    for (int it = 0; it < 32; ++it) {
        const unsigned b0 = (unsigned)(it & 1) * 3072;   // word stride per stage (12 KB)
        {
#pragma unroll
            for (int j = 0; j < 8; j++) fa[j] = __expf(fa[j] - mr) * ir;

            float* ap = frz + (size_t)(m0 + arow)*SEQ + it*16 + akoff;
            *reinterpret_cast<float4*>(ap)     = make_float4(fa[0], fa[1], fa[2], fa[3]);
            *reinterpret_cast<float4*>(ap + 4) = make_float4(fa[4], fa[5], fa[6], fa[7]);

            uint4 pa = make_uint4(packh(fa[0], fa[1]), packh(fa[2], fa[3]),
                                  packh(fa[4], fa[5]), packh(fa[6], fa[7]));
            *reinterpret_cast<uint4*>(&pW[b0 + arow*12 + (akoff >> 1)]) = pa;
            uint4 pb = make_uint4(packh(fb[0], fb[1]), packh(fb[2], fb[3]),
                                  packh(fb[4], fb[5]), packh(fb[6], fb[7]));
            *reinterpret_cast<uint4*>(&pW[b0 + 1536 + bn*12 + 4*bhalf]) = pb;
        }
        __syncthreads();

        if (it + 1 < 32) ldg_stage((it + 1) * 16);

        uint2 a0[4], a1[4], b_h[4];
#pragma unroll
        for (int mt = 0; mt < 4; mt++) {
            const int r = wm*64 + mt*16 + lr2;
            a0[mt] = *reinterpret_cast<const uint2*>(&pW[b0 + r*12 + 2*lc]);
            a1[mt] = *reinterpret_cast<const uint2*>(&pW[b0 + (r+8)*12 + 2*lc]);
        }
#pragma unroll
        for (int nt = 0; nt < 4; nt++) {
            const int c = wn*32 + nt*8 + lr2;
            b_h[nt] = *reinterpret_cast<const uint2*>(&pW[b0 + 1536 + c*12 + 2*lc]);
        }
#pragma unroll
        for (int mt = 0; mt < 4; mt++)
#pragma unroll
            for (int nt = 0; nt < 4; nt++)
                mmah(acc[mt][nt], a0[mt].x, a1[mt].x, a0[mt].y, a1[mt].y, b_h[nt].x, b_h[nt].y);
    }

    // epilogue: emit attn fp16
    const int b = z >> 3;
#pragma unroll
    for (int mt = 0; mt < 4; mt++)
#pragma unroll
        for (int nt = 0; nt < 4; nt++) {
            const int mb = m0 + wm*64 + mt*16 + lr2;
            const int nb = wn*32 + nt*8 + lc2;
#pragma unroll
            for (int hh = 0; hh < 2; hh++) {
                const size_t idx = ((size_t)(b*SEQ + mb + hh*8))*DMODEL + h*DHEAD + nb;
                *reinterpret_cast<unsigned*>(&g_atf[idx]) =
                    packh(acc[mt][nt][hh*2+0], acc[mt][nt][hh*2+1]);
            }
        }
}

// ---------------- output projection (fp16 single-pass) ----------------
__global__ void __launch_bounds__(256, 2)
out_h(const float* __restrict__ bias, float* __restrict__ Cext, int K)
{
    extern __shared__ char sm[];
    const unsigned sbase = smem_u32(sm);

    const int tid  = threadIdx.x;
    const int lane = tid & 31;
    const int warp = tid >> 5;
    const int wm   = warp >> 2, wn = warp & 3;
    const int m0   = blockIdx.y * 128;
    const int n0   = blockIdx.x * 128;

    const __half* A = g_atf;
    const __half* B = g_Wof;

    auto load_stage = [&](int st, int kt) {
        const unsigned sb = sbase + st*HSTAGE;
#pragma unroll
        for (int i = 0; i < 4; i++) {
            const int idx  = tid + i*256;
            const int tile = idx >> 9;
            const int r    = (idx >> 2) & 127;
            const int c    = idx & 3;
            const __half* s = tile ? B : A;
            const int rg = (tile ? n0 : m0) + r;
            cpa16s(sb + tile*TILEB + r*(LDK*2) + c*16,
                   s + (size_t)rg*K + kt + c*8);
        }
    };

    float acc[4][4][4];
#pragma unroll
    for (int i = 0; i < 4; i++)
#pragma unroll
        for (int j = 0; j < 4; j++)
#pragma unroll
            for (int f = 0; f < 4; f++) acc[i][j][f] = 0.f;

    const int rowA = (lane & 7) + ((lane >> 3) & 1) * 8;
    const int colA = ((lane >> 4) & 1) * 8;
    const int rowB = (lane & 7) + ((lane >> 4) & 1) * 8;
    const int colB = ((lane >> 3) & 1) * 8;

    const int iters = K >> 5;
    load_stage(0, 0);
    cpa_commit();

    for (int it = 0; it < iters; ++it) {
        const int cur = it & 1;
        if (it + 1 < iters) { load_stage(cur ^ 1, (it + 1) << 5); cpa_commit(); cpa_wait<1>(); }
        else                { cpa_wait<0>(); }
        __syncthreads();

        const unsigned sb = sbase + cur*HSTAGE;
        const unsigned aA = sb + (wm*64 + rowA)*(LDK*2) + colA*2;
        const unsigned aB = sb + TILEB + (wn*32 + rowB)*(LDK*2) + colB*2;

#pragma unroll
        for (int ks = 0; ks < 2; ks++) {
            const unsigned ko = ks*32;
            unsigned bh[4][2];
#pragma unroll
            for (int p = 0; p < 2; p++) {
                unsigned r0, r1, r2, r3;
                ldm4(r0, r1, r2, r3, aB + p*16*(LDK*2) + ko);
                bh[2*p][0]=r0; bh[2*p][1]=r1; bh[2*p+1][0]=r2; bh[2*p+1][1]=r3;
            }
#pragma unroll
            for (int mt = 0; mt < 4; mt++) {
                unsigned a[4];
                ldm4(a[0], a[1], a[2], a[3], aA + mt*16*(LDK*2) + ko);
#pragma unroll
                for (int nt = 0; nt < 4; nt++)
                    mmah(acc[mt][nt], a[0],a[1],a[2],a[3], bh[nt][0], bh[nt][1]);
            }
        }
        __syncthreads();
    }

    const int lr2 = lane >> 2;
    const int lc2 = (lane & 3) << 1;
#pragma unroll
    for (int mt = 0; mt < 4; mt++)
#pragma unroll
        for (int nt = 0; nt < 4; nt++) {
#pragma unroll
            for (int hh = 0; hh < 2; hh++) {
                const int m = m0 + wm*64 + mt*16 + lr2 + hh*8;
                const int n = n0 + wn*32 + nt*8 + lc2;
                float2 o;
                o.x = acc[mt][nt][hh*2+0] + bias[n];
                o.y = acc[mt][nt][hh*2+1] + bias[n+1];
                *reinterpret_cast<float2*>(&Cext[(size_t)m*DMODEL + n]) = o;
            }
        }
}

// ---------------- launch ----------------
extern "C" void kernel_launch(void* const* d_in, const int* in_sizes, int n_in,
                              void* d_out, int out_size)
{
    const float* x_q      = (const float*)d_in[0];
    const float* x_kv     = (const float*)d_in[1];
    const float* W_head_w = (const float*)d_in[2];
    const float* W_head_b = (const float*)d_in[3];
    const float* W_v_w    = (const float*)d_in[4];
    const float* W_v_b    = (const float*)d_in[5];
    const float* W_out_w  = (const float*)d_in[6];
    const float* W_out_b  = (const float*)d_in[7];
    const float* rel_emb  = (const float*)d_in[8];
    const float* col_head = (const float*)d_in[9];
    const float* col_tail = (const float*)d_in[10];

    float* out_x  = (float*)d_out;                          // [32,512,1024]
    float* out_fr = out_x + (size_t)BATCH*SEQ*DMODEL;       // [256,512,512]

    static bool attr_done = false;
    if (!attr_done) {
        cudaFuncSetAttribute(proj_h,     cudaFuncAttributeMaxDynamicSharedMemorySize, HG_DSM);
        cudaFuncSetAttribute(attn_fused, cudaFuncAttributeMaxDynamicSharedMemorySize, FU_DSM);
        cudaFuncSetAttribute(out_h,      cudaFuncAttributeMaxDynamicSharedMemorySize, HG_DSM);
        attr_done = true;
    }

    // 1) conversions (all fp16)
    cvt_x<<<dim3(2048, 2), 256>>>(x_q, x_kv);
    cvt_w<<<dim3(512, 3),  256>>>(W_head_w, W_v_w, W_out_w);

    // 2) learned column topology mask
    adj_kernel<<<dim3(SEQ, HEADS), 128>>>(col_head, col_tail);

    // 3) projections (fp16 single-pass, merged)
    proj_h<<<dim3(8, 128, 3), 256, HG_DSM>>>(W_head_b, W_v_b, rel_emb, DMODEL);

    // 4) fused scores + softmax + P @ V (fp16 single) -> fr final probs, attn fp16
    attn_fused<<<dim3(1, 4, BHS), 256, FU_DSM>>>(out_fr);

    // 5) output projection (fp16 single-pass)
    out_h<<<dim3(8, 128), 256, HG_DSM>>>(W_out_b, out_x, DMODEL);
}

// round 14
// speedup vs baseline: 2.0038x; 1.0992x over previous
#include <cuda_runtime.h>
#include <cuda_bf16.h>
#include <cuda_fp16.h>
#include <math.h>
#include <cstdint>

#define BATCH   32
#define HEADS   8
#define SEQ     512
#define DMODEL  1024
#define DHEAD   128
#define DCOL    18
#define BHS     (BATCH*HEADS)   // 256
#define BSD     ((size_t)BATCH*SEQ*DMODEL)   // 16777216
#define SCALE   0.08838834764831845f

// ---------------- scratch (static device globals; no allocation) ----------------
__device__ __align__(256) __half        g_xqf[BSD], g_xkf[BSD];          // fp16 inputs
__device__ __align__(256) __half        g_Whf[DMODEL*DMODEL], g_Wvf[DMODEL*DMODEL];
__device__ __align__(256) __half        g_Wof[DMODEL*DMODEL];
__device__ __align__(256) __half        g_fhf[BSD], g_ftf[BSD];          // f_head/f_tail fp16
__device__ __align__(256) float         g_fv [BSD];                      // f_v fp32
__device__ __align__(256) __half        g_atf[BSD];                      // attn fp16
__device__ __align__(256) float         g_adjm[(size_t)HEADS*SEQ*SEQ];

// ---------------- small helpers ----------------
__device__ __forceinline__ unsigned packh(float f0, float f1) {    // f0 -> low half
    unsigned d;
    asm("cvt.rn.f16x2.f32 %0, %1, %2;" : "=r"(d) : "f"(f1), "f"(f0));
    return d;
}

__device__ __forceinline__ unsigned smem_u32(const void* p) {
    unsigned a;
    asm("{ .reg .u64 t; cvta.to.shared.u64 t, %1; cvt.u32.u64 %0, t; }" : "=r"(a) : "l"(p));
    return a;
}
__device__ __forceinline__ void cpa16s(unsigned dst, const void* src) {
    asm volatile("cp.async.ca.shared.global [%0], [%1], 16;" :: "r"(dst), "l"(src));
}
__device__ __forceinline__ void cpa_commit() { asm volatile("cp.async.commit_group;"); }
template<int N>
__device__ __forceinline__ void cpa_wait() { asm volatile("cp.async.wait_group %0;" :: "n"(N)); }

__device__ __forceinline__ void ldm4(unsigned& r0, unsigned& r1, unsigned& r2, unsigned& r3,
                                     unsigned addr) {
    asm volatile("ldmatrix.sync.aligned.m8n8.x4.shared.b16 {%0,%1,%2,%3}, [%4];"
                 : "=r"(r0), "=r"(r1), "=r"(r2), "=r"(r3) : "r"(addr));
}

__device__ __forceinline__ void mmah(float* c, unsigned a0, unsigned a1, unsigned a2,
                                     unsigned a3, unsigned b0, unsigned b1) {
    asm volatile(
        "mma.sync.aligned.m16n8k16.row.col.f32.f16.f16.f32 "
        "{%0,%1,%2,%3}, {%4,%5,%6,%7}, {%8,%9}, {%0,%1,%2,%3};\n"
        : "+f"(c[0]), "+f"(c[1]), "+f"(c[2]), "+f"(c[3])
        : "r"(a0), "r"(a1), "r"(a2), "r"(a3), "r"(b0), "r"(b1));
}

// ---------------- conversions (all fp16) ----------------
__global__ void cvt_x(const float* __restrict__ xq, const float* __restrict__ xkv)
{
    const int sel = blockIdx.y;
    const float4* s4 = reinterpret_cast<const float4*>(sel ? xkv : xq);
    uint2* out = reinterpret_cast<uint2*>(sel ? g_xkf : g_xqf);
    const int n4 = (int)(BSD/4);
    for (int i = blockIdx.x * blockDim.x + threadIdx.x; i < n4; i += gridDim.x * blockDim.x) {
        float4 v = s4[i];
        out[i] = make_uint2(packh(v.x, v.y), packh(v.z, v.w));
    }
}

__global__ void cvt_w(const float* __restrict__ wh, const float* __restrict__ wv,
                      const float* __restrict__ wo)
{
    const int sel = blockIdx.y;
    const float4* s4 = reinterpret_cast<const float4*>(sel == 0 ? wh : sel == 1 ? wv : wo);
    uint2* out = reinterpret_cast<uint2*>(sel == 0 ? g_Whf : sel == 1 ? g_Wvf : g_Wof);
    const int n4 = DMODEL*DMODEL/4;
    for (int i = blockIdx.x * blockDim.x + threadIdx.x; i < n4; i += gridDim.x * blockDim.x) {
        float4 v = s4[i];
        out[i] = make_uint2(packh(v.x, v.y), packh(v.z, v.w));
    }
}

// ---------------- adjacency: softmax(col_head @ col_tail^T, diag=0) ----------------
__global__ void adj_kernel(const float* __restrict__ col_head,
                           const float* __restrict__ col_tail)
{
    const int q = blockIdx.x;
    const int h = blockIdx.y;
    const int t = threadIdx.x;                 // 128 threads
    __shared__ float ch[DCOL];
    __shared__ float sred[4];

    if (t < DCOL) ch[t] = col_head[((size_t)h*SEQ + q)*DCOL + t];
    __syncthreads();

    float l[4];
#pragma unroll
    for (int i = 0; i < 4; i++) {
        const int k = t + i*128;
        const float* ct = col_tail + ((size_t)h*SEQ + k)*DCOL;
        float s = 0.f;
#pragma unroll
        for (int c = 0; c < DCOL; c++) s += ch[c]*ct[c];
        l[i] = (k == q) ? 0.f : s;
    }

    float mx = fmaxf(fmaxf(l[0],l[1]), fmaxf(l[2],l[3]));
#pragma unroll
    for (int o = 16; o; o >>= 1) mx = fmaxf(mx, __shfl_xor_sync(0xffffffffu, mx, o));
    if ((t & 31) == 0) sred[t >> 5] = mx;
    __syncthreads();
    mx = fmaxf(fmaxf(sred[0],sred[1]), fmaxf(sred[2],sred[3]));
    __syncthreads();

    float e[4]; float sum = 0.f;
#pragma unroll
    for (int i = 0; i < 4; i++) { e[i] = expf(l[i]-mx); sum += e[i]; }
#pragma unroll
    for (int o = 16; o; o >>= 1) sum += __shfl_xor_sync(0xffffffffu, sum, o);
    if ((t & 31) == 0) sred[t >> 5] = sum;
    __syncthreads();
    sum = sred[0]+sred[1]+sred[2]+sred[3];
    const float inv = 1.f/sum;

    float* dst = g_adjm + ((size_t)h*SEQ + q)*SEQ;
#pragma unroll
    for (int i = 0; i < 4; i++) {
        const int k = t + i*128;
        dst[k] = (1.f - e[i]*inv) * (-10000.f);
    }
}

// ---------------- tile constants ----------------
#define LDK     40                  // padded smem row (16b elems), 80 B
#define TILEB   (128*LDK*2)         // 10240 B
#define HSTAGE  (2*TILEB)           // fp16 single: A + B
#define HG_DSM  (2*HSTAGE)          // 40960

// ---------------- fp16 single-pass projections: blockIdx.z = mode (0,1,2) ----------------
__global__ void __launch_bounds__(256, 2)
proj_h(const float* __restrict__ biasH, const float* __restrict__ biasV,
       const float* __restrict__ aux, int K)
{
    extern __shared__ char sm[];
    const unsigned sbase = smem_u32(sm);

    const int tid  = threadIdx.x;
    const int lane = tid & 31;
    const int warp = tid >> 5;
    const int wm   = warp >> 2, wn = warp & 3;
    const int mode = blockIdx.z;
    const int m0   = blockIdx.y * 128;
    const int n0   = blockIdx.x * 128;

    const __half* A = (mode == 0) ? g_xqf : g_xkf;
    const __half* B = (mode == 2) ? g_Wvf : g_Whf;
    const float* bias = (mode == 2) ? biasV : biasH;

    auto load_stage = [&](int st, int kt) {
        const unsigned sb = sbase + st*HSTAGE;
#pragma unroll
        for (int i = 0; i < 4; i++) {
            const int idx  = tid + i*256;
            const int tile = idx >> 9;
            const int r    = (idx >> 2) & 127;
            const int c    = idx & 3;
            const __half* s = tile ? B : A;
            const int rg = (tile ? n0 : m0) + r;
            cpa16s(sb + tile*TILEB + r*(LDK*2) + c*16,
                   s + (size_t)rg*K + kt + c*8);
        }
    };

    float acc[4][4][4];
#pragma unroll
    for (int i = 0; i < 4; i++)
#pragma unroll
        for (int j = 0; j < 4; j++)
#pragma unroll
            for (int f = 0; f < 4; f++) acc[i][j][f] = 0.f;

    const int rowA = (lane & 7) + ((lane >> 3) & 1) * 8;
    const int colA = ((lane >> 4) & 1) * 8;
    const int rowB = (lane & 7) + ((lane >> 4) & 1) * 8;
    const int colB = ((lane >> 3) & 1) * 8;

    const int iters = K >> 5;
    load_stage(0, 0);
    cpa_commit();

    for (int it = 0; it < iters; ++it) {
        const int cur = it & 1;
        if (it + 1 < iters) { load_stage(cur ^ 1, (it + 1) << 5); cpa_commit(); cpa_wait<1>(); }
        else                { cpa_wait<0>(); }
        __syncthreads();

        const unsigned sb = sbase + cur*HSTAGE;
        const unsigned aA = sb + (wm*64 + rowA)*(LDK*2) + colA*2;
        const unsigned aB = sb + TILEB + (wn*32 + rowB)*(LDK*2) + colB*2;

#pragma unroll
        for (int ks = 0; ks < 2; ks++) {
            const unsigned ko = ks*32;
            unsigned bh[4][2];
#pragma unroll
            for (int p = 0; p < 2; p++) {
                unsigned r0, r1, r2, r3;
                ldm4(r0, r1, r2, r3, aB + p*16*(LDK*2) + ko);
                bh[2*p][0]=r0; bh[2*p][1]=r1; bh[2*p+1][0]=r2; bh[2*p+1][1]=r3;
            }
#pragma unroll
            for (int mt = 0; mt < 4; mt++) {
                unsigned a[4];
                ldm4(a[0], a[1], a[2], a[3], aA + mt*16*(LDK*2) + ko);
#pragma unroll
                for (int nt = 0; nt < 4; nt++)
                    mmah(acc[mt][nt], a[0],a[1],a[2],a[3], bh[nt][0], bh[nt][1]);
            }
        }
        __syncthreads();
    }

    const int lr2 = lane >> 2;
    const int lc2 = (lane & 3) << 1;
#pragma unroll
    for (int mt = 0; mt < 4; mt++)
#pragma unroll
        for (int nt = 0; nt < 4; nt++) {
#pragma unroll
            for (int hh = 0; hh < 2; hh++) {
                const int m = m0 + wm*64 + mt*16 + lr2 + hh*8;
                const int n = n0 + wn*32 + nt*8 + lc2;
                float v0 = acc[mt][nt][hh*2+0] + bias[n];
                float v1 = acc[mt][nt][hh*2+1] + bias[n+1];
                const int b = m >> 9, q = m & 511, h = n >> 7, dh = n & 127;
                const size_t idx = (((size_t)((b<<3)|h))*SEQ + q)*DHEAD + dh;
                if (mode < 2) {
                    v0 *= aux[n]; v1 *= aux[n+1];
                    __half* dst = (mode == 0) ? g_fhf : g_ftf;
                    *reinterpret_cast<unsigned*>(&dst[idx]) = packh(v0, v1);
                } else {
                    float2 o; o.x = v0; o.y = v1;
                    *reinterpret_cast<float2*>(&g_fv[idx]) = o;
                }
            }
        }
}

// ---------------- fused scores + softmax + P @ V ----------------
// pass 1 writes u = exp(l - tile_max) to fr and per-tile (max, sum).
// pass 2 rescales by fac[t] = exp(tm[t]-m)/den (ONE multiply, no exp),
// writes final P in place, and runs P @ V in single fp16.
#define FU_TM    49152                 // tm:  [4][128] fp32 (2 KB)
#define FU_TS    (FU_TM + 2048)        // ts:  [4][128] fp32 (2 KB)
#define FU_MP    (FU_TM + 4096)        // m_part: [128][4]  (2 KB)
#define FU_SP    (FU_TM + 6144)        // s_part: [128][4]  (2 KB)
#define FU_FAC   (FU_TM + 8192)        // fac: [4][128]     (2 KB)
#define FU_DSM   (FU_TM + 10240)       // 59392

__global__ void __launch_bounds__(256, 2)
attn_fused(float* __restrict__ fr)
{
    extern __shared__ char sm[];
    const unsigned sbase = smem_u32(sm);
    unsigned* pW  = reinterpret_cast<unsigned*>(sm);
    float* tm     = reinterpret_cast<float*>(sm + FU_TM);
    float* ts     = reinterpret_cast<float*>(sm + FU_TS);
    float* m_part = reinterpret_cast<float*>(sm + FU_MP);
    float* s_part = reinterpret_cast<float*>(sm + FU_SP);
    float* fac    = reinterpret_cast<float*>(sm + FU_FAC);

    const int tid  = threadIdx.x;
    const int lane = tid & 31;
    const int warp = tid >> 5;
    const int wm   = warp >> 2, wn = warp & 3;
    const int lr2  = lane >> 2;
    const int lc2  = (lane & 3) << 1;
    const int lc   = lane & 3;
    const int z    = blockIdx.z;
    const int m0   = blockIdx.y * 128;
    const int h    = z & 7;

    const __half* Af = g_fhf + (size_t)z*SEQ*DHEAD;
    const __half* Bf = g_ftf + (size_t)z*SEQ*DHEAD;
    float* frz = fr + (size_t)z*SEQ*SEQ;

    const int rowA = (lane & 7) + ((lane >> 3) & 1) * 8;
    const int colA = ((lane >> 4) & 1) * 8;
    const int rowB = (lane & 7) + ((lane >> 4) & 1) * 8;
    const int colB = ((lane >> 3) & 1) * 8;

    // ================= pass 1: scores -> u = exp(l - tile_max), per-tile stats =================
    for (int ntile = 0; ntile < 4; ++ntile) {
        const int n0 = ntile * 128;

        auto load_stage = [&](int st, int kt) {
            const unsigned sb = sbase + st*HSTAGE;
#pragma unroll
            for (int i = 0; i < 4; i++) {
                const int idx  = tid + i*256;
                const int tile = idx >> 9;
                const int r    = (idx >> 2) & 127;
                const int c    = idx & 3;
                const __half* s = tile ? Bf : Af;
                const int rg = (tile ? n0 : m0) + r;
                cpa16s(sb + tile*TILEB + r*(LDK*2) + c*16,
                       s + (size_t)rg*DHEAD + kt + c*8);
            }
        };

        float acc[4][4][4];
#pragma unroll
        for (int i = 0; i < 4; i++)
#pragma unroll
            for (int j = 0; j < 4; j++)
#pragma unroll
                for (int f = 0; f < 4; f++) acc[i][j][f] = 0.f;

        load_stage(0, 0);
        cpa_commit();

        for (int it = 0; it < 4; ++it) {
            const int cur = it & 1;
            if (it + 1 < 4) { load_stage(cur ^ 1, (it + 1) << 5); cpa_commit(); cpa_wait<1>(); }
            else            { cpa_wait<0>(); }
            __syncthreads();

            const unsigned sb = sbase + cur*HSTAGE;
            const unsigned aA = sb + (wm*64 + rowA)*(LDK*2) + colA*2;
            const unsigned aB = sb + TILEB + (wn*32 + rowB)*(LDK*2) + colB*2;

#pragma unroll
            for (int ks = 0; ks < 2; ks++) {
                const unsigned ko = ks*32;
                unsigned bh[4][2];
#pragma unroll
                for (int p = 0; p < 2; p++) {
                    unsigned r0, r1, r2, r3;
                    ldm4(r0, r1, r2, r3, aB + p*16*(LDK*2) + ko);
                    bh[2*p][0]=r0; bh[2*p][1]=r1; bh[2*p+1][0]=r2; bh[2*p+1][1]=r3;
                }
#pragma unroll
                for (int mt = 0; mt < 4; mt++) {
                    unsigned a[4];
                    ldm4(a[0], a[1], a[2], a[3], aA + mt*16*(LDK*2) + ko);
#pragma unroll
                    for (int nt = 0; nt < 4; nt++)
                        mmah(acc[mt][nt], a[0],a[1],a[2],a[3], bh[nt][0], bh[nt][1]);
                }
            }
            __syncthreads();
        }

        // --- epilogue A: transform acc -> logits (in place), per-warp 32-col row max ---
#pragma unroll
        for (int mt = 0; mt < 4; mt++) {
#pragma unroll
            for (int hh = 0; hh < 2; hh++) {
                const int ml = wm*64 + mt*16 + lr2 + hh*8;
                float mx = -3.4e38f;
#pragma unroll
                for (int nt = 0; nt < 4; nt++) {
                    const int nl = wn*32 + nt*8 + lc2;
                    const size_t off = (size_t)(m0 + ml)*SEQ + n0 + nl;
                    float2 am = *reinterpret_cast<const float2*>(&g_adjm[(size_t)h*SEQ*SEQ + off]);
                    float v0 = acc[mt][nt][hh*2+0] * SCALE + am.x;
                    float v1 = acc[mt][nt][hh*2+1] * SCALE + am.y;
                    acc[mt][nt][hh*2+0] = v0;
                    acc[mt][nt][hh*2+1] = v1;
                    mx = fmaxf(mx, fmaxf(v0, v1));
                }
                mx = fmaxf(mx, __shfl_xor_sync(0xffffffffu, mx, 1));
                mx = fmaxf(mx, __shfl_xor_sync(0xffffffffu, mx, 2));
                if (lc == 0) m_part[ml*4 + wn] = mx;
            }
        }
        __syncthreads();

        if (tid < 128) {
            float m4 = fmaxf(fmaxf(m_part[tid*4+0], m_part[tid*4+1]),
                             fmaxf(m_part[tid*4+2], m_part[tid*4+3]));
            tm[ntile*128 + tid] = m4;
        }
        __syncthreads();

        // --- epilogue B: u = exp(l - tile_max) -> fr, per-warp partial sums ---
#pragma unroll
        for (int mt = 0; mt < 4; mt++) {
#pragma unroll
            for (int hh = 0; hh < 2; hh++) {
                const int ml = wm*64 + mt*16 + lr2 + hh*8;
                const float tmr = tm[ntile*128 + ml];
                float s = 0.f;
#pragma unroll
                for (int nt = 0; nt < 4; nt++) {
                    const int nl = wn*32 + nt*8 + lc2;
                    const size_t off = (size_t)(m0 + ml)*SEQ + n0 + nl;
                    float u0 = __expf(acc[mt][nt][hh*2+0] - tmr);
                    float u1 = __expf(acc[mt][nt][hh*2+1] - tmr);
                    float2 o; o.x = u0; o.y = u1;
                    *reinterpret_cast<float2*>(&frz[off]) = o;
                    s += u0 + u1;
                }
                s += __shfl_xor_sync(0xffffffffu, s, 1);
                s += __shfl_xor_sync(0xffffffffu, s, 2);
                if (lc == 0) s_part[ml*4 + wn] = s;
            }
        }
        __syncthreads();

        if (tid < 128)
            ts[ntile*128 + tid] = s_part[tid*4+0] + s_part[tid*4+1]
                                + s_part[tid*4+2] + s_part[tid*4+3];
        __syncthreads();
    }

    // ---- per-row global stats -> fac[t] = exp(tm[t]-m)/den ----
    if (tid < 128) {
        float mA = tm[tid], mB = tm[128 + tid], mC = tm[256 + tid], mD = tm[384 + tid];
        float m  = fmaxf(fmaxf(mA, mB), fmaxf(mC, mD));
        float eA = __expf(mA - m), eB = __expf(mB - m);
        float eC = __expf(mC - m), eD = __expf(mD - m);
        float den = ts[tid]*eA + ts[128+tid]*eB + ts[256+tid]*eC + ts[384+tid]*eD;
        float iden = 1.f / den;
        fac[tid]       = eA * iden;
        fac[128 + tid] = eB * iden;
        fac[256 + tid] = eC * iden;
        fac[384 + tid] = eD * iden;
    }
    __syncthreads();

    // ================= pass 2: rescale + P @ V (fp16 single, no exp) =================
    const float* Bp = g_fv + (size_t)z*SEQ*DHEAD;
    const int arow  = tid >> 1;
    const int akoff = (tid & 1) << 3;
    const int bn    = tid & 127;
    const int bhalf = tid >> 7;

    float fa[8], fb[8];
    auto ldg_stage = [&](int kt) {
        const float* ap = frz + (size_t)(m0 + arow)*SEQ + kt + akoff;
        float4 v0 = *reinterpret_cast<const float4*>(ap);
        float4 v1 = *reinterpret_cast<const float4*>(ap + 4);
        fa[0]=v0.x; fa[1]=v0.y; fa[2]=v0.z; fa[3]=v0.w;
        fa[4]=v1.x; fa[5]=v1.y; fa[6]=v1.z; fa[7]=v1.w;
#pragma unroll
        for (int j = 0; j < 8; j++)
            fb[j] = Bp[(size_t)(kt + 8*bhalf + j)*DHEAD + bn];
    };

    ldg_stage(0);

    float acc[4][4][4];
#pragma unroll
    for (int i = 0; i < 4; i++)
#pragma unroll
        for (int j = 0; j < 4; j++)
#pragma unroll
            for (int f = 0; f < 4; f++) acc[i][j][f] = 0.f;

    for (int it = 0; it < 32; ++it) {
        const unsigned b0 = (unsigned)(it & 1) * 3072;   // word stride per stage (12 KB)
        {
            const float fct = fac[(it >> 3)*128 + arow];   // ntile = it/8
#pragma unroll
            for (int j = 0; j < 8; j++) fa[j] *= fct;

            float* ap = frz + (size_t)(m0 + arow)*SEQ + it*16 + akoff;
            *reinterpret_cast<float4*>(ap)     = make_float4(fa[0], fa[1], fa[2], fa[3]);
            *reinterpret_cast<float4*>(ap + 4) = make_float4(fa[4], fa[5], fa[6], fa[7]);

            uint4 pa = make_uint4(packh(fa[0], fa[1]), packh(fa[2], fa[3]),
                                  packh(fa[4], fa[5]), packh(fa[6], fa[7]));
            *reinterpret_cast<uint4*>(&pW[b0 + arow*12 + (akoff >> 1)]) = pa;
            uint4 pb = make_uint4(packh(fb[0], fb[1]), packh(fb[2], fb[3]),
                                  packh(fb[4], fb[5]), packh(fb[6], fb[7]));
            *reinterpret_cast<uint4*>(&pW[b0 + 1536 + bn*12 + 4*bhalf]) = pb;
        }
        __syncthreads();

        if (it + 1 < 32) ldg_stage((it + 1) * 16);

        uint2 a0[4], a1[4], b_h[4];
#pragma unroll
        for (int mt = 0; mt < 4; mt++) {
            const int r = wm*64 + mt*16 + lr2;
            a0[mt] = *reinterpret_cast<const uint2*>(&pW[b0 + r*12 + 2*lc]);
            a1[mt] = *reinterpret_cast<const uint2*>(&pW[b0 + (r+8)*12 + 2*lc]);
        }
#pragma unroll
        for (int nt = 0; nt < 4; nt++) {
            const int c = wn*32 + nt*8 + lr2;
            b_h[nt] = *reinterpret_cast<const uint2*>(&pW[b0 + 1536 + c*12 + 2*lc]);
        }
#pragma unroll
        for (int mt = 0; mt < 4; mt++)
#pragma unroll
            for (int nt = 0; nt < 4; nt++)
                mmah(acc[mt][nt], a0[mt].x, a1[mt].x, a0[mt].y, a1[mt].y, b_h[nt].x, b_h[nt].y);
    }

    // epilogue: emit attn fp16
    const int b = z >> 3;
#pragma unroll
    for (int mt = 0; mt < 4; mt++)
#pragma unroll
        for (int nt = 0; nt < 4; nt++) {
            const int mb = m0 + wm*64 + mt*16 + lr2;
            const int nb = wn*32 + nt*8 + lc2;
#pragma unroll
            for (int hh = 0; hh < 2; hh++) {
                const size_t idx = ((size_t)(b*SEQ + mb + hh*8))*DMODEL + h*DHEAD + nb;
                *reinterpret_cast<unsigned*>(&g_atf[idx]) =
                    packh(acc[mt][nt][hh*2+0], acc[mt][nt][hh*2+1]);
            }
        }
}

// ---------------- output projection (fp16 single-pass) ----------------
__global__ void __launch_bounds__(256, 2)
out_h(const float* __restrict__ bias, float* __restrict__ Cext, int K)
{
    extern __shared__ char sm[];
    const unsigned sbase = smem_u32(sm);

    const int tid  = threadIdx.x;
    const int lane = tid & 31;
    const int warp = tid >> 5;
    const int wm   = warp >> 2, wn = warp & 3;
    const int m0   = blockIdx.y * 128;
    const int n0   = blockIdx.x * 128;

    const __half* A = g_atf;
    const __half* B = g_Wof;

    auto load_stage = [&](int st, int kt) {
        const unsigned sb = sbase + st*HSTAGE;
#pragma unroll
        for (int i = 0; i < 4; i++) {
            const int idx  = tid + i*256;
            const int tile = idx >> 9;
            const int r    = (idx >> 2) & 127;
            const int c    = idx & 3;
            const __half* s = tile ? B : A;
            const int rg = (tile ? n0 : m0) + r;
            cpa16s(sb + tile*TILEB + r*(LDK*2) + c*16,
                   s + (size_t)rg*K + kt + c*8);
        }
    };

    float acc[4][4][4];
#pragma unroll
    for (int i = 0; i < 4; i++)
#pragma unroll
        for (int j = 0; j < 4; j++)
#pragma unroll
            for (int f = 0; f < 4; f++) acc[i][j][f] = 0.f;

    const int rowA = (lane & 7) + ((lane >> 3) & 1) * 8;
    const int colA = ((lane >> 4) & 1) * 8;
    const int rowB = (lane & 7) + ((lane >> 4) & 1) * 8;
    const int colB = ((lane >> 3) & 1) * 8;

    const int iters = K >> 5;
    load_stage(0, 0);
    cpa_commit();

    for (int it = 0; it < iters; ++it) {
        const int cur = it & 1;
        if (it + 1 < iters) { load_stage(cur ^ 1, (it + 1) << 5); cpa_commit(); cpa_wait<1>(); }
        else                { cpa_wait<0>(); }
        __syncthreads();

        const unsigned sb = sbase + cur*HSTAGE;
        const unsigned aA = sb + (wm*64 + rowA)*(LDK*2) + colA*2;
        const unsigned aB = sb + TILEB + (wn*32 + rowB)*(LDK*2) + colB*2;

#pragma unroll
        for (int ks = 0; ks < 2; ks++) {
            const unsigned ko = ks*32;
            unsigned bh[4][2];
#pragma unroll
            for (int p = 0; p < 2; p++) {
                unsigned r0, r1, r2, r3;
                ldm4(r0, r1, r2, r3, aB + p*16*(LDK*2) + ko);
                bh[2*p][0]=r0; bh[2*p][1]=r1; bh[2*p+1][0]=r2; bh[2*p+1][1]=r3;
            }
#pragma unroll
            for (int mt = 0; mt < 4; mt++) {
                unsigned a[4];
                ldm4(a[0], a[1], a[2], a[3], aA + mt*16*(LDK*2) + ko);
#pragma unroll
                for (int nt = 0; nt < 4; nt++)
                    mmah(acc[mt][nt], a[0],a[1],a[2],a[3], bh[nt][0], bh[nt][1]);
            }
        }
        __syncthreads();
    }

    const int lr2 = lane >> 2;
    const int lc2 = (lane & 3) << 1;
#pragma unroll
    for (int mt = 0; mt < 4; mt++)
#pragma unroll
        for (int nt = 0; nt < 4; nt++) {
#pragma unroll
            for (int hh = 0; hh < 2; hh++) {
                const int m = m0 + wm*64 + mt*16 + lr2 + hh*8;
                const int n = n0 + wn*32 + nt*8 + lc2;
                float2 o;
                o.x = acc[mt][nt][hh*2+0] + bias[n];
                o.y = acc[mt][nt][hh*2+1] + bias[n+1];
                *reinterpret_cast<float2*>(&Cext[(size_t)m*DMODEL + n]) = o;
            }
        }
}

// ---------------- launch ----------------
extern "C" void kernel_launch(void* const* d_in, const int* in_sizes, int n_in,
                              void* d_out, int out_size)
{
    const float* x_q      = (const float*)d_in[0];
    const float* x_kv     = (const float*)d_in[1];
    const float* W_head_w = (const float*)d_in[2];
    const float* W_head_b = (const float*)d_in[3];
    const float* W_v_w    = (const float*)d_in[4];
    const float* W_v_b    = (const float*)d_in[5];
    const float* W_out_w  = (const float*)d_in[6];
    const float* W_out_b  = (const float*)d_in[7];
    const float* rel_emb  = (const float*)d_in[8];
    const float* col_head = (const float*)d_in[9];
    const float* col_tail = (const float*)d_in[10];

    float* out_x  = (float*)d_out;                          // [32,512,1024]
    float* out_fr = out_x + (size_t)BATCH*SEQ*DMODEL;       // [256,512,512]

    static bool attr_done = false;
    if (!attr_done) {
        cudaFuncSetAttribute(proj_h,     cudaFuncAttributeMaxDynamicSharedMemorySize, HG_DSM);
        cudaFuncSetAttribute(attn_fused, cudaFuncAttributeMaxDynamicSharedMemorySize, FU_DSM);
        cudaFuncSetAttribute(out_h,      cudaFuncAttributeMaxDynamicSharedMemorySize, HG_DSM);
        attr_done = true;
    }

    // 1) conversions (all fp16)
    cvt_x<<<dim3(2048, 2), 256>>>(x_q, x_kv);
    cvt_w<<<dim3(512, 3),  256>>>(W_head_w, W_v_w, W_out_w);

    // 2) learned column topology mask
    adj_kernel<<<dim3(SEQ, HEADS), 128>>>(col_head, col_tail);

    // 3) projections (fp16 single-pass, merged)
    proj_h<<<dim3(8, 128, 3), 256, HG_DSM>>>(W_head_b, W_v_b, rel_emb, DMODEL);

    // 4) fused scores + softmax + P @ V -> fr final probs, attn fp16
    attn_fused<<<dim3(1, 4, BHS), 256, FU_DSM>>>(out_fr);

    // 5) output projection (fp16 single-pass)
    out_h<<<dim3(8, 128), 256, HG_DSM>>>(W_out_b, out_x, DMODEL);
}

// round 15
// speedup vs baseline: 2.0761x; 1.0361x over previous
#include <cuda_runtime.h>
#include <cuda_bf16.h>
#include <cuda_fp16.h>
#include <math.h>
#include <cstdint>

#define BATCH   32
#define HEADS   8
#define SEQ     512
#define DMODEL  1024
#define DHEAD   128
#define DCOL    18
#define BHS     (BATCH*HEADS)   // 256
#define BSD     ((size_t)BATCH*SEQ*DMODEL)   // 16777216
#define SCALE   0.08838834764831845f

// ---------------- scratch (static device globals; no allocation) ----------------
__device__ __align__(256) __half        g_xqf[BSD], g_xkf[BSD];          // fp16 inputs
__device__ __align__(256) __half        g_Whf[DMODEL*DMODEL], g_Wvf[DMODEL*DMODEL];
__device__ __align__(256) __half        g_Wof[DMODEL*DMODEL];
__device__ __align__(256) __half        g_fhf[BSD], g_ftf[BSD];          // f_head/f_tail fp16
__device__ __align__(256) float         g_fv [BSD];                      // f_v fp32
__device__ __align__(256) __half        g_atf[BSD];                      // attn fp16
__device__ __align__(256) float         g_adjm[(size_t)HEADS*SEQ*SEQ];
__device__ __align__(256) __half        g_uf [(size_t)BHS*SEQ*SEQ];      // u = exp(l - tm) fp16

// ---------------- small helpers ----------------
__device__ __forceinline__ unsigned packh(float f0, float f1) {    // f0 -> low half
    unsigned d;
    asm("cvt.rn.f16x2.f32 %0, %1, %2;" : "=r"(d) : "f"(f1), "f"(f0));
    return d;
}
__device__ __forceinline__ float2 h2f2(unsigned p) {
    return __half22float2(*reinterpret_cast<__half2*>(&p));
}

__device__ __forceinline__ unsigned smem_u32(const void* p) {
    unsigned a;
    asm("{ .reg .u64 t; cvta.to.shared.u64 t, %1; cvt.u32.u64 %0, t; }" : "=r"(a) : "l"(p));
    return a;
}
__device__ __forceinline__ void cpa16s(unsigned dst, const void* src) {
    asm volatile("cp.async.ca.shared.global [%0], [%1], 16;" :: "r"(dst), "l"(src));
}
__device__ __forceinline__ void cpa_commit() { asm volatile("cp.async.commit_group;"); }
template<int N>
__device__ __forceinline__ void cpa_wait() { asm volatile("cp.async.wait_group %0;" :: "n"(N)); }

__device__ __forceinline__ void ldm4(unsigned& r0, unsigned& r1, unsigned& r2, unsigned& r3,
                                     unsigned addr) {
    asm volatile("ldmatrix.sync.aligned.m8n8.x4.shared.b16 {%0,%1,%2,%3}, [%4];"
                 : "=r"(r0), "=r"(r1), "=r"(r2), "=r"(r3) : "r"(addr));
}

__device__ __forceinline__ void mmah(float* c, unsigned a0, unsigned a1, unsigned a2,
                                     unsigned a3, unsigned b0, unsigned b1) {
    asm volatile(
        "mma.sync.aligned.m16n8k16.row.col.f32.f16.f16.f32 "
        "{%0,%1,%2,%3}, {%4,%5,%6,%7}, {%8,%9}, {%0,%1,%2,%3};\n"
        : "+f"(c[0]), "+f"(c[1]), "+f"(c[2]), "+f"(c[3])
        : "r"(a0), "r"(a1), "r"(a2), "r"(a3), "r"(b0), "r"(b1));
}

// ---------------- conversions (all fp16) ----------------
__global__ void cvt_x(const float* __restrict__ xq, const float* __restrict__ xkv)
{
    const int sel = blockIdx.y;
    const float4* s4 = reinterpret_cast<const float4*>(sel ? xkv : xq);
    uint2* out = reinterpret_cast<uint2*>(sel ? g_xkf : g_xqf);
    const int n4 = (int)(BSD/4);
    for (int i = blockIdx.x * blockDim.x + threadIdx.x; i < n4; i += gridDim.x * blockDim.x) {
        float4 v = s4[i];
        out[i] = make_uint2(packh(v.x, v.y), packh(v.z, v.w));
    }
}

__global__ void cvt_w(const float* __restrict__ wh, const float* __restrict__ wv,
                      const float* __restrict__ wo)
{
    const int sel = blockIdx.y;
    const float4* s4 = reinterpret_cast<const float4*>(sel == 0 ? wh : sel == 1 ? wv : wo);
    uint2* out = reinterpret_cast<uint2*>(sel == 0 ? g_Whf : sel == 1 ? g_Wvf : g_Wof);
    const int n4 = DMODEL*DMODEL/4;
    for (int i = blockIdx.x * blockDim.x + threadIdx.x; i < n4; i += gridDim.x * blockDim.x) {
        float4 v = s4[i];
        out[i] = make_uint2(packh(v.x, v.y), packh(v.z, v.w));
    }
}

// ---------------- adjacency: softmax(col_head @ col_tail^T, diag=0) ----------------
__global__ void adj_kernel(const float* __restrict__ col_head,
                           const float* __restrict__ col_tail)
{
    const int q = blockIdx.x;
    const int h = blockIdx.y;
    const int t = threadIdx.x;                 // 128 threads
    __shared__ float ch[DCOL];
    __shared__ float sred[4];

    if (t < DCOL) ch[t] = col_head[((size_t)h*SEQ + q)*DCOL + t];
    __syncthreads();

    float l[4];
#pragma unroll
    for (int i = 0; i < 4; i++) {
        const int k = t + i*128;
        const float* ct = col_tail + ((size_t)h*SEQ + k)*DCOL;
        float s = 0.f;
#pragma unroll
        for (int c = 0; c < DCOL; c++) s += ch[c]*ct[c];
        l[i] = (k == q) ? 0.f : s;
    }

    float mx = fmaxf(fmaxf(l[0],l[1]), fmaxf(l[2],l[3]));
#pragma unroll
    for (int o = 16; o; o >>= 1) mx = fmaxf(mx, __shfl_xor_sync(0xffffffffu, mx, o));
    if ((t & 31) == 0) sred[t >> 5] = mx;
    __syncthreads();
    mx = fmaxf(fmaxf(sred[0],sred[1]), fmaxf(sred[2],sred[3]));
    __syncthreads();

    float e[4]; float sum = 0.f;
#pragma unroll
    for (int i = 0; i < 4; i++) { e[i] = expf(l[i]-mx); sum += e[i]; }
#pragma unroll
    for (int o = 16; o; o >>= 1) sum += __shfl_xor_sync(0xffffffffu, sum, o);
    if ((t & 31) == 0) sred[t >> 5] = sum;
    __syncthreads();
    sum = sred[0]+sred[1]+sred[2]+sred[3];
    const float inv = 1.f/sum;

    float* dst = g_adjm + ((size_t)h*SEQ + q)*SEQ;
#pragma unroll
    for (int i = 0; i < 4; i++) {
        const int k = t + i*128;
        dst[k] = (1.f - e[i]*inv) * (-10000.f);
    }
}

// ---------------- tile constants ----------------
#define LDK     40                  // padded smem row (16b elems), 80 B
#define TILEB   (128*LDK*2)         // 10240 B
#define HSTAGE  (2*TILEB)           // fp16 single: A + B
#define HG_DSM  (3*HSTAGE)          // 61440 (3-stage)
#define FU_P1_DSM (2*HSTAGE)        // pass-1 tiles in attn (2-stage)

// ---------------- fp16 single-pass projections: blockIdx.z = mode (0,1,2) ----------------
__global__ void __launch_bounds__(256, 2)
proj_h(const float* __restrict__ biasH, const float* __restrict__ biasV,
       const float* __restrict__ aux, int K)
{
    extern __shared__ char sm[];
    const unsigned sbase = smem_u32(sm);

    const int tid  = threadIdx.x;
    const int lane = tid & 31;
    const int warp = tid >> 5;
    const int wm   = warp >> 2, wn = warp & 3;
    const int mode = blockIdx.z;
    const int m0   = blockIdx.y * 128;
    const int n0   = blockIdx.x * 128;

    const __half* A = (mode == 0) ? g_xqf : g_xkf;
    const __half* B = (mode == 2) ? g_Wvf : g_Whf;
    const float* bias = (mode == 2) ? biasV : biasH;

    auto load_stage = [&](int st, int kt) {
        const unsigned sb = sbase + st*HSTAGE;
#pragma unroll
        for (int i = 0; i < 4; i++) {
            const int idx  = tid + i*256;
            const int tile = idx >> 9;
            const int r    = (idx >> 2) & 127;
            const int c    = idx & 3;
            const __half* s = tile ? B : A;
            const int rg = (tile ? n0 : m0) + r;
            cpa16s(sb + tile*TILEB + r*(LDK*2) + c*16,
                   s + (size_t)rg*K + kt + c*8);
        }
    };

    float acc[4][4][4];
#pragma unroll
    for (int i = 0; i < 4; i++)
#pragma unroll
        for (int j = 0; j < 4; j++)
#pragma unroll
            for (int f = 0; f < 4; f++) acc[i][j][f] = 0.f;

    const int rowA = (lane & 7) + ((lane >> 3) & 1) * 8;
    const int colA = ((lane >> 4) & 1) * 8;
    const int rowB = (lane & 7) + ((lane >> 4) & 1) * 8;
    const int colB = ((lane >> 3) & 1) * 8;

    const int iters = K >> 5;
    load_stage(0, 0);  cpa_commit();
    load_stage(1, 32); cpa_commit();

    int cur = 0;
    for (int it = 0; it < iters; ++it) {
        if (it + 1 < iters) cpa_wait<1>();
        else                cpa_wait<0>();
        __syncthreads();
        if (it + 2 < iters) {
            const int nxt = (cur == 0) ? 2 : cur - 1 + ((cur == 2) ? 0 : 2);  // (cur+2)%3
            load_stage((cur + 2) % 3, (it + 2) << 5);
            cpa_commit();
            (void)nxt;
        }

        const unsigned sb = sbase + cur*HSTAGE;
        const unsigned aA = sb + (wm*64 + rowA)*(LDK*2) + colA*2;
        const unsigned aB = sb + TILEB + (wn*32 + rowB)*(LDK*2) + colB*2;

#pragma unroll
        for (int ks = 0; ks < 2; ks++) {
            const unsigned ko = ks*32;
            unsigned bh[4][2];
#pragma unroll
            for (int p = 0; p < 2; p++) {
                unsigned r0, r1, r2, r3;
                ldm4(r0, r1, r2, r3, aB + p*16*(LDK*2) + ko);
                bh[2*p][0]=r0; bh[2*p][1]=r1; bh[2*p+1][0]=r2; bh[2*p+1][1]=r3;
            }
#pragma unroll
            for (int mt = 0; mt < 4; mt++) {
                unsigned a[4];
                ldm4(a[0], a[1], a[2], a[3], aA + mt*16*(LDK*2) + ko);
#pragma unroll
                for (int nt = 0; nt < 4; nt++)
                    mmah(acc[mt][nt], a[0],a[1],a[2],a[3], bh[nt][0], bh[nt][1]);
            }
        }
        cur = (cur == 2) ? 0 : cur + 1;
    }

    const int lr2 = lane >> 2;
    const int lc2 = (lane & 3) << 1;
#pragma unroll
    for (int mt = 0; mt < 4; mt++)
#pragma unroll
        for (int nt = 0; nt < 4; nt++) {
#pragma unroll
            for (int hh = 0; hh < 2; hh++) {
                const int m = m0 + wm*64 + mt*16 + lr2 + hh*8;
                const int n = n0 + wn*32 + nt*8 + lc2;
                float v0 = acc[mt][nt][hh*2+0] + bias[n];
                float v1 = acc[mt][nt][hh*2+1] + bias[n+1];
                const int b = m >> 9, q = m & 511, h = n >> 7, dh = n & 127;
                const size_t idx = (((size_t)((b<<3)|h))*SEQ + q)*DHEAD + dh;
                if (mode < 2) {
                    v0 *= aux[n]; v1 *= aux[n+1];
                    __half* dst = (mode == 0) ? g_fhf : g_ftf;
                    *reinterpret_cast<unsigned*>(&dst[idx]) = packh(v0, v1);
                } else {
                    float2 o; o.x = v0; o.y = v1;
                    *reinterpret_cast<float2*>(&g_fv[idx]) = o;
                }
            }
        }
}

// ---------------- fused scores + softmax + P @ V ----------------
// pass 1 writes u = exp(l - tile_max) as fp16 -> g_uf, per-tile (max, sum).
// pass 2: P = u * fac (one fp32 multiply), writes fr (only fp32 write), P @ V fp16.
#define FU_TM    49152                 // tm:  [4][128] fp32 (2 KB)
#define FU_TS    (FU_TM + 2048)        // ts:  [4][128]
#define FU_MP    (FU_TM + 4096)        // m_part: [128][4]
#define FU_SP    (FU_TM + 6144)        // s_part: [128][4]
#define FU_FAC   (FU_TM + 8192)        // fac: [4][128]
#define FU_DSM   (FU_TM + 10240)       // 59392

__global__ void __launch_bounds__(256, 2)
attn_fused(float* __restrict__ fr)
{
    extern __shared__ char sm[];
    const unsigned sbase = smem_u32(sm);
    unsigned* pW  = reinterpret_cast<unsigned*>(sm);
    float* tm     = reinterpret_cast<float*>(sm + FU_TM);
    float* ts     = reinterpret_cast<float*>(sm + FU_TS);
    float* m_part = reinterpret_cast<float*>(sm + FU_MP);
    float* s_part = reinterpret_cast<float*>(sm + FU_SP);
    float* fac    = reinterpret_cast<float*>(sm + FU_FAC);

    const int tid  = threadIdx.x;
    const int lane = tid & 31;
    const int warp = tid >> 5;
    const int wm   = warp >> 2, wn = warp & 3;
    const int lr2  = lane >> 2;
    const int lc2  = (lane & 3) << 1;
    const int lc   = lane & 3;
    const int z    = blockIdx.z;
    const int m0   = blockIdx.y * 128;
    const int h    = z & 7;

    const __half* Af = g_fhf + (size_t)z*SEQ*DHEAD;
    const __half* Bf = g_ftf + (size_t)z*SEQ*DHEAD;
    float*  frz = fr   + (size_t)z*SEQ*SEQ;
    __half* ufz = g_uf + (size_t)z*SEQ*SEQ;

    const int rowA = (lane & 7) + ((lane >> 3) & 1) * 8;
    const int colA = ((lane >> 4) & 1) * 8;
    const int rowB = (lane & 7) + ((lane >> 4) & 1) * 8;
    const int colB = ((lane >> 3) & 1) * 8;

    // ================= pass 1: scores -> u fp16, per-tile stats =================
    for (int ntile = 0; ntile < 4; ++ntile) {
        const int n0 = ntile * 128;

        auto load_stage = [&](int st, int kt) {
            const unsigned sb = sbase + st*HSTAGE;
#pragma unroll
            for (int i = 0; i < 4; i++) {
                const int idx  = tid + i*256;
                const int tile = idx >> 9;
                const int r    = (idx >> 2) & 127;
                const int c    = idx & 3;
                const __half* s = tile ? Bf : Af;
                const int rg = (tile ? n0 : m0) + r;
                cpa16s(sb + tile*TILEB + r*(LDK*2) + c*16,
                       s + (size_t)rg*DHEAD + kt + c*8);
            }
        };

        float acc[4][4][4];
#pragma unroll
        for (int i = 0; i < 4; i++)
#pragma unroll
            for (int j = 0; j < 4; j++)
#pragma unroll
                for (int f = 0; f < 4; f++) acc[i][j][f] = 0.f;

        load_stage(0, 0);
        cpa_commit();

        for (int it = 0; it < 4; ++it) {
            const int cur = it & 1;
            if (it + 1 < 4) { load_stage(cur ^ 1, (it + 1) << 5); cpa_commit(); cpa_wait<1>(); }
            else            { cpa_wait<0>(); }
            __syncthreads();

            const unsigned sb = sbase + cur*HSTAGE;
            const unsigned aA = sb + (wm*64 + rowA)*(LDK*2) + colA*2;
            const unsigned aB = sb + TILEB + (wn*32 + rowB)*(LDK*2) + colB*2;

#pragma unroll
            for (int ks = 0; ks < 2; ks++) {
                const unsigned ko = ks*32;
                unsigned bh[4][2];
#pragma unroll
                for (int p = 0; p < 2; p++) {
                    unsigned r0, r1, r2, r3;
                    ldm4(r0, r1, r2, r3, aB + p*16*(LDK*2) + ko);
                    bh[2*p][0]=r0; bh[2*p][1]=r1; bh[2*p+1][0]=r2; bh[2*p+1][1]=r3;
                }
#pragma unroll
                for (int mt = 0; mt < 4; mt++) {
                    unsigned a[4];
                    ldm4(a[0], a[1], a[2], a[3], aA + mt*16*(LDK*2) + ko);
#pragma unroll
                    for (int nt = 0; nt < 4; nt++)
                        mmah(acc[mt][nt], a[0],a[1],a[2],a[3], bh[nt][0], bh[nt][1]);
                }
            }
            __syncthreads();
        }

        // --- epilogue A: acc -> logits, per-warp 32-col row max ---
#pragma unroll
        for (int mt = 0; mt < 4; mt++) {
#pragma unroll
            for (int hh = 0; hh < 2; hh++) {
                const int ml = wm*64 + mt*16 + lr2 + hh*8;
                float mx = -3.4e38f;
#pragma unroll
                for (int nt = 0; nt < 4; nt++) {
                    const int nl = wn*32 + nt*8 + lc2;
                    const size_t off = (size_t)(m0 + ml)*SEQ + n0 + nl;
                    float2 am = *reinterpret_cast<const float2*>(&g_adjm[(size_t)h*SEQ*SEQ + off]);
                    float v0 = acc[mt][nt][hh*2+0] * SCALE + am.x;
                    float v1 = acc[mt][nt][hh*2+1] * SCALE + am.y;
                    acc[mt][nt][hh*2+0] = v0;
                    acc[mt][nt][hh*2+1] = v1;
                    mx = fmaxf(mx, fmaxf(v0, v1));
                }
                mx = fmaxf(mx, __shfl_xor_sync(0xffffffffu, mx, 1));
                mx = fmaxf(mx, __shfl_xor_sync(0xffffffffu, mx, 2));
                if (lc == 0) m_part[ml*4 + wn] = mx;
            }
        }
        __syncthreads();

        if (tid < 128) {
            float m4 = fmaxf(fmaxf(m_part[tid*4+0], m_part[tid*4+1]),
                             fmaxf(m_part[tid*4+2], m_part[tid*4+3]));
            tm[ntile*128 + tid] = m4;
        }
        __syncthreads();

        // --- epilogue B: u = exp(l - tile_max) -> g_uf fp16, per-warp partial sums ---
#pragma unroll
        for (int mt = 0; mt < 4; mt++) {
#pragma unroll
            for (int hh = 0; hh < 2; hh++) {
                const int ml = wm*64 + mt*16 + lr2 + hh*8;
                const float tmr = tm[ntile*128 + ml];
                float s = 0.f;
#pragma unroll
                for (int nt = 0; nt < 4; nt++) {
                    const int nl = wn*32 + nt*8 + lc2;
                    const size_t off = (size_t)(m0 + ml)*SEQ + n0 + nl;
                    float u0 = __expf(acc[mt][nt][hh*2+0] - tmr);
                    float u1 = __expf(acc[mt][nt][hh*2+1] - tmr);
                    *reinterpret_cast<unsigned*>(&ufz[off]) = packh(u0, u1);
                    s += u0 + u1;
                }
                s += __shfl_xor_sync(0xffffffffu, s, 1);
                s += __shfl_xor_sync(0xffffffffu, s, 2);
                if (lc == 0) s_part[ml*4 + wn] = s;
            }
        }
        __syncthreads();

        if (tid < 128)
            ts[ntile*128 + tid] = s_part[tid*4+0] + s_part[tid*4+1]
                                + s_part[tid*4+2] + s_part[tid*4+3];
        __syncthreads();
    }

    // ---- per-row global stats -> fac[t] = exp(tm[t]-m)/den ----
    if (tid < 128) {
        float mA = tm[tid], mB = tm[128 + tid], mC = tm[256 + tid], mD = tm[384 + tid];
        float m  = fmaxf(fmaxf(mA, mB), fmaxf(mC, mD));
        float eA = __expf(mA - m), eB = __expf(mB - m);
        float eC = __expf(mC - m), eD = __expf(mD - m);
        float den = ts[tid]*eA + ts[128+tid]*eB + ts[256+tid]*eC + ts[384+tid]*eD;
        float iden = 1.f / den;
        fac[tid]       = eA * iden;
        fac[128 + tid] = eB * iden;
        fac[256 + tid] = eC * iden;
        fac[384 + tid] = eD * iden;
    }
    __syncthreads();

    // ================= pass 2: P = u*fac, write fr, P @ V (fp16 single) =================
    const float* Bp = g_fv + (size_t)z*SEQ*DHEAD;
    const int arow  = tid >> 1;
    const int akoff = (tid & 1) << 3;
    const int bn    = tid & 127;
    const int bhalf = tid >> 7;

    uint4 ua;            // 8 halves of u
    float fb[8];
    auto ldg_stage = [&](int kt) {
        ua = *reinterpret_cast<const uint4*>(ufz + (size_t)(m0 + arow)*SEQ + kt + akoff);
#pragma unroll
        for (int j = 0; j < 8; j++)
            fb[j] = Bp[(size_t)(kt + 8*bhalf + j)*DHEAD + bn];
    };

    ldg_stage(0);

    float acc[4][4][4];
#pragma unroll
    for (int i = 0; i < 4; i++)
#pragma unroll
        for (int j = 0; j < 4; j++)
#pragma unroll
            for (int f = 0; f < 4; f++) acc[i][j][f] = 0.f;

    for (int it = 0; it < 32; ++it) {
        const unsigned b0 = (unsigned)(it & 1) * 3072;   // word stride per stage (12 KB)
        {
            const float fct = fac[(it >> 3)*128 + arow];   // ntile = it/8
            float2 u0 = h2f2(ua.x), u1 = h2f2(ua.y), u2 = h2f2(ua.z), u3 = h2f2(ua.w);
            float p0 = u0.x*fct, p1 = u0.y*fct, p2 = u1.x*fct, p3 = u1.y*fct;
            float p4 = u2.x*fct, p5 = u2.y*fct, p6 = u3.x*fct, p7 = u3.y*fct;

            float* ap = frz + (size_t)(m0 + arow)*SEQ + it*16 + akoff;
            *reinterpret_cast<float4*>(ap)     = make_float4(p0, p1, p2, p3);
            *reinterpret_cast<float4*>(ap + 4) = make_float4(p4, p5, p6, p7);

            uint4 pa = make_uint4(packh(p0, p1), packh(p2, p3),
                                  packh(p4, p5), packh(p6, p7));
            *reinterpret_cast<uint4*>(&pW[b0 + arow*12 + (akoff >> 1)]) = pa;
            uint4 pb = make_uint4(packh(fb[0], fb[1]), packh(fb[2], fb[3]),
                                  packh(fb[4], fb[5]), packh(fb[6], fb[7]));
            *reinterpret_cast<uint4*>(&pW[b0 + 1536 + bn*12 + 4*bhalf]) = pb;
        }
        __syncthreads();

        if (it + 1 < 32) ldg_stage((it + 1) * 16);

        uint2 a0[4], a1[4], b_h[4];
#pragma unroll
        for (int mt = 0; mt < 4; mt++) {
            const int r = wm*64 + mt*16 + lr2;
            a0[mt] = *reinterpret_cast<const uint2*>(&pW[b0 + r*12 + 2*lc]);
            a1[mt] = *reinterpret_cast<const uint2*>(&pW[b0 + (r+8)*12 + 2*lc]);
        }
#pragma unroll
        for (int nt = 0; nt < 4; nt++) {
            const int c = wn*32 + nt*8 + lr2;
            b_h[nt] = *reinterpret_cast<const uint2*>(&pW[b0 + 1536 + c*12 + 2*lc]);
        }
#pragma unroll
        for (int mt = 0; mt < 4; mt++)
#pragma unroll
            for (int nt = 0; nt < 4; nt++)
                mmah(acc[mt][nt], a0[mt].x, a1[mt].x, a0[mt].y, a1[mt].y, b_h[nt].x, b_h[nt].y);
    }

    // epilogue: emit attn fp16
    const int b = z >> 3;
#pragma unroll
    for (int mt = 0; mt < 4; mt++)
#pragma unroll
        for (int nt = 0; nt < 4; nt++) {
            const int mb = m0 + wm*64 + mt*16 + lr2;
            const int nb = wn*32 + nt*8 + lc2;
#pragma unroll
            for (int hh = 0; hh < 2; hh++) {
                const size_t idx = ((size_t)(b*SEQ + mb + hh*8))*DMODEL + h*DHEAD + nb;
                *reinterpret_cast<unsigned*>(&g_atf[idx]) =
                    packh(acc[mt][nt][hh*2+0], acc[mt][nt][hh*2+1]);
            }
        }
}

// ---------------- output projection (fp16 single-pass, 3-stage) ----------------
__global__ void __launch_bounds__(256, 2)
out_h(const float* __restrict__ bias, float* __restrict__ Cext, int K)
{
    extern __shared__ char sm[];
    const unsigned sbase = smem_u32(sm);

    const int tid  = threadIdx.x;
    const int lane = tid & 31;
    const int warp = tid >> 5;
    const int wm   = warp >> 2, wn = warp & 3;
    const int m0   = blockIdx.y * 128;
    const int n0   = blockIdx.x * 128;

    const __half* A = g_atf;
    const __half* B = g_Wof;

    auto load_stage = [&](int st, int kt) {
        const unsigned sb = sbase + st*HSTAGE;
#pragma unroll
        for (int i = 0; i < 4; i++) {
            const int idx  = tid + i*256;
            const int tile = idx >> 9;
            const int r    = (idx >> 2) & 127;
            const int c    = idx & 3;
            const __half* s = tile ? B : A;
            const int rg = (tile ? n0 : m0) + r;
            cpa16s(sb + tile*TILEB + r*(LDK*2) + c*16,
                   s + (size_t)rg*K + kt + c*8);
        }
    };

    float acc[4][4][4];
#pragma unroll
    for (int i = 0; i < 4; i++)
#pragma unroll
        for (int j = 0; j < 4; j++)
#pragma unroll
            for (int f = 0; f < 4; f++) acc[i][j][f] = 0.f;

    const int rowA = (lane & 7) + ((lane >> 3) & 1) * 8;
    const int colA = ((lane >> 4) & 1) * 8;
    const int rowB = (lane & 7) + ((lane >> 4) & 1) * 8;
    const int colB = ((lane >> 3) & 1) * 8;

    const int iters = K >> 5;
    load_stage(0, 0);  cpa_commit();
    load_stage(1, 32); cpa_commit();

    int cur = 0;
    for (int it = 0; it < iters; ++it) {
        if (it + 1 < iters) cpa_wait<1>();
        else                cpa_wait<0>();
        __syncthreads();
        if (it + 2 < iters) {
            load_stage((cur + 2) % 3, (it + 2) << 5);
            cpa_commit();
        }

        const unsigned sb = sbase + cur*HSTAGE;
        const unsigned aA = sb + (wm*64 + rowA)*(LDK*2) + colA*2;
        const unsigned aB = sb + TILEB + (wn*32 + rowB)*(LDK*2) + colB*2;

#pragma unroll
        for (int ks = 0; ks < 2; ks++) {
            const unsigned ko = ks*32;
            unsigned bh[4][2];
#pragma unroll
            for (int p = 0; p < 2; p++) {
                unsigned r0, r1, r2, r3;
                ldm4(r0, r1, r2, r3, aB + p*16*(LDK*2) + ko);
                bh[2*p][0]=r0; bh[2*p][1]=r1; bh[2*p+1][0]=r2; bh[2*p+1][1]=r3;
            }
#pragma unroll
            for (int mt = 0; mt < 4; mt++) {
                unsigned a[4];
                ldm4(a[0], a[1], a[2], a[3], aA + mt*16*(LDK*2) + ko);
#pragma unroll
                for (int nt = 0; nt < 4; nt++)
                    mmah(acc[mt][nt], a[0],a[1],a[2],a[3], bh[nt][0], bh[nt][1]);
            }
        }
        cur = (cur == 2) ? 0 : cur + 1;
    }

    const int lr2 = lane >> 2;
    const int lc2 = (lane & 3) << 1;
#pragma unroll
    for (int mt = 0; mt < 4; mt++)
#pragma unroll
        for (int nt = 0; nt < 4; nt++) {
#pragma unroll
            for (int hh = 0; hh < 2; hh++) {
                const int m = m0 + wm*64 + mt*16 + lr2 + hh*8;
                const int n = n0 + wn*32 + nt*8 + lc2;
                float2 o;
                o.x = acc[mt][nt][hh*2+0] + bias[n];
                o.y = acc[mt][nt][hh*2+1] + bias[n+1];
                *reinterpret_cast<float2*>(&Cext[(size_t)m*DMODEL + n]) = o;
            }
        }
}

// ---------------- launch ----------------
extern "C" void kernel_launch(void* const* d_in, const int* in_sizes, int n_in,
                              void* d_out, int out_size)
{
    const float* x_q      = (const float*)d_in[0];
    const float* x_kv     = (const float*)d_in[1];
    const float* W_head_w = (const float*)d_in[2];
    const float* W_head_b = (const float*)d_in[3];
    const float* W_v_w    = (const float*)d_in[4];
    const float* W_v_b    = (const float*)d_in[5];
    const float* W_out_w  = (const float*)d_in[6];
    const float* W_out_b  = (const float*)d_in[7];
    const float* rel_emb  = (const float*)d_in[8];
    const float* col_head = (const float*)d_in[9];
    const float* col_tail = (const float*)d_in[10];

    float* out_x  = (float*)d_out;                          // [32,512,1024]
    float* out_fr = out_x + (size_t)BATCH*SEQ*DMODEL;       // [256,512,512]

    static bool attr_done = false;
    if (!attr_done) {
        cudaFuncSetAttribute(proj_h,     cudaFuncAttributeMaxDynamicSharedMemorySize, HG_DSM);
        cudaFuncSetAttribute(attn_fused, cudaFuncAttributeMaxDynamicSharedMemorySize, FU_DSM);
        cudaFuncSetAttribute(out_h,      cudaFuncAttributeMaxDynamicSharedMemorySize, HG_DSM);
        attr_done = true;
    }

    // 1) conversions (all fp16)
    cvt_x<<<dim3(2048, 2), 256>>>(x_q, x_kv);
    cvt_w<<<dim3(512, 3),  256>>>(W_head_w, W_v_w, W_out_w);

    // 2) learned column topology mask
    adj_kernel<<<dim3(SEQ, HEADS), 128>>>(col_head, col_tail);

    // 3) projections (fp16 single-pass, merged, 3-stage pipeline)
    proj_h<<<dim3(8, 128, 3), 256, HG_DSM>>>(W_head_b, W_v_b, rel_emb, DMODEL);

    // 4) fused scores + softmax + P @ V -> fr final probs, attn fp16
    attn_fused<<<dim3(1, 4, BHS), 256, FU_DSM>>>(out_fr);

    // 5) output projection (fp16 single-pass, 3-stage pipeline)
    out_h<<<dim3(8, 128), 256, HG_DSM>>>(W_out_b, out_x, DMODEL);
}